// round 10
// baseline (speedup 1.0000x reference)
#include <cuda_runtime.h>
#include <cuda_fp16.h>
#include <math.h>
#include <stdint.h>

// ---------------- problem constants ----------------
#define BATCH   16
#define IMG     112
#define CC      192
#define NHEADS  6
#define DHEAD   32
#define WSZ     7
#define NTOK    49
#define NWIN    4096
#define MROWS   200704
#define HID     768

// ---------------- device scratch ----------------
__device__ __half g_xs [(size_t)MROWS * CC];     // LN2 output
__device__ __half g_aos[(size_t)MROWS * CC];
__device__ __half g_hs [(size_t)MROWS * HID];
__device__ __half g_q[(size_t)NWIN * NHEADS * NTOK * DHEAD];
__device__ __half g_k[(size_t)NWIN * NHEADS * NTOK * DHEAD];
__device__ __half g_v[(size_t)NWIN * NHEADS * NTOK * DHEAD];
__device__ float g_x2[(size_t)MROWS * CC];
__device__ __half g_wqkv [(size_t)576 * 192];
__device__ __half g_wproj[(size_t)192 * 192];
__device__ __half g_wfc1 [(size_t)768 * 192];
__device__ __half g_wfc2 [(size_t)192 * 768];
__device__ __half g_cmb[(size_t)4 * NHEADS * 64 * 56];

// ---------------- helpers ----------------
__device__ __forceinline__ uint32_t smem_to_u32(const void* p) {
    uint32_t a;
    asm("{ .reg .u64 t; cvta.to.shared.u64 t, %1; cvt.u32.u64 %0, t; }" : "=r"(a) : "l"(p));
    return a;
}
__device__ __forceinline__ void cp16(uint32_t sm, const void* gp) {
    asm volatile("cp.async.cg.shared.global [%0], [%1], 16;" :: "r"(sm), "l"(gp));
}
__device__ __forceinline__ void cp_commit() { asm volatile("cp.async.commit_group;"); }
__device__ __forceinline__ void cp_wait1()  { asm volatile("cp.async.wait_group 1;"); }
__device__ __forceinline__ void cp_wait0()  { asm volatile("cp.async.wait_group 0;"); }

__device__ __forceinline__ void ldm4(uint32_t& x0, uint32_t& x1, uint32_t& x2, uint32_t& x3, uint32_t addr) {
    asm volatile("ldmatrix.sync.aligned.m8n8.x4.shared.b16 {%0,%1,%2,%3}, [%4];"
                 : "=r"(x0), "=r"(x1), "=r"(x2), "=r"(x3) : "r"(addr));
}
__device__ __forceinline__ void ldm4t(uint32_t& x0, uint32_t& x1, uint32_t& x2, uint32_t& x3, uint32_t addr) {
    asm volatile("ldmatrix.sync.aligned.m8n8.x4.trans.shared.b16 {%0,%1,%2,%3}, [%4];"
                 : "=r"(x0), "=r"(x1), "=r"(x2), "=r"(x3) : "r"(addr));
}
__device__ __forceinline__ void mma16816(float& d0, float& d1, float& d2, float& d3,
                                         uint32_t a0, uint32_t a1, uint32_t a2, uint32_t a3,
                                         uint32_t b0, uint32_t b1) {
    asm volatile("mma.sync.aligned.m16n8k16.row.col.f32.f16.f16.f32 "
                 "{%0,%1,%2,%3},{%4,%5,%6,%7},{%8,%9},{%0,%1,%2,%3};"
                 : "+f"(d0), "+f"(d1), "+f"(d2), "+f"(d3)
                 : "r"(a0), "r"(a1), "r"(a2), "r"(a3), "r"(b0), "r"(b1));
}
__device__ __forceinline__ uint32_t f22u(float a, float b) {
    __half2 h = __floats2half2_rn(a, b);
    return *(uint32_t*)&h;
}
// full-K tile: rows of 192 halves (384B, 24 x 16B chunks)
__device__ __forceinline__ uint32_t full_off(int row, int c) {
    return (uint32_t)(row * 384 + (((c & 24) | ((c ^ row) & 7)) << 4));
}
// 64-half tile: rows of 128B, 8 x 16B chunks
__device__ __forceinline__ uint32_t t64_addr(uint32_t base, int row, int c) {
    return base + row * 128 + (((c ^ row) & 7) << 4);
}
__device__ __forceinline__ float gelu_exact(float x) {
    return 0.5f * x * (1.f + erff(x * 0.70710678118654752f));
}

// ---------------- merged weight prep ----------------
__global__ void prep_all(const float* __restrict__ qkv_w, const float* __restrict__ proj_w,
                         const float* __restrict__ fc1_w, const float* __restrict__ fc2_w) {
    int i = blockIdx.x * 256 + threadIdx.x;
    const float* W; __half* D; int K, N, off;
    if (i < 110592)      { W = qkv_w;  D = g_wqkv;  K = 192; N = 576; off = i; }
    else if (i < 147456) { W = proj_w; D = g_wproj; K = 192; N = 192; off = i - 110592; }
    else if (i < 294912) { W = fc1_w;  D = g_wfc1;  K = 192; N = 768; off = i - 147456; }
    else if (i < 442368) { W = fc2_w;  D = g_wfc2;  K = 768; N = 192; off = i - 294912; }
    else return;
    int k = off / N, n = off - k * N;
    D[(size_t)n * K + k] = __float2half(W[off]);
}

// ---------------- bias+mask table prep ----------------
__global__ void prep_cmb(const float* __restrict__ amask, const float* __restrict__ rpb) {
    int ch = blockIdx.x;
    int cls = ch / NHEADS, head = ch - cls * NHEADS;
    int wi_rep = (cls >> 1 ? 240 : 0) + ((cls & 1) ? 15 : 0);
    __half* dst = g_cmb + (size_t)ch * (64 * 56);
    for (int idx = threadIdx.x; idx < 64 * 56; idx += 256) {
        int r = idx / 56, c = idx - r * 56;
        float v;
        if (r < NTOK && c < NTOK) {
            int i1 = r / WSZ, j1 = r - i1 * WSZ;
            int i2 = c / WSZ, j2 = c - i2 * WSZ;
            int rel = (i1 - i2 + 6) * 13 + (j1 - j2 + 6);
            v = rpb[rel * NHEADS + head] + amask[((size_t)wi_rep * NTOK + r) * NTOK + c];
        } else {
            v = -100.f;
        }
        dst[idx] = __float2half(v);
    }
}

// ================= gemm_full: K=192 resident, no K-loop =================
// BM=64, BN=192. 256 thr (8 warps 2x4), warp tile 32x48, 2 CTA/SM.
// EPI 1: A = LN1(x window-gathered) computed in-kernel; out q/k/v.
// EPI 2: A=aos; proj + unshift + shortcut -> x2, fused LN2 -> xs
// EPI 3: A=xs; fc1 + gelu -> hs
#define SMEM_FULL 98304
template<int EPI>
__global__ __launch_bounds__(256, 2)
void gemm_full(const __half* __restrict__ A2, const __half* __restrict__ B2,
               const float* __restrict__ bias, float* __restrict__ outF,
               const float* __restrict__ addsrc, __half* __restrict__ outS,
               const float* __restrict__ g2, const float* __restrict__ b2,
               __half* __restrict__ xsOut) {
    extern __shared__ __align__(16) char sm_dyn[];
    uint32_t a_base = smem_to_u32(sm_dyn);
    uint32_t b_base = a_base + 24576;

    int tid = threadIdx.x, lane = tid & 31, wid = tid >> 5;
    int wm = wid >> 2, wn = wid & 3;
    int bm = blockIdx.y * 64, bn = blockIdx.x * 192;
    const int K = 192;

    // ---- B slice (192x192) via cp.async ----
    {
        const __half* Bg = B2 + (size_t)bn * K;
        #pragma unroll
        for (int i = 0; i < 18; i++) {
            int t = tid + i * 256, row = t / 24, c = t - row * 24;
            cp16(b_base + full_off(row, c), Bg + (size_t)row * K + c * 8);
        }
    }
    cp_commit();

    // ---- A tile ----
    if constexpr (EPI == 1) {
        // fused LN1: gather pixel row, normalize, store fp16 swizzled
        int row = tid >> 2, q4 = tid & 3;
        int grow = bm + row;
        int win = grow / NTOK, n = grow - win * NTOK;
        int b = win >> 8, wi = win & 255;
        int hh = (wi >> 4) * WSZ + n / WSZ;
        int ww = (wi & 15) * WSZ + n % WSZ;
        int p = hh + 3; if (p >= IMG) p -= IMG;
        int q = ww + 3; if (q >= IMG) q -= IMG;
        const float* srcp = addsrc + (size_t)((b * IMG + p) * IMG + q) * CC + q4 * 48;
        float s = 0.f, s2 = 0.f;
        #pragma unroll
        for (int j = 0; j < 12; j++) {
            float4 v = *(const float4*)(srcp + j * 4);
            s += v.x + v.y + v.z + v.w;
            s2 += v.x * v.x + v.y * v.y + v.z * v.z + v.w * v.w;
        }
        #pragma unroll
        for (int o = 1; o <= 2; o <<= 1) {
            s  += __shfl_xor_sync(0xffffffffu, s,  o);
            s2 += __shfl_xor_sync(0xffffffffu, s2, o);
        }
        float mean = s * (1.f / 192.f);
        float var  = s2 * (1.f / 192.f) - mean * mean;
        float rstd = rsqrtf(var + 1e-5f);
        #pragma unroll
        for (int cc = 0; cc < 6; cc++) {
            int c0 = q4 * 48 + cc * 8;
            float4 v0 = *(const float4*)(srcp + cc * 8);
            float4 v1 = *(const float4*)(srcp + cc * 8 + 4);
            float4 ga = *(const float4*)(g2 + c0);
            float4 gb = *(const float4*)(g2 + c0 + 4);
            float4 ba = *(const float4*)(b2 + c0);
            float4 bb = *(const float4*)(b2 + c0 + 4);
            uint4 o;
            o.x = f22u((v0.x - mean) * rstd * ga.x + ba.x, (v0.y - mean) * rstd * ga.y + ba.y);
            o.y = f22u((v0.z - mean) * rstd * ga.z + ba.z, (v0.w - mean) * rstd * ga.w + ba.w);
            o.z = f22u((v1.x - mean) * rstd * gb.x + bb.x, (v1.y - mean) * rstd * gb.y + bb.y);
            o.w = f22u((v1.z - mean) * rstd * gb.z + bb.z, (v1.w - mean) * rstd * gb.w + bb.w);
            *(uint4*)(sm_dyn + full_off(row, q4 * 6 + cc)) = o;
        }
    } else {
        const __half* Ag = A2 + (size_t)bm * K;
        #pragma unroll
        for (int i = 0; i < 6; i++) {
            int t = tid + i * 256, row = t / 24, c = t - row * 24;
            cp16(a_base + full_off(row, c), Ag + (size_t)row * K + c * 8);
        }
        cp_commit();
    }
    cp_wait0();
    __syncthreads();

    // ---- 12 k-steps, no barriers ----
    float acc[2][6][4] = {};
    int arow = wm * 32 + (lane & 15);
    int bnrow = wn * 48 + (lane & 7) + ((lane >> 4) << 3);
    int bk8 = (lane >> 3) & 1;
    #pragma unroll
    for (int ks = 0; ks < 12; ks++) {
        uint32_t af[2][4];
        #pragma unroll
        for (int mt = 0; mt < 2; mt++)
            ldm4(af[mt][0], af[mt][1], af[mt][2], af[mt][3],
                 a_base + full_off(arow + mt * 16, ks * 2 + (lane >> 4)));
        uint32_t bf[6][2];
        #pragma unroll
        for (int pr = 0; pr < 3; pr++)
            ldm4(bf[2 * pr][0], bf[2 * pr][1], bf[2 * pr + 1][0], bf[2 * pr + 1][1],
                 b_base + full_off(bnrow + pr * 16, ks * 2 + bk8));
        #pragma unroll
        for (int mt = 0; mt < 2; mt++)
            #pragma unroll
            for (int nt = 0; nt < 6; nt++)
                mma16816(acc[mt][nt][0], acc[mt][nt][1], acc[mt][nt][2], acc[mt][nt][3],
                         af[mt][0], af[mt][1], af[mt][2], af[mt][3],
                         bf[nt][0], bf[nt][1]);
    }
    __syncthreads();

    float2 bcol[6];
    #pragma unroll
    for (int nt = 0; nt < 6; nt++) {
        int col = bn + wn * 48 + nt * 8 + 2 * (lane & 3);
        bcol[nt] = *(const float2*)&bias[col];
    }

    if constexpr (EPI == 2) {
        float* red  = (float*)sm_dyn;
        float* redq = red + 64 * 17;
        int slot = wn * 4 + (lane & 3);

        #pragma unroll
        for (int mt = 0; mt < 2; mt++) {
            #pragma unroll
            for (int half = 0; half < 2; half++) {
                int rl = wm * 32 + mt * 16 + (lane >> 2) + half * 8;
                int row = bm + rl;
                int win = row / NTOK, n = row - win * NTOK;
                int b = win >> 8, wi = win & 255;
                int hh = (wi >> 4) * WSZ + n / WSZ;
                int ww = (wi & 15) * WSZ + n % WSZ;
                int p = hh + 3; if (p >= IMG) p -= IMG;
                int q = ww + 3; if (q >= IMG) q -= IMG;
                size_t pixbase = (size_t)((b * IMG + p) * IMG + q) * CC;
                float s = 0.f, sq2 = 0.f;
                #pragma unroll
                for (int nt = 0; nt < 6; nt++) {
                    int col = wn * 48 + nt * 8 + 2 * (lane & 3);
                    float2 sc = *(const float2*)&addsrc[pixbase + col];
                    float vx = acc[mt][nt][half * 2] + bcol[nt].x + sc.x;
                    float vy = acc[mt][nt][half * 2 + 1] + bcol[nt].y + sc.y;
                    acc[mt][nt][half * 2] = vx;
                    acc[mt][nt][half * 2 + 1] = vy;
                    *(float2*)&outF[pixbase + col] = make_float2(vx, vy);
                    s += vx + vy;
                    sq2 += vx * vx + vy * vy;
                }
                red [rl * 17 + slot] = s;
                redq[rl * 17 + slot] = sq2;
            }
        }
        __syncthreads();
        if (tid < 64) {
            float s = 0.f, qq = 0.f;
            #pragma unroll
            for (int i = 0; i < 16; i++) { s += red[tid * 17 + i]; qq += redq[tid * 17 + i]; }
            float mean = s * (1.f / 192.f);
            float var = qq * (1.f / 192.f) - mean * mean;
            red [tid * 17 + 16] = mean;
            redq[tid * 17 + 16] = rsqrtf(var + 1e-5f);
        }
        __syncthreads();
        #pragma unroll
        for (int mt = 0; mt < 2; mt++) {
            #pragma unroll
            for (int half = 0; half < 2; half++) {
                int rl = wm * 32 + mt * 16 + (lane >> 2) + half * 8;
                int row = bm + rl;
                int win = row / NTOK, n = row - win * NTOK;
                int b = win >> 8, wi = win & 255;
                int hh = (wi >> 4) * WSZ + n / WSZ;
                int ww = (wi & 15) * WSZ + n % WSZ;
                int p = hh + 3; if (p >= IMG) p -= IMG;
                int q = ww + 3; if (q >= IMG) q -= IMG;
                size_t pixbase = (size_t)((b * IMG + p) * IMG + q) * CC;
                float mean = red [rl * 17 + 16];
                float rstd = redq[rl * 17 + 16];
                #pragma unroll
                for (int nt = 0; nt < 6; nt++) {
                    int col = wn * 48 + nt * 8 + 2 * (lane & 3);
                    float2 gv = *(const float2*)&g2[col];
                    float2 bv = *(const float2*)&b2[col];
                    float yx = (acc[mt][nt][half * 2] - mean) * rstd * gv.x + bv.x;
                    float yy = (acc[mt][nt][half * 2 + 1] - mean) * rstd * gv.y + bv.y;
                    *(__half2*)&xsOut[pixbase + col] = __floats2half2_rn(yx, yy);
                }
            }
        }
    } else {
        #pragma unroll
        for (int mt = 0; mt < 2; mt++) {
            #pragma unroll
            for (int half = 0; half < 2; half++) {
                int row = bm + wm * 32 + mt * 16 + (lane >> 2) + half * 8;
                if constexpr (EPI == 1) {
                    int t3 = bn / 192;
                    float scale = (t3 == 0) ? 0.17677669529663687f : 1.f;
                    __half* dst = (t3 == 0) ? g_q : ((t3 == 1) ? g_k : g_v);
                    int win = row / NTOK, n = row - win * NTOK;
                    #pragma unroll
                    for (int nt = 0; nt < 6; nt++) {
                        int col = wn * 48 + nt * 8 + 2 * (lane & 3);
                        int head = col >> 5, dd = col & 31;
                        float vx = (acc[mt][nt][half * 2] + bcol[nt].x) * scale;
                        float vy = (acc[mt][nt][half * 2 + 1] + bcol[nt].y) * scale;
                        *(__half2*)&dst[(((size_t)win * NHEADS + head) * NTOK + n) * DHEAD + dd] =
                            __floats2half2_rn(vx, vy);
                    }
                } else {  // EPI == 3
                    size_t rb = (size_t)row * HID;
                    #pragma unroll
                    for (int nt = 0; nt < 6; nt++) {
                        int col = bn + wn * 48 + nt * 8 + 2 * (lane & 3);
                        float gx = gelu_exact(acc[mt][nt][half * 2] + bcol[nt].x);
                        float gy = gelu_exact(acc[mt][nt][half * 2 + 1] + bcol[nt].y);
                        *(__half2*)&outS[rb + col] = __floats2half2_rn(gx, gy);
                    }
                }
            }
        }
    }
}

// ================= gemm_pipe64 (fc2: K=768): 3-stage BK=64 pipeline =================
#define SMEM_P64 98304   // 3*(8192 + 24576)
__global__ __launch_bounds__(256, 2)
void gemm_pipe64(const __half* __restrict__ A2, const __half* __restrict__ B2,
                 const float* __restrict__ bias, float* __restrict__ outF,
                 const float* __restrict__ addsrc) {
    extern __shared__ __align__(16) char sm_dyn[];
    uint32_t a_base = smem_to_u32(sm_dyn);
    uint32_t b_base = a_base + 24576;
    const int K = 768;

    int tid = threadIdx.x, lane = tid & 31, wid = tid >> 5;
    int wm = wid >> 2, wn = wid & 3;
    int bm = blockIdx.y * 64, bn = blockIdx.x * 192;
    const int NC = 12;

    float acc[2][6][4] = {};

    auto issue = [&](int buf, int cc) {
        const __half* Ag = A2 + (size_t)bm * K + cc * 64;
        const __half* Bg = B2 + (size_t)bn * K + cc * 64;
        uint32_t ab = a_base + buf * 8192;
        uint32_t bb = b_base + buf * 24576;
        #pragma unroll
        for (int i = 0; i < 2; i++) {   // A: 512 chunks
            int t = tid + i * 256, row = t >> 3, c = t & 7;
            cp16(t64_addr(ab, row, c), Ag + (size_t)row * K + c * 8);
        }
        #pragma unroll
        for (int i = 0; i < 6; i++) {   // B: 1536 chunks
            int t = tid + i * 256, row = t >> 3, c = t & 7;
            cp16(t64_addr(bb, row, c), Bg + (size_t)row * K + c * 8);
        }
        cp_commit();
    };

    issue(0, 0);
    issue(1, 1);

    for (int cc = 0; cc < NC; cc++) {
        int buf = cc % 3;
        if (cc + 1 < NC) cp_wait1(); else cp_wait0();
        __syncthreads();
        if (cc + 2 < NC) issue((cc + 2) % 3, cc + 2);

        uint32_t ab = a_base + buf * 8192;
        uint32_t bb = b_base + buf * 24576;
        int arow = wm * 32 + (lane & 15);
        int bnrow = wn * 48 + (lane & 7) + ((lane >> 4) << 3);
        int bk8 = (lane >> 3) & 1;
        #pragma unroll
        for (int ks = 0; ks < 4; ks++) {
            uint32_t af[2][4];
            #pragma unroll
            for (int mt = 0; mt < 2; mt++)
                ldm4(af[mt][0], af[mt][1], af[mt][2], af[mt][3],
                     t64_addr(ab, arow + mt * 16, ks * 2 + (lane >> 4)));
            uint32_t bf[6][2];
            #pragma unroll
            for (int pr = 0; pr < 3; pr++)
                ldm4(bf[2 * pr][0], bf[2 * pr][1], bf[2 * pr + 1][0], bf[2 * pr + 1][1],
                     t64_addr(bb, bnrow + pr * 16, ks * 2 + bk8));
            #pragma unroll
            for (int mt = 0; mt < 2; mt++)
                #pragma unroll
                for (int nt = 0; nt < 6; nt++)
                    mma16816(acc[mt][nt][0], acc[mt][nt][1], acc[mt][nt][2], acc[mt][nt][3],
                             af[mt][0], af[mt][1], af[mt][2], af[mt][3],
                             bf[nt][0], bf[nt][1]);
        }
    }

    float2 bcol[6];
    #pragma unroll
    for (int nt = 0; nt < 6; nt++) {
        int col = bn + wn * 48 + nt * 8 + 2 * (lane & 3);
        bcol[nt] = *(const float2*)&bias[col];
    }
    #pragma unroll
    for (int mt = 0; mt < 2; mt++) {
        #pragma unroll
        for (int half = 0; half < 2; half++) {
            int row = bm + wm * 32 + mt * 16 + (lane >> 2) + half * 8;
            size_t rb = (size_t)row * 192;
            #pragma unroll
            for (int nt = 0; nt < 6; nt++) {
                int col = bn + wn * 48 + nt * 8 + 2 * (lane & 3);
                float2 s = *(const float2*)&addsrc[rb + col];
                float vx = acc[mt][nt][half * 2] + bcol[nt].x + s.x;
                float vy = acc[mt][nt][half * 2 + 1] + bcol[nt].y + s.y;
                *(float2*)&outF[rb + col] = make_float2(vx, vy);
            }
        }
    }
}

// ---------------- attention: 256 thr, 2 heads parallel, cp.async double-buffered ----------------
// dyn smem: QKV [buf][wg]: 4 x 15360B = 61440; C [buf][wg]: 4 x 7168 = 28672. total 90112.
#define SMEM_ATTN 90112
__global__ __launch_bounds__(256) void attn_mma(__half* __restrict__ outs) {
    extern __shared__ __align__(16) char sm_dyn[];
    uint32_t smb = smem_to_u32(sm_dyn);
    int win = blockIdx.x;
    int wi = win & 255;
    int cls = (((wi >> 4) == 15) ? 2 : 0) + (((wi & 15) == 15) ? 1 : 0);
    int tid = threadIdx.x;
    int wg = tid >> 7;
    int t = tid & 127;
    int lane = t & 31, wmg = t >> 5;
    int g = lane >> 3, r8 = lane & 7;
    int mr = wmg * 16;

    // zero QKV pads (rows >= 49) — zero whole QKV region once
    uint4 z = make_uint4(0, 0, 0, 0);
    for (int i = tid; i < 3840; i += 256) ((uint4*)sm_dyn)[i] = z;
    __syncthreads();

    auto load_pair = [&](int buf, int h2) {
        int h = h2 * 2 + wg;
        uint32_t qb = smb + (buf * 2 + wg) * 15360;
        const uint4* qg = (const uint4*)(g_q + (size_t)(win * NHEADS + h) * (NTOK * DHEAD));
        const uint4* kg = (const uint4*)(g_k + (size_t)(win * NHEADS + h) * (NTOK * DHEAD));
        const uint4* vg = (const uint4*)(g_v + (size_t)(win * NHEADS + h) * (NTOK * DHEAD));
        for (int i = t; i < 196; i += 128) {
            int r = i >> 2, c = i & 3;
            uint32_t off = r * 80 + c * 16;
            cp16(qb + off, qg + i);
            cp16(qb + 5120 + off, kg + i);
            cp16(qb + 10240 + off, vg + i);
        }
        uint32_t cb = smb + 61440 + (buf * 2 + wg) * 7168;
        const uint4* cg = (const uint4*)(g_cmb + (size_t)(cls * NHEADS + h) * (64 * 56));
        for (int i = t; i < 448; i += 128) cp16(cb + i * 16, cg + i);
        cp_commit();
    };

    load_pair(0, 0);

    int buf = 0;
    for (int h2 = 0; h2 < 3; h2++) {
        int h = h2 * 2 + wg;
        if (h2 < 2) load_pair(buf ^ 1, h2 + 1);
        if (h2 < 2) cp_wait1(); else cp_wait0();
        __syncthreads();

        uint32_t qbase = smb + (buf * 2 + wg) * 15360;
        uint32_t kbase = qbase + 5120, vbase = qbase + 10240;
        uint32_t cbase = smb + 61440 + (buf * 2 + wg) * 7168;

        uint32_t qf[2][4];
        #pragma unroll
        for (int ks = 0; ks < 2; ks++) {
            int row = mr + (g & 1) * 8 + r8;
            int col = ks * 16 + (g >> 1) * 8;
            ldm4(qf[ks][0], qf[ks][1], qf[ks][2], qf[ks][3], qbase + row * 80 + col * 2);
        }

        float sacc[7][4] = {};
        #pragma unroll
        for (int ks = 0; ks < 2; ks++) {
            #pragma unroll
            for (int np = 0; np < 4; np++) {
                int row = np * 16 + ((g >> 1) & 1) * 8 + r8;
                int col = ks * 16 + (g & 1) * 8;
                uint32_t b0, b1, b2, b3;
                ldm4(b0, b1, b2, b3, kbase + row * 80 + col * 2);
                mma16816(sacc[2 * np][0], sacc[2 * np][1], sacc[2 * np][2], sacc[2 * np][3],
                         qf[ks][0], qf[ks][1], qf[ks][2], qf[ks][3], b0, b1);
                if (np < 3)
                    mma16816(sacc[2 * np + 1][0], sacc[2 * np + 1][1], sacc[2 * np + 1][2], sacc[2 * np + 1][3],
                             qf[ks][0], qf[ks][1], qf[ks][2], qf[ks][3], b2, b3);
            }
        }

        #pragma unroll
        for (int np = 0; np < 4; np++) {
            int row = mr + (g & 1) * 8 + r8;
            int colc = 2 * np + ((g >> 1) & 1); if (colc > 6) colc = 6;
            uint32_t c0, c1, c2, c3;
            ldm4(c0, c1, c2, c3, cbase + row * 112 + colc * 8 * 2);
            float2 f;
            f = __half22float2(*(__half2*)&c0); sacc[2 * np][0] += f.x; sacc[2 * np][1] += f.y;
            f = __half22float2(*(__half2*)&c1); sacc[2 * np][2] += f.x; sacc[2 * np][3] += f.y;
            if (np < 3) {
                f = __half22float2(*(__half2*)&c2); sacc[2 * np + 1][0] += f.x; sacc[2 * np + 1][1] += f.y;
                f = __half22float2(*(__half2*)&c3); sacc[2 * np + 1][2] += f.x; sacc[2 * np + 1][3] += f.y;
            }
        }

        float mx0 = -1e30f, mx8 = -1e30f;
        #pragma unroll
        for (int nt = 0; nt < 7; nt++) {
            mx0 = fmaxf(mx0, fmaxf(sacc[nt][0], sacc[nt][1]));
            mx8 = fmaxf(mx8, fmaxf(sacc[nt][2], sacc[nt][3]));
        }
        #pragma unroll
        for (int o = 1; o <= 2; o <<= 1) {
            mx0 = fmaxf(mx0, __shfl_xor_sync(0xffffffffu, mx0, o));
            mx8 = fmaxf(mx8, __shfl_xor_sync(0xffffffffu, mx8, o));
        }
        float s0 = 0.f, s8 = 0.f;
        #pragma unroll
        for (int nt = 0; nt < 7; nt++) {
            sacc[nt][0] = __expf(sacc[nt][0] - mx0); s0 += sacc[nt][0];
            sacc[nt][1] = __expf(sacc[nt][1] - mx0); s0 += sacc[nt][1];
            sacc[nt][2] = __expf(sacc[nt][2] - mx8); s8 += sacc[nt][2];
            sacc[nt][3] = __expf(sacc[nt][3] - mx8); s8 += sacc[nt][3];
        }
        #pragma unroll
        for (int o = 1; o <= 2; o <<= 1) {
            s0 += __shfl_xor_sync(0xffffffffu, s0, o);
            s8 += __shfl_xor_sync(0xffffffffu, s8, o);
        }
        float inv0 = 1.f / s0, inv8 = 1.f / s8;
        #pragma unroll
        for (int nt = 0; nt < 7; nt++) {
            sacc[nt][0] *= inv0; sacc[nt][1] *= inv0;
            sacc[nt][2] *= inv8; sacc[nt][3] *= inv8;
        }

        float oacc[4][4] = {};
        #pragma unroll
        for (int kt = 0; kt < 4; kt++) {
            uint32_t a0 = f22u(sacc[2 * kt][0], sacc[2 * kt][1]);
            uint32_t a1 = f22u(sacc[2 * kt][2], sacc[2 * kt][3]);
            uint32_t a2 = 0, a3 = 0;
            if (kt < 3) {
                a2 = f22u(sacc[2 * kt + 1][0], sacc[2 * kt + 1][1]);
                a3 = f22u(sacc[2 * kt + 1][2], sacc[2 * kt + 1][3]);
            }
            #pragma unroll
            for (int dp = 0; dp < 2; dp++) {
                int row = kt * 16 + (g & 1) * 8 + r8;
                int col = dp * 16 + ((g >> 1) & 1) * 8;
                uint32_t b0, b1, b2, b3;
                ldm4t(b0, b1, b2, b3, vbase + row * 80 + col * 2);
                mma16816(oacc[2 * dp][0], oacc[2 * dp][1], oacc[2 * dp][2], oacc[2 * dp][3],
                         a0, a1, a2, a3, b0, b1);
                mma16816(oacc[2 * dp + 1][0], oacc[2 * dp + 1][1], oacc[2 * dp + 1][2], oacc[2 * dp + 1][3],
                         a0, a1, a2, a3, b2, b3);
            }
        }

        int r0 = mr + (lane >> 2);
        int cbase2 = h * DHEAD + 2 * (lane & 3);
        if (r0 < NTOK) {
            size_t ob = ((size_t)win * NTOK + r0) * CC + cbase2;
            #pragma unroll
            for (int dn = 0; dn < 4; dn++)
                *(__half2*)&outs[ob + dn * 8] = __floats2half2_rn(oacc[dn][0], oacc[dn][1]);
        }
        int r1 = r0 + 8;
        if (r1 < NTOK) {
            size_t ob = ((size_t)win * NTOK + r1) * CC + cbase2;
            #pragma unroll
            for (int dn = 0; dn < 4; dn++)
                *(__half2*)&outs[ob + dn * 8] = __floats2half2_rn(oacc[dn][2], oacc[dn][3]);
        }
        __syncthreads();
        buf ^= 1;
    }
}

// ---------------- launch ----------------
extern "C" void kernel_launch(void* const* d_in, const int* in_sizes, int n_in,
                              void* d_out, int out_size) {
    const float* x      = (const float*)d_in[0];
    const float* amask  = (const float*)d_in[1];
    const float* n1g    = (const float*)d_in[2];
    const float* n1b    = (const float*)d_in[3];
    const float* qkv_w  = (const float*)d_in[4];
    const float* qkv_b  = (const float*)d_in[5];
    const float* rpb    = (const float*)d_in[6];
    const float* proj_w = (const float*)d_in[7];
    const float* proj_b = (const float*)d_in[8];
    const float* n2g    = (const float*)d_in[9];
    const float* n2b    = (const float*)d_in[10];
    const float* fc1_w  = (const float*)d_in[11];
    const float* fc1_b  = (const float*)d_in[12];
    const float* fc2_w  = (const float*)d_in[13];
    const float* fc2_b  = (const float*)d_in[14];
    float* out = (float*)d_out;

    __half *xs, *aos, *hs, *wqkv, *wproj, *wfc1, *wfc2;
    float *x2;
    cudaGetSymbolAddress((void**)&xs,    g_xs);
    cudaGetSymbolAddress((void**)&aos,   g_aos);
    cudaGetSymbolAddress((void**)&hs,    g_hs);
    cudaGetSymbolAddress((void**)&x2,    g_x2);
    cudaGetSymbolAddress((void**)&wqkv,  g_wqkv);
    cudaGetSymbolAddress((void**)&wproj, g_wproj);
    cudaGetSymbolAddress((void**)&wfc1,  g_wfc1);
    cudaGetSymbolAddress((void**)&wfc2,  g_wfc2);

    cudaFuncSetAttribute(gemm_full<1>, cudaFuncAttributeMaxDynamicSharedMemorySize, SMEM_FULL);
    cudaFuncSetAttribute(gemm_full<2>, cudaFuncAttributeMaxDynamicSharedMemorySize, SMEM_FULL);
    cudaFuncSetAttribute(gemm_full<3>, cudaFuncAttributeMaxDynamicSharedMemorySize, SMEM_FULL);
    cudaFuncSetAttribute(gemm_pipe64,  cudaFuncAttributeMaxDynamicSharedMemorySize, SMEM_P64);
    cudaFuncSetAttribute(attn_mma,     cudaFuncAttributeMaxDynamicSharedMemorySize, SMEM_ATTN);

    const int MB = MROWS / 64;  // 3136

    prep_all<<<1728, 256>>>(qkv_w, proj_w, fc1_w, fc2_w);
    prep_cmb<<<24, 256>>>(amask, rpb);
    // 1) QKV GEMM with fused LN1 (reads x directly)
    gemm_full<1><<<dim3(3, MB), 256, SMEM_FULL>>>(nullptr, wqkv, qkv_b, nullptr, x, nullptr,
                                                  n1g, n1b, nullptr);
    // 2) attention
    attn_mma<<<NWIN, 256, SMEM_ATTN>>>(aos);
    // 3) proj + shortcut -> x2, fused LN2 -> xs
    gemm_full<2><<<dim3(1, MB), 256, SMEM_FULL>>>(aos, wproj, proj_b, x2, x, nullptr,
                                                  n2g, n2b, xs);
    // 4) fc1 + gelu -> hs
    gemm_full<3><<<dim3(4, MB), 256, SMEM_FULL>>>(xs, wfc1, fc1_b, nullptr, nullptr, hs,
                                                  nullptr, nullptr, nullptr);
    // 5) fc2 + residual -> out
    gemm_pipe64<<<dim3(1, MB), 256, SMEM_P64>>>(hs, wfc2, fc2_b, out, x2);
}

// round 11
// speedup vs baseline: 1.0937x; 1.0937x over previous
#include <cuda_runtime.h>
#include <cuda_fp16.h>
#include <math.h>
#include <stdint.h>

// ---------------- problem constants ----------------
#define BATCH   16
#define IMG     112
#define CC      192
#define NHEADS  6
#define DHEAD   32
#define WSZ     7
#define NTOK    49
#define NWIN    4096
#define MROWS   200704
#define HID     768

// ---------------- device scratch ----------------
__device__ __half g_xs [(size_t)MROWS * CC];     // LN1/LN2 output
__device__ __half g_aos[(size_t)MROWS * CC];
__device__ __half g_hs [(size_t)MROWS * HID];
__device__ __half g_q[(size_t)NWIN * NHEADS * NTOK * DHEAD];
__device__ __half g_k[(size_t)NWIN * NHEADS * NTOK * DHEAD];
__device__ __half g_v[(size_t)NWIN * NHEADS * NTOK * DHEAD];
__device__ float g_x2[(size_t)MROWS * CC];
__device__ __half g_wqkv [(size_t)576 * 192];
__device__ __half g_wproj[(size_t)192 * 192];
__device__ __half g_wfc1 [(size_t)768 * 192];
__device__ __half g_wfc2 [(size_t)192 * 768];
__device__ __half g_cmb[(size_t)4 * NHEADS * 64 * 56];

// ---------------- helpers ----------------
__device__ __forceinline__ uint32_t smem_to_u32(const void* p) {
    uint32_t a;
    asm("{ .reg .u64 t; cvta.to.shared.u64 t, %1; cvt.u32.u64 %0, t; }" : "=r"(a) : "l"(p));
    return a;
}
__device__ __forceinline__ void cp16(uint32_t sm, const void* gp) {
    asm volatile("cp.async.cg.shared.global [%0], [%1], 16;" :: "r"(sm), "l"(gp));
}
__device__ __forceinline__ void cp_commit() { asm volatile("cp.async.commit_group;"); }
__device__ __forceinline__ void cp_wait1()  { asm volatile("cp.async.wait_group 1;"); }
__device__ __forceinline__ void cp_wait0()  { asm volatile("cp.async.wait_group 0;"); }

__device__ __forceinline__ void ldm4(uint32_t& x0, uint32_t& x1, uint32_t& x2, uint32_t& x3, uint32_t addr) {
    asm volatile("ldmatrix.sync.aligned.m8n8.x4.shared.b16 {%0,%1,%2,%3}, [%4];"
                 : "=r"(x0), "=r"(x1), "=r"(x2), "=r"(x3) : "r"(addr));
}
__device__ __forceinline__ void ldm4t(uint32_t& x0, uint32_t& x1, uint32_t& x2, uint32_t& x3, uint32_t addr) {
    asm volatile("ldmatrix.sync.aligned.m8n8.x4.trans.shared.b16 {%0,%1,%2,%3}, [%4];"
                 : "=r"(x0), "=r"(x1), "=r"(x2), "=r"(x3) : "r"(addr));
}
__device__ __forceinline__ void mma16816(float& d0, float& d1, float& d2, float& d3,
                                         uint32_t a0, uint32_t a1, uint32_t a2, uint32_t a3,
                                         uint32_t b0, uint32_t b1) {
    asm volatile("mma.sync.aligned.m16n8k16.row.col.f32.f16.f16.f32 "
                 "{%0,%1,%2,%3},{%4,%5,%6,%7},{%8,%9},{%0,%1,%2,%3};"
                 : "+f"(d0), "+f"(d1), "+f"(d2), "+f"(d3)
                 : "r"(a0), "r"(a1), "r"(a2), "r"(a3), "r"(b0), "r"(b1));
}
__device__ __forceinline__ uint32_t f22u(float a, float b) {
    __half2 h = __floats2half2_rn(a, b);
    return *(uint32_t*)&h;
}
// full-K tile: rows of 192 halves (384B, 24 x 16B chunks)
__device__ __forceinline__ uint32_t full_off(int row, int c) {
    return (uint32_t)(row * 384 + (((c & 24) | ((c ^ row) & 7)) << 4));
}
// 64-half tile: rows of 128B, 8 x 16B chunks
__device__ __forceinline__ uint32_t t64_addr(uint32_t base, int row, int c) {
    return base + row * 128 + (((c ^ row) & 7) << 4);
}
__device__ __forceinline__ float gelu_exact(float x) {
    return 0.5f * x * (1.f + erff(x * 0.70710678118654752f));
}

// ---------------- merged weight prep ----------------
__global__ void prep_all(const float* __restrict__ qkv_w, const float* __restrict__ proj_w,
                         const float* __restrict__ fc1_w, const float* __restrict__ fc2_w) {
    int i = blockIdx.x * 256 + threadIdx.x;
    const float* W; __half* D; int K, N, off;
    if (i < 110592)      { W = qkv_w;  D = g_wqkv;  K = 192; N = 576; off = i; }
    else if (i < 147456) { W = proj_w; D = g_wproj; K = 192; N = 192; off = i - 110592; }
    else if (i < 294912) { W = fc1_w;  D = g_wfc1;  K = 192; N = 768; off = i - 147456; }
    else if (i < 442368) { W = fc2_w;  D = g_wfc2;  K = 768; N = 192; off = i - 294912; }
    else return;
    int k = off / N, n = off - k * N;
    D[(size_t)n * K + k] = __float2half(W[off]);
}

// ---------------- bias+mask table prep ----------------
__global__ void prep_cmb(const float* __restrict__ amask, const float* __restrict__ rpb) {
    int ch = blockIdx.x;
    int cls = ch / NHEADS, head = ch - cls * NHEADS;
    int wi_rep = (cls >> 1 ? 240 : 0) + ((cls & 1) ? 15 : 0);
    __half* dst = g_cmb + (size_t)ch * (64 * 56);
    for (int idx = threadIdx.x; idx < 64 * 56; idx += 256) {
        int r = idx / 56, c = idx - r * 56;
        float v;
        if (r < NTOK && c < NTOK) {
            int i1 = r / WSZ, j1 = r - i1 * WSZ;
            int i2 = c / WSZ, j2 = c - i2 * WSZ;
            int rel = (i1 - i2 + 6) * 13 + (j1 - j2 + 6);
            v = rpb[rel * NHEADS + head] + amask[((size_t)wi_rep * NTOK + r) * NTOK + c];
        } else {
            v = -100.f;
        }
        dst[idx] = __float2half(v);
    }
}

// ---------------- LN1 (fused shift + window partition) ----------------
__global__ __launch_bounds__(256) void ln1_kernel(const float* __restrict__ src_full,
                                                  const float* __restrict__ gam,
                                                  const float* __restrict__ bet,
                                                  __half* __restrict__ out) {
    int t = blockIdx.x * 8 + (threadIdx.x >> 5);
    int lane = threadIdx.x & 31;
    int win = t / NTOK, n = t - win * NTOK;
    int b = win >> 8, wi = win & 255;
    int hh = (wi >> 4) * WSZ + n / WSZ;
    int ww = (wi & 15) * WSZ + n % WSZ;
    int sh = hh + 3; if (sh >= IMG) sh -= IMG;
    int sw = ww + 3; if (sw >= IMG) sw -= IMG;
    const float* src = src_full + (size_t)((b * IMG + sh) * IMG + sw) * CC;

    float v[6]; float s = 0.f, s2 = 0.f;
    #pragma unroll
    for (int i = 0; i < 6; i++) { float a = src[i * 32 + lane]; v[i] = a; s += a; s2 += a * a; }
    #pragma unroll
    for (int o = 16; o; o >>= 1) {
        s  += __shfl_xor_sync(0xffffffffu, s,  o);
        s2 += __shfl_xor_sync(0xffffffffu, s2, o);
    }
    float mean = s * (1.f / 192.f);
    float var  = s2 * (1.f / 192.f) - mean * mean;
    float rstd = rsqrtf(var + 1e-5f);
    __half* dst = out + (size_t)t * CC;
    #pragma unroll
    for (int i = 0; i < 6; i++) {
        int c = i * 32 + lane;
        dst[c] = __float2half((v[i] - mean) * rstd * gam[c] + bet[c]);
    }
}

// ================= gemm_full: K=192 resident, no K-loop =================
// BM=64, BN=192. 256 thr (8 warps 2x4), warp tile 32x48, 2 CTA/SM.
#define SMEM_FULL 98304
template<int EPI>
__global__ __launch_bounds__(256, 2)
void gemm_full(const __half* __restrict__ A2, const __half* __restrict__ B2,
               const float* __restrict__ bias, float* __restrict__ outF,
               const float* __restrict__ addsrc, __half* __restrict__ outS,
               const float* __restrict__ g2, const float* __restrict__ b2,
               __half* __restrict__ xsOut) {
    extern __shared__ __align__(16) char sm_dyn[];
    uint32_t a_base = smem_to_u32(sm_dyn);
    uint32_t b_base = a_base + 24576;

    int tid = threadIdx.x, lane = tid & 31, wid = tid >> 5;
    int wm = wid >> 2, wn = wid & 3;
    int bm = blockIdx.y * 64, bn = blockIdx.x * 192;
    const int K = 192;

    // ---- load whole A (64x192) + B slice (192x192) via cp.async ----
    {
        const __half* Ag = A2 + (size_t)bm * K;
        #pragma unroll
        for (int i = 0; i < 6; i++) {
            int t = tid + i * 256, row = t / 24, c = t - row * 24;
            cp16(a_base + full_off(row, c), Ag + (size_t)row * K + c * 8);
        }
        const __half* Bg = B2 + (size_t)bn * K;
        #pragma unroll
        for (int i = 0; i < 18; i++) {
            int t = tid + i * 256, row = t / 24, c = t - row * 24;
            cp16(b_base + full_off(row, c), Bg + (size_t)row * K + c * 8);
        }
    }
    cp_commit();
    cp_wait0();
    __syncthreads();

    // ---- 12 k-steps, no barriers ----
    float acc[2][6][4] = {};
    int arow = wm * 32 + (lane & 15);
    int bnrow = wn * 48 + (lane & 7) + ((lane >> 4) << 3);
    int bk8 = (lane >> 3) & 1;
    #pragma unroll
    for (int ks = 0; ks < 12; ks++) {
        uint32_t af[2][4];
        #pragma unroll
        for (int mt = 0; mt < 2; mt++)
            ldm4(af[mt][0], af[mt][1], af[mt][2], af[mt][3],
                 a_base + full_off(arow + mt * 16, ks * 2 + (lane >> 4)));
        uint32_t bf[6][2];
        #pragma unroll
        for (int pr = 0; pr < 3; pr++)
            ldm4(bf[2 * pr][0], bf[2 * pr][1], bf[2 * pr + 1][0], bf[2 * pr + 1][1],
                 b_base + full_off(bnrow + pr * 16, ks * 2 + bk8));
        #pragma unroll
        for (int mt = 0; mt < 2; mt++)
            #pragma unroll
            for (int nt = 0; nt < 6; nt++)
                mma16816(acc[mt][nt][0], acc[mt][nt][1], acc[mt][nt][2], acc[mt][nt][3],
                         af[mt][0], af[mt][1], af[mt][2], af[mt][3],
                         bf[nt][0], bf[nt][1]);
    }
    __syncthreads();

    float2 bcol[6];
    #pragma unroll
    for (int nt = 0; nt < 6; nt++) {
        int col = bn + wn * 48 + nt * 8 + 2 * (lane & 3);
        bcol[nt] = *(const float2*)&bias[col];
    }

    if constexpr (EPI == 2) {
        float* red  = (float*)sm_dyn;
        float* redq = red + 64 * 17;
        int slot = wn * 4 + (lane & 3);

        #pragma unroll
        for (int mt = 0; mt < 2; mt++) {
            #pragma unroll
            for (int half = 0; half < 2; half++) {
                int rl = wm * 32 + mt * 16 + (lane >> 2) + half * 8;
                int row = bm + rl;
                int win = row / NTOK, n = row - win * NTOK;
                int b = win >> 8, wi = win & 255;
                int hh = (wi >> 4) * WSZ + n / WSZ;
                int ww = (wi & 15) * WSZ + n % WSZ;
                int p = hh + 3; if (p >= IMG) p -= IMG;
                int q = ww + 3; if (q >= IMG) q -= IMG;
                size_t pixbase = (size_t)((b * IMG + p) * IMG + q) * CC;
                float s = 0.f, sq2 = 0.f;
                #pragma unroll
                for (int nt = 0; nt < 6; nt++) {
                    int col = wn * 48 + nt * 8 + 2 * (lane & 3);
                    float2 sc = *(const float2*)&addsrc[pixbase + col];
                    float vx = acc[mt][nt][half * 2] + bcol[nt].x + sc.x;
                    float vy = acc[mt][nt][half * 2 + 1] + bcol[nt].y + sc.y;
                    acc[mt][nt][half * 2] = vx;
                    acc[mt][nt][half * 2 + 1] = vy;
                    *(float2*)&outF[pixbase + col] = make_float2(vx, vy);
                    s += vx + vy;
                    sq2 += vx * vx + vy * vy;
                }
                red [rl * 17 + slot] = s;
                redq[rl * 17 + slot] = sq2;
            }
        }
        __syncthreads();
        if (tid < 64) {
            float s = 0.f, qq = 0.f;
            #pragma unroll
            for (int i = 0; i < 16; i++) { s += red[tid * 17 + i]; qq += redq[tid * 17 + i]; }
            float mean = s * (1.f / 192.f);
            float var = qq * (1.f / 192.f) - mean * mean;
            red [tid * 17 + 16] = mean;
            redq[tid * 17 + 16] = rsqrtf(var + 1e-5f);
        }
        __syncthreads();
        #pragma unroll
        for (int mt = 0; mt < 2; mt++) {
            #pragma unroll
            for (int half = 0; half < 2; half++) {
                int rl = wm * 32 + mt * 16 + (lane >> 2) + half * 8;
                int row = bm + rl;
                int win = row / NTOK, n = row - win * NTOK;
                int b = win >> 8, wi = win & 255;
                int hh = (wi >> 4) * WSZ + n / WSZ;
                int ww = (wi & 15) * WSZ + n % WSZ;
                int p = hh + 3; if (p >= IMG) p -= IMG;
                int q = ww + 3; if (q >= IMG) q -= IMG;
                size_t pixbase = (size_t)((b * IMG + p) * IMG + q) * CC;
                float mean = red [rl * 17 + 16];
                float rstd = redq[rl * 17 + 16];
                #pragma unroll
                for (int nt = 0; nt < 6; nt++) {
                    int col = wn * 48 + nt * 8 + 2 * (lane & 3);
                    float2 gv = *(const float2*)&g2[col];
                    float2 bv = *(const float2*)&b2[col];
                    float yx = (acc[mt][nt][half * 2] - mean) * rstd * gv.x + bv.x;
                    float yy = (acc[mt][nt][half * 2 + 1] - mean) * rstd * gv.y + bv.y;
                    *(__half2*)&xsOut[pixbase + col] = __floats2half2_rn(yx, yy);
                }
            }
        }
    } else {
        #pragma unroll
        for (int mt = 0; mt < 2; mt++) {
            #pragma unroll
            for (int half = 0; half < 2; half++) {
                int row = bm + wm * 32 + mt * 16 + (lane >> 2) + half * 8;
                if constexpr (EPI == 1) {
                    int t3 = bn / 192;
                    float scale = (t3 == 0) ? 0.17677669529663687f : 1.f;
                    __half* dst = (t3 == 0) ? g_q : ((t3 == 1) ? g_k : g_v);
                    int win = row / NTOK, n = row - win * NTOK;
                    #pragma unroll
                    for (int nt = 0; nt < 6; nt++) {
                        int col = wn * 48 + nt * 8 + 2 * (lane & 3);
                        int head = col >> 5, dd = col & 31;
                        float vx = (acc[mt][nt][half * 2] + bcol[nt].x) * scale;
                        float vy = (acc[mt][nt][half * 2 + 1] + bcol[nt].y) * scale;
                        *(__half2*)&dst[(((size_t)win * NHEADS + head) * NTOK + n) * DHEAD + dd] =
                            __floats2half2_rn(vx, vy);
                    }
                } else {  // EPI == 3
                    size_t rb = (size_t)row * HID;
                    #pragma unroll
                    for (int nt = 0; nt < 6; nt++) {
                        int col = bn + wn * 48 + nt * 8 + 2 * (lane & 3);
                        float gx = gelu_exact(acc[mt][nt][half * 2] + bcol[nt].x);
                        float gy = gelu_exact(acc[mt][nt][half * 2 + 1] + bcol[nt].y);
                        *(__half2*)&outS[rb + col] = __floats2half2_rn(gx, gy);
                    }
                }
            }
        }
    }
}

// ================= gemm_pipe64 (fc2: K=768): 3-stage BK=64 pipeline =================
#define SMEM_P64 98304
__global__ __launch_bounds__(256, 2)
void gemm_pipe64(const __half* __restrict__ A2, const __half* __restrict__ B2,
                 const float* __restrict__ bias, float* __restrict__ outF,
                 const float* __restrict__ addsrc) {
    extern __shared__ __align__(16) char sm_dyn[];
    uint32_t a_base = smem_to_u32(sm_dyn);
    uint32_t b_base = a_base + 24576;
    const int K = 768;

    int tid = threadIdx.x, lane = tid & 31, wid = tid >> 5;
    int wm = wid >> 2, wn = wid & 3;
    int bm = blockIdx.y * 64, bn = blockIdx.x * 192;
    const int NC = 12;

    float acc[2][6][4] = {};

    auto issue = [&](int buf, int cc) {
        const __half* Ag = A2 + (size_t)bm * K + cc * 64;
        const __half* Bg = B2 + (size_t)bn * K + cc * 64;
        uint32_t ab = a_base + buf * 8192;
        uint32_t bb = b_base + buf * 24576;
        #pragma unroll
        for (int i = 0; i < 2; i++) {
            int t = tid + i * 256, row = t >> 3, c = t & 7;
            cp16(t64_addr(ab, row, c), Ag + (size_t)row * K + c * 8);
        }
        #pragma unroll
        for (int i = 0; i < 6; i++) {
            int t = tid + i * 256, row = t >> 3, c = t & 7;
            cp16(t64_addr(bb, row, c), Bg + (size_t)row * K + c * 8);
        }
        cp_commit();
    };

    issue(0, 0);
    issue(1, 1);

    for (int cc = 0; cc < NC; cc++) {
        int buf = cc % 3;
        if (cc + 1 < NC) cp_wait1(); else cp_wait0();
        __syncthreads();
        if (cc + 2 < NC) issue((cc + 2) % 3, cc + 2);

        uint32_t ab = a_base + buf * 8192;
        uint32_t bb = b_base + buf * 24576;
        int arow = wm * 32 + (lane & 15);
        int bnrow = wn * 48 + (lane & 7) + ((lane >> 4) << 3);
        int bk8 = (lane >> 3) & 1;
        #pragma unroll
        for (int ks = 0; ks < 4; ks++) {
            uint32_t af[2][4];
            #pragma unroll
            for (int mt = 0; mt < 2; mt++)
                ldm4(af[mt][0], af[mt][1], af[mt][2], af[mt][3],
                     t64_addr(ab, arow + mt * 16, ks * 2 + (lane >> 4)));
            uint32_t bf[6][2];
            #pragma unroll
            for (int pr = 0; pr < 3; pr++)
                ldm4(bf[2 * pr][0], bf[2 * pr][1], bf[2 * pr + 1][0], bf[2 * pr + 1][1],
                     t64_addr(bb, bnrow + pr * 16, ks * 2 + bk8));
            #pragma unroll
            for (int mt = 0; mt < 2; mt++)
                #pragma unroll
                for (int nt = 0; nt < 6; nt++)
                    mma16816(acc[mt][nt][0], acc[mt][nt][1], acc[mt][nt][2], acc[mt][nt][3],
                             af[mt][0], af[mt][1], af[mt][2], af[mt][3],
                             bf[nt][0], bf[nt][1]);
        }
    }

    float2 bcol[6];
    #pragma unroll
    for (int nt = 0; nt < 6; nt++) {
        int col = bn + wn * 48 + nt * 8 + 2 * (lane & 3);
        bcol[nt] = *(const float2*)&bias[col];
    }
    #pragma unroll
    for (int mt = 0; mt < 2; mt++) {
        #pragma unroll
        for (int half = 0; half < 2; half++) {
            int row = bm + wm * 32 + mt * 16 + (lane >> 2) + half * 8;
            size_t rb = (size_t)row * 192;
            #pragma unroll
            for (int nt = 0; nt < 6; nt++) {
                int col = bn + wn * 48 + nt * 8 + 2 * (lane & 3);
                float2 s = *(const float2*)&addsrc[rb + col];
                float vx = acc[mt][nt][half * 2] + bcol[nt].x + s.x;
                float vy = acc[mt][nt][half * 2 + 1] + bcol[nt].y + s.y;
                *(float2*)&outF[rb + col] = make_float2(vx, vy);
            }
        }
    }
}

// ---------------- attention: 256 thr, 2 heads parallel, cp.async double-buffered ----------------
#define SMEM_ATTN 90112
__global__ __launch_bounds__(256) void attn_mma(__half* __restrict__ outs) {
    extern __shared__ __align__(16) char sm_dyn[];
    uint32_t smb = smem_to_u32(sm_dyn);
    int win = blockIdx.x;
    int wi = win & 255;
    int cls = (((wi >> 4) == 15) ? 2 : 0) + (((wi & 15) == 15) ? 1 : 0);
    int tid = threadIdx.x;
    int wg = tid >> 7;
    int t = tid & 127;
    int lane = t & 31, wmg = t >> 5;
    int g = lane >> 3, r8 = lane & 7;
    int mr = wmg * 16;

    uint4 z = make_uint4(0, 0, 0, 0);
    for (int i = tid; i < 3840; i += 256) ((uint4*)sm_dyn)[i] = z;
    __syncthreads();

    auto load_pair = [&](int buf, int h2) {
        int h = h2 * 2 + wg;
        uint32_t qb = smb + (buf * 2 + wg) * 15360;
        const uint4* qg = (const uint4*)(g_q + (size_t)(win * NHEADS + h) * (NTOK * DHEAD));
        const uint4* kg = (const uint4*)(g_k + (size_t)(win * NHEADS + h) * (NTOK * DHEAD));
        const uint4* vg = (const uint4*)(g_v + (size_t)(win * NHEADS + h) * (NTOK * DHEAD));
        for (int i = t; i < 196; i += 128) {
            int r = i >> 2, c = i & 3;
            uint32_t off = r * 80 + c * 16;
            cp16(qb + off, qg + i);
            cp16(qb + 5120 + off, kg + i);
            cp16(qb + 10240 + off, vg + i);
        }
        uint32_t cb = smb + 61440 + (buf * 2 + wg) * 7168;
        const uint4* cg = (const uint4*)(g_cmb + (size_t)(cls * NHEADS + h) * (64 * 56));
        for (int i = t; i < 448; i += 128) cp16(cb + i * 16, cg + i);
        cp_commit();
    };

    load_pair(0, 0);

    int buf = 0;
    for (int h2 = 0; h2 < 3; h2++) {
        int h = h2 * 2 + wg;
        if (h2 < 2) load_pair(buf ^ 1, h2 + 1);
        if (h2 < 2) cp_wait1(); else cp_wait0();
        __syncthreads();

        uint32_t qbase = smb + (buf * 2 + wg) * 15360;
        uint32_t kbase = qbase + 5120, vbase = qbase + 10240;
        uint32_t cbase = smb + 61440 + (buf * 2 + wg) * 7168;

        uint32_t qf[2][4];
        #pragma unroll
        for (int ks = 0; ks < 2; ks++) {
            int row = mr + (g & 1) * 8 + r8;
            int col = ks * 16 + (g >> 1) * 8;
            ldm4(qf[ks][0], qf[ks][1], qf[ks][2], qf[ks][3], qbase + row * 80 + col * 2);
        }

        float sacc[7][4] = {};
        #pragma unroll
        for (int ks = 0; ks < 2; ks++) {
            #pragma unroll
            for (int np = 0; np < 4; np++) {
                int row = np * 16 + ((g >> 1) & 1) * 8 + r8;
                int col = ks * 16 + (g & 1) * 8;
                uint32_t b0, b1, b2, b3;
                ldm4(b0, b1, b2, b3, kbase + row * 80 + col * 2);
                mma16816(sacc[2 * np][0], sacc[2 * np][1], sacc[2 * np][2], sacc[2 * np][3],
                         qf[ks][0], qf[ks][1], qf[ks][2], qf[ks][3], b0, b1);
                if (np < 3)
                    mma16816(sacc[2 * np + 1][0], sacc[2 * np + 1][1], sacc[2 * np + 1][2], sacc[2 * np + 1][3],
                             qf[ks][0], qf[ks][1], qf[ks][2], qf[ks][3], b2, b3);
            }
        }

        #pragma unroll
        for (int np = 0; np < 4; np++) {
            int row = mr + (g & 1) * 8 + r8;
            int colc = 2 * np + ((g >> 1) & 1); if (colc > 6) colc = 6;
            uint32_t c0, c1, c2, c3;
            ldm4(c0, c1, c2, c3, cbase + row * 112 + colc * 8 * 2);
            float2 f;
            f = __half22float2(*(__half2*)&c0); sacc[2 * np][0] += f.x; sacc[2 * np][1] += f.y;
            f = __half22float2(*(__half2*)&c1); sacc[2 * np][2] += f.x; sacc[2 * np][3] += f.y;
            if (np < 3) {
                f = __half22float2(*(__half2*)&c2); sacc[2 * np + 1][0] += f.x; sacc[2 * np + 1][1] += f.y;
                f = __half22float2(*(__half2*)&c3); sacc[2 * np + 1][2] += f.x; sacc[2 * np + 1][3] += f.y;
            }
        }

        float mx0 = -1e30f, mx8 = -1e30f;
        #pragma unroll
        for (int nt = 0; nt < 7; nt++) {
            mx0 = fmaxf(mx0, fmaxf(sacc[nt][0], sacc[nt][1]));
            mx8 = fmaxf(mx8, fmaxf(sacc[nt][2], sacc[nt][3]));
        }
        #pragma unroll
        for (int o = 1; o <= 2; o <<= 1) {
            mx0 = fmaxf(mx0, __shfl_xor_sync(0xffffffffu, mx0, o));
            mx8 = fmaxf(mx8, __shfl_xor_sync(0xffffffffu, mx8, o));
        }
        float s0 = 0.f, s8 = 0.f;
        #pragma unroll
        for (int nt = 0; nt < 7; nt++) {
            sacc[nt][0] = __expf(sacc[nt][0] - mx0); s0 += sacc[nt][0];
            sacc[nt][1] = __expf(sacc[nt][1] - mx0); s0 += sacc[nt][1];
            sacc[nt][2] = __expf(sacc[nt][2] - mx8); s8 += sacc[nt][2];
            sacc[nt][3] = __expf(sacc[nt][3] - mx8); s8 += sacc[nt][3];
        }
        #pragma unroll
        for (int o = 1; o <= 2; o <<= 1) {
            s0 += __shfl_xor_sync(0xffffffffu, s0, o);
            s8 += __shfl_xor_sync(0xffffffffu, s8, o);
        }
        float inv0 = 1.f / s0, inv8 = 1.f / s8;
        #pragma unroll
        for (int nt = 0; nt < 7; nt++) {
            sacc[nt][0] *= inv0; sacc[nt][1] *= inv0;
            sacc[nt][2] *= inv8; sacc[nt][3] *= inv8;
        }

        float oacc[4][4] = {};
        #pragma unroll
        for (int kt = 0; kt < 4; kt++) {
            uint32_t a0 = f22u(sacc[2 * kt][0], sacc[2 * kt][1]);
            uint32_t a1 = f22u(sacc[2 * kt][2], sacc[2 * kt][3]);
            uint32_t a2 = 0, a3 = 0;
            if (kt < 3) {
                a2 = f22u(sacc[2 * kt + 1][0], sacc[2 * kt + 1][1]);
                a3 = f22u(sacc[2 * kt + 1][2], sacc[2 * kt + 1][3]);
            }
            #pragma unroll
            for (int dp = 0; dp < 2; dp++) {
                int row = kt * 16 + (g & 1) * 8 + r8;
                int col = dp * 16 + ((g >> 1) & 1) * 8;
                uint32_t b0, b1, b2, b3;
                ldm4t(b0, b1, b2, b3, vbase + row * 80 + col * 2);
                mma16816(oacc[2 * dp][0], oacc[2 * dp][1], oacc[2 * dp][2], oacc[2 * dp][3],
                         a0, a1, a2, a3, b0, b1);
                mma16816(oacc[2 * dp + 1][0], oacc[2 * dp + 1][1], oacc[2 * dp + 1][2], oacc[2 * dp + 1][3],
                         a0, a1, a2, a3, b2, b3);
            }
        }

        int r0 = mr + (lane >> 2);
        int cbase2 = h * DHEAD + 2 * (lane & 3);
        if (r0 < NTOK) {
            size_t ob = ((size_t)win * NTOK + r0) * CC + cbase2;
            #pragma unroll
            for (int dn = 0; dn < 4; dn++)
                *(__half2*)&outs[ob + dn * 8] = __floats2half2_rn(oacc[dn][0], oacc[dn][1]);
        }
        int r1 = r0 + 8;
        if (r1 < NTOK) {
            size_t ob = ((size_t)win * NTOK + r1) * CC + cbase2;
            #pragma unroll
            for (int dn = 0; dn < 4; dn++)
                *(__half2*)&outs[ob + dn * 8] = __floats2half2_rn(oacc[dn][2], oacc[dn][3]);
        }
        __syncthreads();
        buf ^= 1;
    }
}

// ---------------- launch ----------------
extern "C" void kernel_launch(void* const* d_in, const int* in_sizes, int n_in,
                              void* d_out, int out_size) {
    const float* x      = (const float*)d_in[0];
    const float* amask  = (const float*)d_in[1];
    const float* n1g    = (const float*)d_in[2];
    const float* n1b    = (const float*)d_in[3];
    const float* qkv_w  = (const float*)d_in[4];
    const float* qkv_b  = (const float*)d_in[5];
    const float* rpb    = (const float*)d_in[6];
    const float* proj_w = (const float*)d_in[7];
    const float* proj_b = (const float*)d_in[8];
    const float* n2g    = (const float*)d_in[9];
    const float* n2b    = (const float*)d_in[10];
    const float* fc1_w  = (const float*)d_in[11];
    const float* fc1_b  = (const float*)d_in[12];
    const float* fc2_w  = (const float*)d_in[13];
    const float* fc2_b  = (const float*)d_in[14];
    float* out = (float*)d_out;

    __half *xs, *aos, *hs, *wqkv, *wproj, *wfc1, *wfc2;
    float *x2;
    cudaGetSymbolAddress((void**)&xs,    g_xs);
    cudaGetSymbolAddress((void**)&aos,   g_aos);
    cudaGetSymbolAddress((void**)&hs,    g_hs);
    cudaGetSymbolAddress((void**)&x2,    g_x2);
    cudaGetSymbolAddress((void**)&wqkv,  g_wqkv);
    cudaGetSymbolAddress((void**)&wproj, g_wproj);
    cudaGetSymbolAddress((void**)&wfc1,  g_wfc1);
    cudaGetSymbolAddress((void**)&wfc2,  g_wfc2);

    cudaFuncSetAttribute(gemm_full<1>, cudaFuncAttributeMaxDynamicSharedMemorySize, SMEM_FULL);
    cudaFuncSetAttribute(gemm_full<2>, cudaFuncAttributeMaxDynamicSharedMemorySize, SMEM_FULL);
    cudaFuncSetAttribute(gemm_full<3>, cudaFuncAttributeMaxDynamicSharedMemorySize, SMEM_FULL);
    cudaFuncSetAttribute(gemm_pipe64,  cudaFuncAttributeMaxDynamicSharedMemorySize, SMEM_P64);
    cudaFuncSetAttribute(attn_mma,     cudaFuncAttributeMaxDynamicSharedMemorySize, SMEM_ATTN);

    const int MB = MROWS / 64;  // 3136

    prep_all<<<1728, 256>>>(qkv_w, proj_w, fc1_w, fc2_w);
    prep_cmb<<<24, 256>>>(amask, rpb);
    // 1) LN1 + shift + window partition -> fp16
    ln1_kernel<<<MROWS / 8, 256>>>(x, n1g, n1b, xs);
    // 2) QKV GEMM
    gemm_full<1><<<dim3(3, MB), 256, SMEM_FULL>>>(xs, wqkv, qkv_b, nullptr, nullptr, nullptr,
                                                  nullptr, nullptr, nullptr);
    // 3) attention
    attn_mma<<<NWIN, 256, SMEM_ATTN>>>(aos);
    // 4) proj + shortcut -> x2, fused LN2 -> xs
    gemm_full<2><<<dim3(1, MB), 256, SMEM_FULL>>>(aos, wproj, proj_b, x2, x, nullptr,
                                                  n2g, n2b, xs);
    // 5) fc1 + gelu -> hs
    gemm_full<3><<<dim3(4, MB), 256, SMEM_FULL>>>(xs, wfc1, fc1_b, nullptr, nullptr, hs,
                                                  nullptr, nullptr, nullptr);
    // 6) fc2 + residual -> out
    gemm_pipe64<<<dim3(1, MB), 256, SMEM_P64>>>(hs, wfc2, fc2_b, out, x2);
}

// round 13
// speedup vs baseline: 1.1061x; 1.0113x over previous
#include <cuda_runtime.h>
#include <cuda_fp16.h>
#include <math.h>
#include <stdint.h>

// ---------------- problem constants ----------------
#define BATCH   16
#define IMG     112
#define CC      192
#define NHEADS  6
#define DHEAD   32
#define WSZ     7
#define NTOK    49
#define NWIN    4096
#define MROWS   200704
#define HID     768

// ---------------- device scratch ----------------
__device__ __half g_xs [(size_t)MROWS * CC];     // LN1 output (windowed)
__device__ __half g_aos[(size_t)MROWS * CC];
__device__ __half g_hs [(size_t)MROWS * HID];    // gelu(fc1), PIXEL order
__device__ __half g_q[(size_t)NWIN * NHEADS * NTOK * DHEAD];
__device__ __half g_k[(size_t)NWIN * NHEADS * NTOK * DHEAD];
__device__ __half g_v[(size_t)NWIN * NHEADS * NTOK * DHEAD];
__device__ float g_x2[(size_t)MROWS * CC];       // PIXEL order
__device__ __half g_wqkv [(size_t)576 * 192];
__device__ __half g_wproj[(size_t)192 * 192];
__device__ __half g_wfc1 [(size_t)768 * 192];
__device__ __half g_wfc2 [(size_t)192 * 768];
__device__ __half g_cmb[(size_t)4 * NHEADS * 64 * 56];

// ---------------- helpers ----------------
__device__ __forceinline__ uint32_t smem_to_u32(const void* p) {
    uint32_t a;
    asm("{ .reg .u64 t; cvta.to.shared.u64 t, %1; cvt.u32.u64 %0, t; }" : "=r"(a) : "l"(p));
    return a;
}
__device__ __forceinline__ void cp16(uint32_t sm, const void* gp) {
    asm volatile("cp.async.cg.shared.global [%0], [%1], 16;" :: "r"(sm), "l"(gp));
}
__device__ __forceinline__ void cp_commit() { asm volatile("cp.async.commit_group;"); }
__device__ __forceinline__ void cp_wait1()  { asm volatile("cp.async.wait_group 1;"); }
__device__ __forceinline__ void cp_wait0()  { asm volatile("cp.async.wait_group 0;"); }

__device__ __forceinline__ void ldm4(uint32_t& x0, uint32_t& x1, uint32_t& x2, uint32_t& x3, uint32_t addr) {
    asm volatile("ldmatrix.sync.aligned.m8n8.x4.shared.b16 {%0,%1,%2,%3}, [%4];"
                 : "=r"(x0), "=r"(x1), "=r"(x2), "=r"(x3) : "r"(addr));
}
__device__ __forceinline__ void ldm4t(uint32_t& x0, uint32_t& x1, uint32_t& x2, uint32_t& x3, uint32_t addr) {
    asm volatile("ldmatrix.sync.aligned.m8n8.x4.trans.shared.b16 {%0,%1,%2,%3}, [%4];"
                 : "=r"(x0), "=r"(x1), "=r"(x2), "=r"(x3) : "r"(addr));
}
__device__ __forceinline__ void mma16816(float& d0, float& d1, float& d2, float& d3,
                                         uint32_t a0, uint32_t a1, uint32_t a2, uint32_t a3,
                                         uint32_t b0, uint32_t b1) {
    asm volatile("mma.sync.aligned.m16n8k16.row.col.f32.f16.f16.f32 "
                 "{%0,%1,%2,%3},{%4,%5,%6,%7},{%8,%9},{%0,%1,%2,%3};"
                 : "+f"(d0), "+f"(d1), "+f"(d2), "+f"(d3)
                 : "r"(a0), "r"(a1), "r"(a2), "r"(a3), "r"(b0), "r"(b1));
}
__device__ __forceinline__ uint32_t f22u(float a, float b) {
    __half2 h = __floats2half2_rn(a, b);
    return *(uint32_t*)&h;
}
// full-K tile: rows of 192 halves (384B, 24 x 16B chunks)
__device__ __forceinline__ uint32_t full_off(int row, int c) {
    return (uint32_t)(row * 384 + (((c & 24) | ((c ^ row) & 7)) << 4));
}
// 64-half tile: rows of 128B, 8 x 16B chunks
__device__ __forceinline__ uint32_t t64_addr(uint32_t base, int row, int c) {
    return base + row * 128 + (((c ^ row) & 7) << 4);
}
__device__ __forceinline__ float gelu_exact(float x) {
    return 0.5f * x * (1.f + erff(x * 0.70710678118654752f));
}
// windowed row -> pixel row
__device__ __forceinline__ int pix_of_row(int row) {
    int win = row / NTOK, n = row - win * NTOK;
    int b = win >> 8, wi = win & 255;
    int hh = (wi >> 4) * WSZ + n / WSZ;
    int ww = (wi & 15) * WSZ + n % WSZ;
    int p = hh + 3; if (p >= IMG) p -= IMG;
    int q = ww + 3; if (q >= IMG) q -= IMG;
    return (b * IMG + p) * IMG + q;
}

// ---------------- merged weight prep ----------------
__global__ void prep_all(const float* __restrict__ qkv_w, const float* __restrict__ proj_w,
                         const float* __restrict__ fc1_w, const float* __restrict__ fc2_w) {
    int i = blockIdx.x * 256 + threadIdx.x;
    const float* W; __half* D; int K, N, off;
    if (i < 110592)      { W = qkv_w;  D = g_wqkv;  K = 192; N = 576; off = i; }
    else if (i < 147456) { W = proj_w; D = g_wproj; K = 192; N = 192; off = i - 110592; }
    else if (i < 294912) { W = fc1_w;  D = g_wfc1;  K = 192; N = 768; off = i - 147456; }
    else if (i < 442368) { W = fc2_w;  D = g_wfc2;  K = 768; N = 192; off = i - 294912; }
    else return;
    int k = off / N, n = off - k * N;
    D[(size_t)n * K + k] = __float2half(W[off]);
}

// ---------------- bias+mask table prep ----------------
__global__ void prep_cmb(const float* __restrict__ amask, const float* __restrict__ rpb) {
    int ch = blockIdx.x;
    int cls = ch / NHEADS, head = ch - cls * NHEADS;
    int wi_rep = (cls >> 1 ? 240 : 0) + ((cls & 1) ? 15 : 0);
    __half* dst = g_cmb + (size_t)ch * (64 * 56);
    for (int idx = threadIdx.x; idx < 64 * 56; idx += 256) {
        int r = idx / 56, c = idx - r * 56;
        float v;
        if (r < NTOK && c < NTOK) {
            int i1 = r / WSZ, j1 = r - i1 * WSZ;
            int i2 = c / WSZ, j2 = c - i2 * WSZ;
            int rel = (i1 - i2 + 6) * 13 + (j1 - j2 + 6);
            v = rpb[rel * NHEADS + head] + amask[((size_t)wi_rep * NTOK + r) * NTOK + c];
        } else {
            v = -100.f;
        }
        dst[idx] = __float2half(v);
    }
}

// ---------------- LN1 (fused shift + window partition) ----------------
__global__ __launch_bounds__(256) void ln1_kernel(const float* __restrict__ src_full,
                                                  const float* __restrict__ gam,
                                                  const float* __restrict__ bet,
                                                  __half* __restrict__ out) {
    int t = blockIdx.x * 8 + (threadIdx.x >> 5);
    int lane = threadIdx.x & 31;
    int win = t / NTOK, n = t - win * NTOK;
    int b = win >> 8, wi = win & 255;
    int hh = (wi >> 4) * WSZ + n / WSZ;
    int ww = (wi & 15) * WSZ + n % WSZ;
    int sh = hh + 3; if (sh >= IMG) sh -= IMG;
    int sw = ww + 3; if (sw >= IMG) sw -= IMG;
    const float* src = src_full + (size_t)((b * IMG + sh) * IMG + sw) * CC;

    float v[6]; float s = 0.f, s2 = 0.f;
    #pragma unroll
    for (int i = 0; i < 6; i++) { float a = src[i * 32 + lane]; v[i] = a; s += a; s2 += a * a; }
    #pragma unroll
    for (int o = 16; o; o >>= 1) {
        s  += __shfl_xor_sync(0xffffffffu, s,  o);
        s2 += __shfl_xor_sync(0xffffffffu, s2, o);
    }
    float mean = s * (1.f / 192.f);
    float var  = s2 * (1.f / 192.f) - mean * mean;
    float rstd = rsqrtf(var + 1e-5f);
    __half* dst = out + (size_t)t * CC;
    #pragma unroll
    for (int i = 0; i < 6; i++) {
        int c = i * 32 + lane;
        dst[c] = __float2half((v[i] - mean) * rstd * gam[c] + bet[c]);
    }
}

// ---- shared mainloop: 12 k-steps over resident A/B full-K tiles ----
__device__ __forceinline__ void mainloop192(uint32_t a_base, uint32_t b_base,
                                            int wm, int wn, int lane,
                                            float acc[2][6][4]) {
    int arow = wm * 32 + (lane & 15);
    int bnrow = wn * 48 + (lane & 7) + ((lane >> 4) << 3);
    int bk8 = (lane >> 3) & 1;
    #pragma unroll
    for (int ks = 0; ks < 12; ks++) {
        uint32_t af[2][4];
        #pragma unroll
        for (int mt = 0; mt < 2; mt++)
            ldm4(af[mt][0], af[mt][1], af[mt][2], af[mt][3],
                 a_base + full_off(arow + mt * 16, ks * 2 + (lane >> 4)));
        uint32_t bf[6][2];
        #pragma unroll
        for (int pr = 0; pr < 3; pr++)
            ldm4(bf[2 * pr][0], bf[2 * pr][1], bf[2 * pr + 1][0], bf[2 * pr + 1][1],
                 b_base + full_off(bnrow + pr * 16, ks * 2 + bk8));
        #pragma unroll
        for (int mt = 0; mt < 2; mt++)
            #pragma unroll
            for (int nt = 0; nt < 6; nt++)
                mma16816(acc[mt][nt][0], acc[mt][nt][1], acc[mt][nt][2], acc[mt][nt][3],
                         af[mt][0], af[mt][1], af[mt][2], af[mt][3],
                         bf[nt][0], bf[nt][1]);
    }
}

// ================= gemm_qkv: A(xs) resident, 3 wqkv chunks streamed =================
#define SMEM_QKV 98304
__global__ __launch_bounds__(256, 2)
void gemm_qkv(const __half* __restrict__ A2, const __half* __restrict__ B2,
              const float* __restrict__ bias) {
    extern __shared__ __align__(16) char sm_dyn[];
    uint32_t a_base = smem_to_u32(sm_dyn);
    uint32_t b_base = a_base + 24576;

    int tid = threadIdx.x, lane = tid & 31, wid = tid >> 5;
    int wm = wid >> 2, wn = wid & 3;
    int bm = blockIdx.x * 64;
    const int K = 192;

    {
        const __half* Ag = A2 + (size_t)bm * K;
        #pragma unroll
        for (int i = 0; i < 6; i++) {
            int t = tid + i * 256, row = t / 24, c = t - row * 24;
            cp16(a_base + full_off(row, c), Ag + (size_t)row * K + c * 8);
        }
        #pragma unroll
        for (int i = 0; i < 18; i++) {
            int t = tid + i * 256, row = t / 24, c = t - row * 24;
            cp16(b_base + full_off(row, c), B2 + (size_t)row * K + c * 8);
        }
    }
    cp_commit();

    for (int nc = 0; nc < 3; nc++) {
        cp_wait0();
        __syncthreads();

        float acc[2][6][4] = {};
        mainloop192(a_base, b_base, wm, wn, lane, acc);
        __syncthreads();

        if (nc < 2) {
            const __half* Bg = B2 + (size_t)(nc + 1) * 192 * K;
            #pragma unroll
            for (int i = 0; i < 18; i++) {
                int t = tid + i * 256, row = t / 24, c = t - row * 24;
                cp16(b_base + full_off(row, c), Bg + (size_t)row * K + c * 8);
            }
            cp_commit();
        }

        float scale = (nc == 0) ? 0.17677669529663687f : 1.f;
        __half* dst = (nc == 0) ? g_q : ((nc == 1) ? g_k : g_v);
        float2 bcol[6];
        #pragma unroll
        for (int nt = 0; nt < 6; nt++)
            bcol[nt] = *(const float2*)&bias[nc * 192 + wn * 48 + nt * 8 + 2 * (lane & 3)];

        #pragma unroll
        for (int mt = 0; mt < 2; mt++) {
            #pragma unroll
            for (int half = 0; half < 2; half++) {
                int row = bm + wm * 32 + mt * 16 + (lane >> 2) + half * 8;
                int win = row / NTOK, n = row - win * NTOK;
                #pragma unroll
                for (int nt = 0; nt < 6; nt++) {
                    int col = wn * 48 + nt * 8 + 2 * (lane & 3);
                    int head = col >> 5, dd = col & 31;
                    float vx = (acc[mt][nt][half * 2] + bcol[nt].x) * scale;
                    float vy = (acc[mt][nt][half * 2 + 1] + bcol[nt].y) * scale;
                    *(__half2*)&dst[(((size_t)win * NHEADS + head) * NTOK + n) * DHEAD + dd] =
                        __floats2half2_rn(vx, vy);
                }
            }
        }
    }
}

// ================= gemm_mlp: proj + residual -> x2, LN2 -> smem, fc1+gelu -> hs (PIXEL rows) ====
#define SMEM_MLP 107008
__global__ __launch_bounds__(256, 2)
void gemm_mlp(const __half* __restrict__ Aaos, const __half* __restrict__ Wproj,
              const float* __restrict__ pbias, float* __restrict__ x2out,
              const float* __restrict__ xsrc,
              const float* __restrict__ g2, const float* __restrict__ b2,
              const __half* __restrict__ Wfc1, const float* __restrict__ f1bias,
              __half* __restrict__ hsout) {
    extern __shared__ __align__(16) char sm_dyn[];
    uint32_t a_base = smem_to_u32(sm_dyn);
    uint32_t b_base = a_base + 24576;
    float* red  = (float*)(sm_dyn + 98304);
    float* redq = (float*)(sm_dyn + 102656);

    int tid = threadIdx.x, lane = tid & 31, wid = tid >> 5;
    int wm = wid >> 2, wn = wid & 3;
    int bm = blockIdx.x * 64;
    const int K = 192;

    {
        const __half* Ag = Aaos + (size_t)bm * K;
        #pragma unroll
        for (int i = 0; i < 6; i++) {
            int t = tid + i * 256, row = t / 24, c = t - row * 24;
            cp16(a_base + full_off(row, c), Ag + (size_t)row * K + c * 8);
        }
        #pragma unroll
        for (int i = 0; i < 18; i++) {
            int t = tid + i * 256, row = t / 24, c = t - row * 24;
            cp16(b_base + full_off(row, c), Wproj + (size_t)row * K + c * 8);
        }
    }
    cp_commit();
    cp_wait0();
    __syncthreads();

    // ---- proj mainloop ----
    float acc[2][6][4] = {};
    mainloop192(a_base, b_base, wm, wn, lane, acc);
    __syncthreads();

    // prefetch fc1 chunk 0 (overlaps epilogue)
    {
        #pragma unroll
        for (int i = 0; i < 18; i++) {
            int t = tid + i * 256, row = t / 24, c = t - row * 24;
            cp16(b_base + full_off(row, c), Wfc1 + (size_t)row * K + c * 8);
        }
        cp_commit();
    }

    // ---- proj epilogue: residual -> x2 (pixel), LN2 stats; cache pixel rows ----
    float2 bcol[6];
    #pragma unroll
    for (int nt = 0; nt < 6; nt++)
        bcol[nt] = *(const float2*)&pbias[wn * 48 + nt * 8 + 2 * (lane & 3)];
    int slot = wn * 4 + (lane & 3);
    int pixrow[2][2];

    #pragma unroll
    for (int mt = 0; mt < 2; mt++) {
        #pragma unroll
        for (int half = 0; half < 2; half++) {
            int rl = wm * 32 + mt * 16 + (lane >> 2) + half * 8;
            int row = bm + rl;
            int pr = pix_of_row(row);
            pixrow[mt][half] = pr;
            size_t pixbase = (size_t)pr * CC;
            float s = 0.f, sq2 = 0.f;
            #pragma unroll
            for (int nt = 0; nt < 6; nt++) {
                int col = wn * 48 + nt * 8 + 2 * (lane & 3);
                float2 sc = *(const float2*)&xsrc[pixbase + col];
                float vx = acc[mt][nt][half * 2] + bcol[nt].x + sc.x;
                float vy = acc[mt][nt][half * 2 + 1] + bcol[nt].y + sc.y;
                acc[mt][nt][half * 2] = vx;
                acc[mt][nt][half * 2 + 1] = vy;
                *(float2*)&x2out[pixbase + col] = make_float2(vx, vy);
                s += vx + vy;
                sq2 += vx * vx + vy * vy;
            }
            red [rl * 17 + slot] = s;
            redq[rl * 17 + slot] = sq2;
        }
    }
    __syncthreads();
    if (tid < 64) {
        float s = 0.f, qq = 0.f;
        #pragma unroll
        for (int i = 0; i < 16; i++) { s += red[tid * 17 + i]; qq += redq[tid * 17 + i]; }
        float mean = s * (1.f / 192.f);
        float var = qq * (1.f / 192.f) - mean * mean;
        red [tid * 17 + 16] = mean;
        redq[tid * 17 + 16] = rsqrtf(var + 1e-5f);
    }
    __syncthreads();

    // ---- LN2'd xs into a_base (smem only; windowed rows, fine for A-tile) ----
    #pragma unroll
    for (int mt = 0; mt < 2; mt++) {
        #pragma unroll
        for (int half = 0; half < 2; half++) {
            int rl = wm * 32 + mt * 16 + (lane >> 2) + half * 8;
            float mean = red [rl * 17 + 16];
            float rstd = redq[rl * 17 + 16];
            #pragma unroll
            for (int nt = 0; nt < 6; nt++) {
                int col = wn * 48 + nt * 8 + 2 * (lane & 3);
                float2 gv = *(const float2*)&g2[col];
                float2 bv = *(const float2*)&b2[col];
                float yx = (acc[mt][nt][half * 2] - mean) * rstd * gv.x + bv.x;
                float yy = (acc[mt][nt][half * 2 + 1] - mean) * rstd * gv.y + bv.y;
                uint32_t addr = a_base + full_off(rl, col >> 3) + (col & 7) * 2;
                asm volatile("st.shared.b32 [%0], %1;" :: "r"(addr), "r"(f22u(yx, yy)));
            }
        }
    }

    // ---- fc1: 4 N-chunks of 192; outputs at PIXEL rows ----
    for (int nc = 0; nc < 4; nc++) {
        cp_wait0();
        __syncthreads();

        float acc2[2][6][4] = {};
        mainloop192(a_base, b_base, wm, wn, lane, acc2);
        __syncthreads();

        if (nc < 3) {
            const __half* Bg = Wfc1 + (size_t)(nc + 1) * 192 * K;
            #pragma unroll
            for (int i = 0; i < 18; i++) {
                int t = tid + i * 256, row = t / 24, c = t - row * 24;
                cp16(b_base + full_off(row, c), Bg + (size_t)row * K + c * 8);
            }
            cp_commit();
        }

        float2 fb[6];
        #pragma unroll
        for (int nt = 0; nt < 6; nt++)
            fb[nt] = *(const float2*)&f1bias[nc * 192 + wn * 48 + nt * 8 + 2 * (lane & 3)];

        #pragma unroll
        for (int mt = 0; mt < 2; mt++) {
            #pragma unroll
            for (int half = 0; half < 2; half++) {
                size_t rb = (size_t)pixrow[mt][half] * HID + nc * 192;
                #pragma unroll
                for (int nt = 0; nt < 6; nt++) {
                    int col = wn * 48 + nt * 8 + 2 * (lane & 3);
                    float gx = gelu_exact(acc2[mt][nt][half * 2] + fb[nt].x);
                    float gy = gelu_exact(acc2[mt][nt][half * 2 + 1] + fb[nt].y);
                    *(__half2*)&hsout[rb + col] = __floats2half2_rn(gx, gy);
                }
            }
        }
    }
}

// ================= gemm_pipe64 (fc2: K=768, PIXEL rows): 3-stage BK=64 pipeline =================
#define SMEM_P64 98304
__global__ __launch_bounds__(256, 2)
void gemm_pipe64(const __half* __restrict__ A2, const __half* __restrict__ B2,
                 const float* __restrict__ bias, float* __restrict__ outF,
                 const float* __restrict__ addsrc) {
    extern __shared__ __align__(16) char sm_dyn[];
    uint32_t a_base = smem_to_u32(sm_dyn);
    uint32_t b_base = a_base + 24576;
    const int K = 768;

    int tid = threadIdx.x, lane = tid & 31, wid = tid >> 5;
    int wm = wid >> 2, wn = wid & 3;
    int bm = blockIdx.y * 64, bn = blockIdx.x * 192;
    const int NC = 12;

    float acc[2][6][4] = {};

    auto issue = [&](int buf, int cc) {
        const __half* Ag = A2 + (size_t)bm * K + cc * 64;
        const __half* Bg = B2 + (size_t)bn * K + cc * 64;
        uint32_t ab = a_base + buf * 8192;
        uint32_t bb = b_base + buf * 24576;
        #pragma unroll
        for (int i = 0; i < 2; i++) {
            int t = tid + i * 256, row = t >> 3, c = t & 7;
            cp16(t64_addr(ab, row, c), Ag + (size_t)row * K + c * 8);
        }
        #pragma unroll
        for (int i = 0; i < 6; i++) {
            int t = tid + i * 256, row = t >> 3, c = t & 7;
            cp16(t64_addr(bb, row, c), Bg + (size_t)row * K + c * 8);
        }
        cp_commit();
    };

    issue(0, 0);
    issue(1, 1);

    for (int cc = 0; cc < NC; cc++) {
        int buf = cc % 3;
        if (cc + 1 < NC) cp_wait1(); else cp_wait0();
        __syncthreads();
        if (cc + 2 < NC) issue((cc + 2) % 3, cc + 2);

        uint32_t ab = a_base + buf * 8192;
        uint32_t bb = b_base + buf * 24576;
        int arow = wm * 32 + (lane & 15);
        int bnrow = wn * 48 + (lane & 7) + ((lane >> 4) << 3);
        int bk8 = (lane >> 3) & 1;
        #pragma unroll
        for (int ks = 0; ks < 4; ks++) {
            uint32_t af[2][4];
            #pragma unroll
            for (int mt = 0; mt < 2; mt++)
                ldm4(af[mt][0], af[mt][1], af[mt][2], af[mt][3],
                     t64_addr(ab, arow + mt * 16, ks * 2 + (lane >> 4)));
            uint32_t bf[6][2];
            #pragma unroll
            for (int pr = 0; pr < 3; pr++)
                ldm4(bf[2 * pr][0], bf[2 * pr][1], bf[2 * pr + 1][0], bf[2 * pr + 1][1],
                     t64_addr(bb, bnrow + pr * 16, ks * 2 + bk8));
            #pragma unroll
            for (int mt = 0; mt < 2; mt++)
                #pragma unroll
                for (int nt = 0; nt < 6; nt++)
                    mma16816(acc[mt][nt][0], acc[mt][nt][1], acc[mt][nt][2], acc[mt][nt][3],
                             af[mt][0], af[mt][1], af[mt][2], af[mt][3],
                             bf[nt][0], bf[nt][1]);
        }
    }

    float2 bcol[6];
    #pragma unroll
    for (int nt = 0; nt < 6; nt++) {
        int col = bn + wn * 48 + nt * 8 + 2 * (lane & 3);
        bcol[nt] = *(const float2*)&bias[col];
    }
    #pragma unroll
    for (int mt = 0; mt < 2; mt++) {
        #pragma unroll
        for (int half = 0; half < 2; half++) {
            int row = bm + wm * 32 + mt * 16 + (lane >> 2) + half * 8;
            size_t rb = (size_t)row * 192;
            #pragma unroll
            for (int nt = 0; nt < 6; nt++) {
                int col = bn + wn * 48 + nt * 8 + 2 * (lane & 3);
                float2 s = *(const float2*)&addsrc[rb + col];
                float vx = acc[mt][nt][half * 2] + bcol[nt].x + s.x;
                float vy = acc[mt][nt][half * 2 + 1] + bcol[nt].y + s.y;
                *(float2*)&outF[rb + col] = make_float2(vx, vy);
            }
        }
    }
}

// ---------------- attention: 256 thr, 2 heads parallel, cp.async double-buffered ----------------
#define SMEM_ATTN 90112
__global__ __launch_bounds__(256) void attn_mma(__half* __restrict__ outs) {
    extern __shared__ __align__(16) char sm_dyn[];
    uint32_t smb = smem_to_u32(sm_dyn);
    int win = blockIdx.x;
    int wi = win & 255;
    int cls = (((wi >> 4) == 15) ? 2 : 0) + (((wi & 15) == 15) ? 1 : 0);
    int tid = threadIdx.x;
    int wg = tid >> 7;
    int t = tid & 127;
    int lane = t & 31, wmg = t >> 5;
    int g = lane >> 3, r8 = lane & 7;
    int mr = wmg * 16;

    uint4 z = make_uint4(0, 0, 0, 0);
    for (int i = tid; i < 3840; i += 256) ((uint4*)sm_dyn)[i] = z;
    __syncthreads();

    auto load_pair = [&](int buf, int h2) {
        int h = h2 * 2 + wg;
        uint32_t qb = smb + (buf * 2 + wg) * 15360;
        const uint4* qg = (const uint4*)(g_q + (size_t)(win * NHEADS + h) * (NTOK * DHEAD));
        const uint4* kg = (const uint4*)(g_k + (size_t)(win * NHEADS + h) * (NTOK * DHEAD));
        const uint4* vg = (const uint4*)(g_v + (size_t)(win * NHEADS + h) * (NTOK * DHEAD));
        for (int i = t; i < 196; i += 128) {
            int r = i >> 2, c = i & 3;
            uint32_t off = r * 80 + c * 16;
            cp16(qb + off, qg + i);
            cp16(qb + 5120 + off, kg + i);
            cp16(qb + 10240 + off, vg + i);
        }
        uint32_t cb = smb + 61440 + (buf * 2 + wg) * 7168;
        const uint4* cg = (const uint4*)(g_cmb + (size_t)(cls * NHEADS + h) * (64 * 56));
        for (int i = t; i < 448; i += 128) cp16(cb + i * 16, cg + i);
        cp_commit();
    };

    load_pair(0, 0);

    int buf = 0;
    for (int h2 = 0; h2 < 3; h2++) {
        int h = h2 * 2 + wg;
        if (h2 < 2) load_pair(buf ^ 1, h2 + 1);
        if (h2 < 2) cp_wait1(); else cp_wait0();
        __syncthreads();

        uint32_t qbase = smb + (buf * 2 + wg) * 15360;
        uint32_t kbase = qbase + 5120, vbase = qbase + 10240;
        uint32_t cbase = smb + 61440 + (buf * 2 + wg) * 7168;

        uint32_t qf[2][4];
        #pragma unroll
        for (int ks = 0; ks < 2; ks++) {
            int row = mr + (g & 1) * 8 + r8;
            int col = ks * 16 + (g >> 1) * 8;
            ldm4(qf[ks][0], qf[ks][1], qf[ks][2], qf[ks][3], qbase + row * 80 + col * 2);
        }

        float sacc[7][4] = {};
        #pragma unroll
        for (int ks = 0; ks < 2; ks++) {
            #pragma unroll
            for (int np = 0; np < 4; np++) {
                int row = np * 16 + ((g >> 1) & 1) * 8 + r8;
                int col = ks * 16 + (g & 1) * 8;
                uint32_t b0, b1, b2, b3;
                ldm4(b0, b1, b2, b3, kbase + row * 80 + col * 2);
                mma16816(sacc[2 * np][0], sacc[2 * np][1], sacc[2 * np][2], sacc[2 * np][3],
                         qf[ks][0], qf[ks][1], qf[ks][2], qf[ks][3], b0, b1);
                if (np < 3)
                    mma16816(sacc[2 * np + 1][0], sacc[2 * np + 1][1], sacc[2 * np + 1][2], sacc[2 * np + 1][3],
                             qf[ks][0], qf[ks][1], qf[ks][2], qf[ks][3], b2, b3);
            }
        }

        #pragma unroll
        for (int np = 0; np < 4; np++) {
            int row = mr + (g & 1) * 8 + r8;
            int colc = 2 * np + ((g >> 1) & 1); if (colc > 6) colc = 6;
            uint32_t c0, c1, c2, c3;
            ldm4(c0, c1, c2, c3, cbase + row * 112 + colc * 8 * 2);
            float2 f;
            f = __half22float2(*(__half2*)&c0); sacc[2 * np][0] += f.x; sacc[2 * np][1] += f.y;
            f = __half22float2(*(__half2*)&c1); sacc[2 * np][2] += f.x; sacc[2 * np][3] += f.y;
            if (np < 3) {
                f = __half22float2(*(__half2*)&c2); sacc[2 * np + 1][0] += f.x; sacc[2 * np + 1][1] += f.y;
                f = __half22float2(*(__half2*)&c3); sacc[2 * np + 1][2] += f.x; sacc[2 * np + 1][3] += f.y;
            }
        }

        float mx0 = -1e30f, mx8 = -1e30f;
        #pragma unroll
        for (int nt = 0; nt < 7; nt++) {
            mx0 = fmaxf(mx0, fmaxf(sacc[nt][0], sacc[nt][1]));
            mx8 = fmaxf(mx8, fmaxf(sacc[nt][2], sacc[nt][3]));
        }
        #pragma unroll
        for (int o = 1; o <= 2; o <<= 1) {
            mx0 = fmaxf(mx0, __shfl_xor_sync(0xffffffffu, mx0, o));
            mx8 = fmaxf(mx8, __shfl_xor_sync(0xffffffffu, mx8, o));
        }
        float s0 = 0.f, s8 = 0.f;
        #pragma unroll
        for (int nt = 0; nt < 7; nt++) {
            sacc[nt][0] = __expf(sacc[nt][0] - mx0); s0 += sacc[nt][0];
            sacc[nt][1] = __expf(sacc[nt][1] - mx0); s0 += sacc[nt][1];
            sacc[nt][2] = __expf(sacc[nt][2] - mx8); s8 += sacc[nt][2];
            sacc[nt][3] = __expf(sacc[nt][3] - mx8); s8 += sacc[nt][3];
        }
        #pragma unroll
        for (int o = 1; o <= 2; o <<= 1) {
            s0 += __shfl_xor_sync(0xffffffffu, s0, o);
            s8 += __shfl_xor_sync(0xffffffffu, s8, o);
        }
        float inv0 = 1.f / s0, inv8 = 1.f / s8;
        #pragma unroll
        for (int nt = 0; nt < 7; nt++) {
            sacc[nt][0] *= inv0; sacc[nt][1] *= inv0;
            sacc[nt][2] *= inv8; sacc[nt][3] *= inv8;
        }

        float oacc[4][4] = {};
        #pragma unroll
        for (int kt = 0; kt < 4; kt++) {
            uint32_t a0 = f22u(sacc[2 * kt][0], sacc[2 * kt][1]);
            uint32_t a1 = f22u(sacc[2 * kt][2], sacc[2 * kt][3]);
            uint32_t a2 = 0, a3 = 0;
            if (kt < 3) {
                a2 = f22u(sacc[2 * kt + 1][0], sacc[2 * kt + 1][1]);
                a3 = f22u(sacc[2 * kt + 1][2], sacc[2 * kt + 1][3]);
            }
            #pragma unroll
            for (int dp = 0; dp < 2; dp++) {
                int row = kt * 16 + (g & 1) * 8 + r8;
                int col = dp * 16 + ((g >> 1) & 1) * 8;
                uint32_t b0, b1, b2, b3;
                ldm4t(b0, b1, b2, b3, vbase + row * 80 + col * 2);
                mma16816(oacc[2 * dp][0], oacc[2 * dp][1], oacc[2 * dp][2], oacc[2 * dp][3],
                         a0, a1, a2, a3, b0, b1);
                mma16816(oacc[2 * dp + 1][0], oacc[2 * dp + 1][1], oacc[2 * dp + 1][2], oacc[2 * dp + 1][3],
                         a0, a1, a2, a3, b2, b3);
            }
        }

        int r0 = mr + (lane >> 2);
        int cbase2 = h * DHEAD + 2 * (lane & 3);
        if (r0 < NTOK) {
            size_t ob = ((size_t)win * NTOK + r0) * CC + cbase2;
            #pragma unroll
            for (int dn = 0; dn < 4; dn++)
                *(__half2*)&outs[ob + dn * 8] = __floats2half2_rn(oacc[dn][0], oacc[dn][1]);
        }
        int r1 = r0 + 8;
        if (r1 < NTOK) {
            size_t ob = ((size_t)win * NTOK + r1) * CC + cbase2;
            #pragma unroll
            for (int dn = 0; dn < 4; dn++)
                *(__half2*)&outs[ob + dn * 8] = __floats2half2_rn(oacc[dn][2], oacc[dn][3]);
        }
        __syncthreads();
        buf ^= 1;
    }
}

// ---------------- launch ----------------
extern "C" void kernel_launch(void* const* d_in, const int* in_sizes, int n_in,
                              void* d_out, int out_size) {
    const float* x      = (const float*)d_in[0];
    const float* amask  = (const float*)d_in[1];
    const float* n1g    = (const float*)d_in[2];
    const float* n1b    = (const float*)d_in[3];
    const float* qkv_w  = (const float*)d_in[4];
    const float* qkv_b  = (const float*)d_in[5];
    const float* rpb    = (const float*)d_in[6];
    const float* proj_w = (const float*)d_in[7];
    const float* proj_b = (const float*)d_in[8];
    const float* n2g    = (const float*)d_in[9];
    const float* n2b    = (const float*)d_in[10];
    const float* fc1_w  = (const float*)d_in[11];
    const float* fc1_b  = (const float*)d_in[12];
    const float* fc2_w  = (const float*)d_in[13];
    const float* fc2_b  = (const float*)d_in[14];
    float* out = (float*)d_out;

    __half *xs, *aos, *hs, *wqkv, *wproj, *wfc1, *wfc2;
    float *x2;
    cudaGetSymbolAddress((void**)&xs,    g_xs);
    cudaGetSymbolAddress((void**)&aos,   g_aos);
    cudaGetSymbolAddress((void**)&hs,    g_hs);
    cudaGetSymbolAddress((void**)&x2,    g_x2);
    cudaGetSymbolAddress((void**)&wqkv,  g_wqkv);
    cudaGetSymbolAddress((void**)&wproj, g_wproj);
    cudaGetSymbolAddress((void**)&wfc1,  g_wfc1);
    cudaGetSymbolAddress((void**)&wfc2,  g_wfc2);

    cudaFuncSetAttribute(gemm_qkv,    cudaFuncAttributeMaxDynamicSharedMemorySize, SMEM_QKV);
    cudaFuncSetAttribute(gemm_mlp,    cudaFuncAttributeMaxDynamicSharedMemorySize, SMEM_MLP);
    cudaFuncSetAttribute(gemm_pipe64, cudaFuncAttributeMaxDynamicSharedMemorySize, SMEM_P64);
    cudaFuncSetAttribute(attn_mma,    cudaFuncAttributeMaxDynamicSharedMemorySize, SMEM_ATTN);

    const int MB = MROWS / 64;  // 3136

    prep_all<<<1728, 256>>>(qkv_w, proj_w, fc1_w, fc2_w);
    prep_cmb<<<24, 256>>>(amask, rpb);
    // 1) LN1 + shift + window partition -> fp16
    ln1_kernel<<<MROWS / 8, 256>>>(x, n1g, n1b, xs);
    // 2) QKV GEMM (A resident, 3 weight chunks streamed)
    gemm_qkv<<<MB, 256, SMEM_QKV>>>(xs, wqkv, qkv_b);
    // 3) attention
    attn_mma<<<NWIN, 256, SMEM_ATTN>>>(aos);
    // 4) proj + shortcut -> x2 (pixel), LN2 (smem), fc1 + gelu -> hs (pixel rows)
    gemm_mlp<<<MB, 256, SMEM_MLP>>>(aos, wproj, proj_b, x2, x, n2g, n2b, wfc1, fc1_b, hs);
    // 5) fc2 + residual -> out (pixel rows)
    gemm_pipe64<<<dim3(1, MB), 256, SMEM_P64>>>(hs, wfc2, fc2_b, out, x2);
}

// round 14
// speedup vs baseline: 1.1206x; 1.0131x over previous
#include <cuda_runtime.h>
#include <cuda_fp16.h>
#include <math.h>
#include <stdint.h>

// ---------------- problem constants ----------------
#define BATCH   16
#define IMG     112
#define CC      192
#define NHEADS  6
#define DHEAD   32
#define WSZ     7
#define NTOK    49
#define NWIN    4096
#define MROWS   200704
#define HID     768

// ---------------- device scratch ----------------
__device__ __half g_xs [(size_t)MROWS * CC];     // LN1 output (windowed)
__device__ __half g_aos[(size_t)MROWS * CC];
__device__ __half g_hs [(size_t)MROWS * HID];    // gelu(fc1), PIXEL order
__device__ __half g_q[(size_t)NWIN * NHEADS * NTOK * DHEAD];
__device__ __half g_k[(size_t)NWIN * NHEADS * NTOK * DHEAD];
__device__ __half g_v[(size_t)NWIN * NHEADS * NTOK * DHEAD];
__device__ float g_x2[(size_t)MROWS * CC];       // PIXEL order
__device__ __half g_wqkv [(size_t)576 * 192];
__device__ __half g_wproj[(size_t)192 * 192];
__device__ __half g_wfc1 [(size_t)768 * 192];
__device__ __half g_wfc2 [(size_t)192 * 768];
__device__ __half g_cmb[(size_t)4 * NHEADS * 64 * 56];

// ---------------- helpers ----------------
__device__ __forceinline__ uint32_t smem_to_u32(const void* p) {
    uint32_t a;
    asm("{ .reg .u64 t; cvta.to.shared.u64 t, %1; cvt.u32.u64 %0, t; }" : "=r"(a) : "l"(p));
    return a;
}
__device__ __forceinline__ void cp16(uint32_t sm, const void* gp) {
    asm volatile("cp.async.cg.shared.global [%0], [%1], 16;" :: "r"(sm), "l"(gp));
}
__device__ __forceinline__ void cp_commit() { asm volatile("cp.async.commit_group;"); }
__device__ __forceinline__ void cp_wait1()  { asm volatile("cp.async.wait_group 1;"); }
__device__ __forceinline__ void cp_wait0()  { asm volatile("cp.async.wait_group 0;"); }

__device__ __forceinline__ void ldm4(uint32_t& x0, uint32_t& x1, uint32_t& x2, uint32_t& x3, uint32_t addr) {
    asm volatile("ldmatrix.sync.aligned.m8n8.x4.shared.b16 {%0,%1,%2,%3}, [%4];"
                 : "=r"(x0), "=r"(x1), "=r"(x2), "=r"(x3) : "r"(addr));
}
__device__ __forceinline__ void ldm4t(uint32_t& x0, uint32_t& x1, uint32_t& x2, uint32_t& x3, uint32_t addr) {
    asm volatile("ldmatrix.sync.aligned.m8n8.x4.trans.shared.b16 {%0,%1,%2,%3}, [%4];"
                 : "=r"(x0), "=r"(x1), "=r"(x2), "=r"(x3) : "r"(addr));
}
__device__ __forceinline__ void mma16816(float& d0, float& d1, float& d2, float& d3,
                                         uint32_t a0, uint32_t a1, uint32_t a2, uint32_t a3,
                                         uint32_t b0, uint32_t b1) {
    asm volatile("mma.sync.aligned.m16n8k16.row.col.f32.f16.f16.f32 "
                 "{%0,%1,%2,%3},{%4,%5,%6,%7},{%8,%9},{%0,%1,%2,%3};"
                 : "+f"(d0), "+f"(d1), "+f"(d2), "+f"(d3)
                 : "r"(a0), "r"(a1), "r"(a2), "r"(a3), "r"(b0), "r"(b1));
}
__device__ __forceinline__ uint32_t f22u(float a, float b) {
    __half2 h = __floats2half2_rn(a, b);
    return *(uint32_t*)&h;
}
// full-K tile: rows of 192 halves (384B, 24 x 16B chunks)
__device__ __forceinline__ uint32_t full_off(int row, int c) {
    return (uint32_t)(row * 384 + (((c & 24) | ((c ^ row) & 7)) << 4));
}
// 64-half tile: rows of 128B, 8 x 16B chunks
__device__ __forceinline__ uint32_t t64_addr(uint32_t base, int row, int c) {
    return base + row * 128 + (((c ^ row) & 7) << 4);
}
__device__ __forceinline__ float gelu_exact(float x) {
    return 0.5f * x * (1.f + erff(x * 0.70710678118654752f));
}
// windowed row -> pixel row
__device__ __forceinline__ int pix_of_row(int row) {
    int win = row / NTOK, n = row - win * NTOK;
    int b = win >> 8, wi = win & 255;
    int hh = (wi >> 4) * WSZ + n / WSZ;
    int ww = (wi & 15) * WSZ + n % WSZ;
    int p = hh + 3; if (p >= IMG) p -= IMG;
    int q = ww + 3; if (q >= IMG) q -= IMG;
    return (b * IMG + p) * IMG + q;
}

// ---------------- merged weight prep ----------------
__global__ void prep_all(const float* __restrict__ qkv_w, const float* __restrict__ proj_w,
                         const float* __restrict__ fc1_w, const float* __restrict__ fc2_w) {
    int i = blockIdx.x * 256 + threadIdx.x;
    const float* W; __half* D; int K, N, off;
    if (i < 110592)      { W = qkv_w;  D = g_wqkv;  K = 192; N = 576; off = i; }
    else if (i < 147456) { W = proj_w; D = g_wproj; K = 192; N = 192; off = i - 110592; }
    else if (i < 294912) { W = fc1_w;  D = g_wfc1;  K = 192; N = 768; off = i - 147456; }
    else if (i < 442368) { W = fc2_w;  D = g_wfc2;  K = 768; N = 192; off = i - 294912; }
    else return;
    int k = off / N, n = off - k * N;
    D[(size_t)n * K + k] = __float2half(W[off]);
}

// ---------------- bias+mask table prep ----------------
__global__ void prep_cmb(const float* __restrict__ amask, const float* __restrict__ rpb) {
    int ch = blockIdx.x;
    int cls = ch / NHEADS, head = ch - cls * NHEADS;
    int wi_rep = (cls >> 1 ? 240 : 0) + ((cls & 1) ? 15 : 0);
    __half* dst = g_cmb + (size_t)ch * (64 * 56);
    for (int idx = threadIdx.x; idx < 64 * 56; idx += 256) {
        int r = idx / 56, c = idx - r * 56;
        float v;
        if (r < NTOK && c < NTOK) {
            int i1 = r / WSZ, j1 = r - i1 * WSZ;
            int i2 = c / WSZ, j2 = c - i2 * WSZ;
            int rel = (i1 - i2 + 6) * 13 + (j1 - j2 + 6);
            v = rpb[rel * NHEADS + head] + amask[((size_t)wi_rep * NTOK + r) * NTOK + c];
        } else {
            v = -100.f;
        }
        dst[idx] = __float2half(v);
    }
}

// ---------------- LN1 (fused shift + window partition) ----------------
__global__ __launch_bounds__(256) void ln1_kernel(const float* __restrict__ src_full,
                                                  const float* __restrict__ gam,
                                                  const float* __restrict__ bet,
                                                  __half* __restrict__ out) {
    int t = blockIdx.x * 8 + (threadIdx.x >> 5);
    int lane = threadIdx.x & 31;
    int win = t / NTOK, n = t - win * NTOK;
    int b = win >> 8, wi = win & 255;
    int hh = (wi >> 4) * WSZ + n / WSZ;
    int ww = (wi & 15) * WSZ + n % WSZ;
    int sh = hh + 3; if (sh >= IMG) sh -= IMG;
    int sw = ww + 3; if (sw >= IMG) sw -= IMG;
    const float* src = src_full + (size_t)((b * IMG + sh) * IMG + sw) * CC;

    float v[6]; float s = 0.f, s2 = 0.f;
    #pragma unroll
    for (int i = 0; i < 6; i++) { float a = src[i * 32 + lane]; v[i] = a; s += a; s2 += a * a; }
    #pragma unroll
    for (int o = 16; o; o >>= 1) {
        s  += __shfl_xor_sync(0xffffffffu, s,  o);
        s2 += __shfl_xor_sync(0xffffffffu, s2, o);
    }
    float mean = s * (1.f / 192.f);
    float var  = s2 * (1.f / 192.f) - mean * mean;
    float rstd = rsqrtf(var + 1e-5f);
    __half* dst = out + (size_t)t * CC;
    #pragma unroll
    for (int i = 0; i < 6; i++) {
        int c = i * 32 + lane;
        dst[c] = __float2half((v[i] - mean) * rstd * gam[c] + bet[c]);
    }
}

// ---- shared mainloop: 12 k-steps over resident A/B full-K tiles ----
__device__ __forceinline__ void mainloop192(uint32_t a_base, uint32_t b_base,
                                            int wm, int wn, int lane,
                                            float acc[2][6][4]) {
    int arow = wm * 32 + (lane & 15);
    int bnrow = wn * 48 + (lane & 7) + ((lane >> 4) << 3);
    int bk8 = (lane >> 3) & 1;
    #pragma unroll
    for (int ks = 0; ks < 12; ks++) {
        uint32_t af[2][4];
        #pragma unroll
        for (int mt = 0; mt < 2; mt++)
            ldm4(af[mt][0], af[mt][1], af[mt][2], af[mt][3],
                 a_base + full_off(arow + mt * 16, ks * 2 + (lane >> 4)));
        uint32_t bf[6][2];
        #pragma unroll
        for (int pr = 0; pr < 3; pr++)
            ldm4(bf[2 * pr][0], bf[2 * pr][1], bf[2 * pr + 1][0], bf[2 * pr + 1][1],
                 b_base + full_off(bnrow + pr * 16, ks * 2 + bk8));
        #pragma unroll
        for (int mt = 0; mt < 2; mt++)
            #pragma unroll
            for (int nt = 0; nt < 6; nt++)
                mma16816(acc[mt][nt][0], acc[mt][nt][1], acc[mt][nt][2], acc[mt][nt][3],
                         af[mt][0], af[mt][1], af[mt][2], af[mt][3],
                         bf[nt][0], bf[nt][1]);
    }
}

// ================= gemm_qkv: one N-block per CTA (R11 style; best measured) =================
// grid (3, MB): blockIdx.x = qkv chunk, blockIdx.y = M block.
#define SMEM_QKV 98304
__global__ __launch_bounds__(256, 2)
void gemm_qkv(const __half* __restrict__ A2, const __half* __restrict__ B2,
              const float* __restrict__ bias) {
    extern __shared__ __align__(16) char sm_dyn[];
    uint32_t a_base = smem_to_u32(sm_dyn);
    uint32_t b_base = a_base + 24576;

    int tid = threadIdx.x, lane = tid & 31, wid = tid >> 5;
    int wm = wid >> 2, wn = wid & 3;
    int bm = blockIdx.y * 64;
    int nc = blockIdx.x;
    const int K = 192;

    {
        const __half* Ag = A2 + (size_t)bm * K;
        #pragma unroll
        for (int i = 0; i < 6; i++) {
            int t = tid + i * 256, row = t / 24, c = t - row * 24;
            cp16(a_base + full_off(row, c), Ag + (size_t)row * K + c * 8);
        }
        const __half* Bg = B2 + (size_t)nc * 192 * K;
        #pragma unroll
        for (int i = 0; i < 18; i++) {
            int t = tid + i * 256, row = t / 24, c = t - row * 24;
            cp16(b_base + full_off(row, c), Bg + (size_t)row * K + c * 8);
        }
    }
    cp_commit();
    cp_wait0();
    __syncthreads();

    float acc[2][6][4] = {};
    mainloop192(a_base, b_base, wm, wn, lane, acc);

    float scale = (nc == 0) ? 0.17677669529663687f : 1.f;
    __half* dst = (nc == 0) ? g_q : ((nc == 1) ? g_k : g_v);
    float2 bcol[6];
    #pragma unroll
    for (int nt = 0; nt < 6; nt++)
        bcol[nt] = *(const float2*)&bias[nc * 192 + wn * 48 + nt * 8 + 2 * (lane & 3)];

    #pragma unroll
    for (int mt = 0; mt < 2; mt++) {
        #pragma unroll
        for (int half = 0; half < 2; half++) {
            int row = bm + wm * 32 + mt * 16 + (lane >> 2) + half * 8;
            int win = row / NTOK, n = row - win * NTOK;
            #pragma unroll
            for (int nt = 0; nt < 6; nt++) {
                int col = wn * 48 + nt * 8 + 2 * (lane & 3);
                int head = col >> 5, dd = col & 31;
                float vx = (acc[mt][nt][half * 2] + bcol[nt].x) * scale;
                float vy = (acc[mt][nt][half * 2 + 1] + bcol[nt].y) * scale;
                *(__half2*)&dst[(((size_t)win * NHEADS + head) * NTOK + n) * DHEAD + dd] =
                    __floats2half2_rn(vx, vy);
            }
        }
    }
}

// ================= gemm_mlp: proj + residual -> x2, LN2 -> smem, fc1+gelu -> hs (PIXEL rows) ====
#define SMEM_MLP 107008
__global__ __launch_bounds__(256, 2)
void gemm_mlp(const __half* __restrict__ Aaos, const __half* __restrict__ Wproj,
              const float* __restrict__ pbias, float* __restrict__ x2out,
              const float* __restrict__ xsrc,
              const float* __restrict__ g2, const float* __restrict__ b2,
              const __half* __restrict__ Wfc1, const float* __restrict__ f1bias,
              __half* __restrict__ hsout) {
    extern __shared__ __align__(16) char sm_dyn[];
    uint32_t a_base = smem_to_u32(sm_dyn);
    uint32_t b_base = a_base + 24576;
    float* red  = (float*)(sm_dyn + 98304);
    float* redq = (float*)(sm_dyn + 102656);

    int tid = threadIdx.x, lane = tid & 31, wid = tid >> 5;
    int wm = wid >> 2, wn = wid & 3;
    int bm = blockIdx.x * 64;
    const int K = 192;

    {
        const __half* Ag = Aaos + (size_t)bm * K;
        #pragma unroll
        for (int i = 0; i < 6; i++) {
            int t = tid + i * 256, row = t / 24, c = t - row * 24;
            cp16(a_base + full_off(row, c), Ag + (size_t)row * K + c * 8);
        }
        #pragma unroll
        for (int i = 0; i < 18; i++) {
            int t = tid + i * 256, row = t / 24, c = t - row * 24;
            cp16(b_base + full_off(row, c), Wproj + (size_t)row * K + c * 8);
        }
    }
    cp_commit();
    cp_wait0();
    __syncthreads();

    // ---- proj mainloop ----
    float acc[2][6][4] = {};
    mainloop192(a_base, b_base, wm, wn, lane, acc);
    __syncthreads();

    // prefetch fc1 chunk 0 (overlaps epilogue)
    {
        #pragma unroll
        for (int i = 0; i < 18; i++) {
            int t = tid + i * 256, row = t / 24, c = t - row * 24;
            cp16(b_base + full_off(row, c), Wfc1 + (size_t)row * K + c * 8);
        }
        cp_commit();
    }

    // ---- proj epilogue: residual -> x2 (pixel), LN2 stats; cache pixel rows ----
    float2 bcol[6];
    #pragma unroll
    for (int nt = 0; nt < 6; nt++)
        bcol[nt] = *(const float2*)&pbias[wn * 48 + nt * 8 + 2 * (lane & 3)];
    int slot = wn * 4 + (lane & 3);
    int pixrow[2][2];

    #pragma unroll
    for (int mt = 0; mt < 2; mt++) {
        #pragma unroll
        for (int half = 0; half < 2; half++) {
            int rl = wm * 32 + mt * 16 + (lane >> 2) + half * 8;
            int row = bm + rl;
            int pr = pix_of_row(row);
            pixrow[mt][half] = pr;
            size_t pixbase = (size_t)pr * CC;
            float s = 0.f, sq2 = 0.f;
            #pragma unroll
            for (int nt = 0; nt < 6; nt++) {
                int col = wn * 48 + nt * 8 + 2 * (lane & 3);
                float2 sc = *(const float2*)&xsrc[pixbase + col];
                float vx = acc[mt][nt][half * 2] + bcol[nt].x + sc.x;
                float vy = acc[mt][nt][half * 2 + 1] + bcol[nt].y + sc.y;
                acc[mt][nt][half * 2] = vx;
                acc[mt][nt][half * 2 + 1] = vy;
                *(float2*)&x2out[pixbase + col] = make_float2(vx, vy);
                s += vx + vy;
                sq2 += vx * vx + vy * vy;
            }
            red [rl * 17 + slot] = s;
            redq[rl * 17 + slot] = sq2;
        }
    }
    __syncthreads();
    if (tid < 64) {
        float s = 0.f, qq = 0.f;
        #pragma unroll
        for (int i = 0; i < 16; i++) { s += red[tid * 17 + i]; qq += redq[tid * 17 + i]; }
        float mean = s * (1.f / 192.f);
        float var = qq * (1.f / 192.f) - mean * mean;
        red [tid * 17 + 16] = mean;
        redq[tid * 17 + 16] = rsqrtf(var + 1e-5f);
    }
    __syncthreads();

    // ---- LN2'd xs into a_base (smem only) ----
    #pragma unroll
    for (int mt = 0; mt < 2; mt++) {
        #pragma unroll
        for (int half = 0; half < 2; half++) {
            int rl = wm * 32 + mt * 16 + (lane >> 2) + half * 8;
            float mean = red [rl * 17 + 16];
            float rstd = redq[rl * 17 + 16];
            #pragma unroll
            for (int nt = 0; nt < 6; nt++) {
                int col = wn * 48 + nt * 8 + 2 * (lane & 3);
                float2 gv = *(const float2*)&g2[col];
                float2 bv = *(const float2*)&b2[col];
                float yx = (acc[mt][nt][half * 2] - mean) * rstd * gv.x + bv.x;
                float yy = (acc[mt][nt][half * 2 + 1] - mean) * rstd * gv.y + bv.y;
                uint32_t addr = a_base + full_off(rl, col >> 3) + (col & 7) * 2;
                asm volatile("st.shared.b32 [%0], %1;" :: "r"(addr), "r"(f22u(yx, yy)));
            }
        }
    }

    // ---- fc1: 4 N-chunks of 192; outputs at PIXEL rows ----
    for (int nc = 0; nc < 4; nc++) {
        cp_wait0();
        __syncthreads();

        float acc2[2][6][4] = {};
        mainloop192(a_base, b_base, wm, wn, lane, acc2);
        __syncthreads();

        if (nc < 3) {
            const __half* Bg = Wfc1 + (size_t)(nc + 1) * 192 * K;
            #pragma unroll
            for (int i = 0; i < 18; i++) {
                int t = tid + i * 256, row = t / 24, c = t - row * 24;
                cp16(b_base + full_off(row, c), Bg + (size_t)row * K + c * 8);
            }
            cp_commit();
        }

        float2 fb[6];
        #pragma unroll
        for (int nt = 0; nt < 6; nt++)
            fb[nt] = *(const float2*)&f1bias[nc * 192 + wn * 48 + nt * 8 + 2 * (lane & 3)];

        #pragma unroll
        for (int mt = 0; mt < 2; mt++) {
            #pragma unroll
            for (int half = 0; half < 2; half++) {
                size_t rb = (size_t)pixrow[mt][half] * HID + nc * 192;
                #pragma unroll
                for (int nt = 0; nt < 6; nt++) {
                    int col = wn * 48 + nt * 8 + 2 * (lane & 3);
                    float gx = gelu_exact(acc2[mt][nt][half * 2] + fb[nt].x);
                    float gy = gelu_exact(acc2[mt][nt][half * 2 + 1] + fb[nt].y);
                    *(__half2*)&hsout[rb + col] = __floats2half2_rn(gx, gy);
                }
            }
        }
    }
}

// ================= gemm_pipe64 (fc2: K=768, PIXEL rows): 3-stage BK=64 pipeline =================
#define SMEM_P64 98304
__global__ __launch_bounds__(256, 2)
void gemm_pipe64(const __half* __restrict__ A2, const __half* __restrict__ B2,
                 const float* __restrict__ bias, float* __restrict__ outF,
                 const float* __restrict__ addsrc) {
    extern __shared__ __align__(16) char sm_dyn[];
    uint32_t a_base = smem_to_u32(sm_dyn);
    uint32_t b_base = a_base + 24576;
    const int K = 768;

    int tid = threadIdx.x, lane = tid & 31, wid = tid >> 5;
    int wm = wid >> 2, wn = wid & 3;
    int bm = blockIdx.y * 64, bn = blockIdx.x * 192;
    const int NC = 12;

    float acc[2][6][4] = {};

    auto issue = [&](int buf, int cc) {
        const __half* Ag = A2 + (size_t)bm * K + cc * 64;
        const __half* Bg = B2 + (size_t)bn * K + cc * 64;
        uint32_t ab = a_base + buf * 8192;
        uint32_t bb = b_base + buf * 24576;
        #pragma unroll
        for (int i = 0; i < 2; i++) {
            int t = tid + i * 256, row = t >> 3, c = t & 7;
            cp16(t64_addr(ab, row, c), Ag + (size_t)row * K + c * 8);
        }
        #pragma unroll
        for (int i = 0; i < 6; i++) {
            int t = tid + i * 256, row = t >> 3, c = t & 7;
            cp16(t64_addr(bb, row, c), Bg + (size_t)row * K + c * 8);
        }
        cp_commit();
    };

    issue(0, 0);
    issue(1, 1);

    for (int cc = 0; cc < NC; cc++) {
        int buf = cc % 3;
        if (cc + 1 < NC) cp_wait1(); else cp_wait0();
        __syncthreads();
        if (cc + 2 < NC) issue((cc + 2) % 3, cc + 2);

        uint32_t ab = a_base + buf * 8192;
        uint32_t bb = b_base + buf * 24576;
        int arow = wm * 32 + (lane & 15);
        int bnrow = wn * 48 + (lane & 7) + ((lane >> 4) << 3);
        int bk8 = (lane >> 3) & 1;
        #pragma unroll
        for (int ks = 0; ks < 4; ks++) {
            uint32_t af[2][4];
            #pragma unroll
            for (int mt = 0; mt < 2; mt++)
                ldm4(af[mt][0], af[mt][1], af[mt][2], af[mt][3],
                     t64_addr(ab, arow + mt * 16, ks * 2 + (lane >> 4)));
            uint32_t bf[6][2];
            #pragma unroll
            for (int pr = 0; pr < 3; pr++)
                ldm4(bf[2 * pr][0], bf[2 * pr][1], bf[2 * pr + 1][0], bf[2 * pr + 1][1],
                     t64_addr(bb, bnrow + pr * 16, ks * 2 + bk8));
            #pragma unroll
            for (int mt = 0; mt < 2; mt++)
                #pragma unroll
                for (int nt = 0; nt < 6; nt++)
                    mma16816(acc[mt][nt][0], acc[mt][nt][1], acc[mt][nt][2], acc[mt][nt][3],
                             af[mt][0], af[mt][1], af[mt][2], af[mt][3],
                             bf[nt][0], bf[nt][1]);
        }
    }

    float2 bcol[6];
    #pragma unroll
    for (int nt = 0; nt < 6; nt++) {
        int col = bn + wn * 48 + nt * 8 + 2 * (lane & 3);
        bcol[nt] = *(const float2*)&bias[col];
    }
    #pragma unroll
    for (int mt = 0; mt < 2; mt++) {
        #pragma unroll
        for (int half = 0; half < 2; half++) {
            int row = bm + wm * 32 + mt * 16 + (lane >> 2) + half * 8;
            size_t rb = (size_t)row * 192;
            #pragma unroll
            for (int nt = 0; nt < 6; nt++) {
                int col = bn + wn * 48 + nt * 8 + 2 * (lane & 3);
                float2 s = *(const float2*)&addsrc[rb + col];
                float vx = acc[mt][nt][half * 2] + bcol[nt].x + s.x;
                float vy = acc[mt][nt][half * 2 + 1] + bcol[nt].y + s.y;
                *(float2*)&outF[rb + col] = make_float2(vx, vy);
            }
        }
    }
}

// ---------------- attention: 256 thr, 2 heads parallel, cp.async double-buffered ----------------
#define SMEM_ATTN 90112
__global__ __launch_bounds__(256) void attn_mma(__half* __restrict__ outs) {
    extern __shared__ __align__(16) char sm_dyn[];
    uint32_t smb = smem_to_u32(sm_dyn);
    int win = blockIdx.x;
    int wi = win & 255;
    int cls = (((wi >> 4) == 15) ? 2 : 0) + (((wi & 15) == 15) ? 1 : 0);
    int tid = threadIdx.x;
    int wg = tid >> 7;
    int t = tid & 127;
    int lane = t & 31, wmg = t >> 5;
    int g = lane >> 3, r8 = lane & 7;
    int mr = wmg * 16;

    uint4 z = make_uint4(0, 0, 0, 0);
    for (int i = tid; i < 3840; i += 256) ((uint4*)sm_dyn)[i] = z;
    __syncthreads();

    auto load_pair = [&](int buf, int h2) {
        int h = h2 * 2 + wg;
        uint32_t qb = smb + (buf * 2 + wg) * 15360;
        const uint4* qg = (const uint4*)(g_q + (size_t)(win * NHEADS + h) * (NTOK * DHEAD));
        const uint4* kg = (const uint4*)(g_k + (size_t)(win * NHEADS + h) * (NTOK * DHEAD));
        const uint4* vg = (const uint4*)(g_v + (size_t)(win * NHEADS + h) * (NTOK * DHEAD));
        for (int i = t; i < 196; i += 128) {
            int r = i >> 2, c = i & 3;
            uint32_t off = r * 80 + c * 16;
            cp16(qb + off, qg + i);
            cp16(qb + 5120 + off, kg + i);
            cp16(qb + 10240 + off, vg + i);
        }
        uint32_t cb = smb + 61440 + (buf * 2 + wg) * 7168;
        const uint4* cg = (const uint4*)(g_cmb + (size_t)(cls * NHEADS + h) * (64 * 56));
        for (int i = t; i < 448; i += 128) cp16(cb + i * 16, cg + i);
        cp_commit();
    };

    load_pair(0, 0);

    int buf = 0;
    for (int h2 = 0; h2 < 3; h2++) {
        int h = h2 * 2 + wg;
        if (h2 < 2) load_pair(buf ^ 1, h2 + 1);
        if (h2 < 2) cp_wait1(); else cp_wait0();
        __syncthreads();

        uint32_t qbase = smb + (buf * 2 + wg) * 15360;
        uint32_t kbase = qbase + 5120, vbase = qbase + 10240;
        uint32_t cbase = smb + 61440 + (buf * 2 + wg) * 7168;

        uint32_t qf[2][4];
        #pragma unroll
        for (int ks = 0; ks < 2; ks++) {
            int row = mr + (g & 1) * 8 + r8;
            int col = ks * 16 + (g >> 1) * 8;
            ldm4(qf[ks][0], qf[ks][1], qf[ks][2], qf[ks][3], qbase + row * 80 + col * 2);
        }

        float sacc[7][4] = {};
        #pragma unroll
        for (int ks = 0; ks < 2; ks++) {
            #pragma unroll
            for (int np = 0; np < 4; np++) {
                int row = np * 16 + ((g >> 1) & 1) * 8 + r8;
                int col = ks * 16 + (g & 1) * 8;
                uint32_t b0, b1, b2, b3;
                ldm4(b0, b1, b2, b3, kbase + row * 80 + col * 2);
                mma16816(sacc[2 * np][0], sacc[2 * np][1], sacc[2 * np][2], sacc[2 * np][3],
                         qf[ks][0], qf[ks][1], qf[ks][2], qf[ks][3], b0, b1);
                if (np < 3)
                    mma16816(sacc[2 * np + 1][0], sacc[2 * np + 1][1], sacc[2 * np + 1][2], sacc[2 * np + 1][3],
                             qf[ks][0], qf[ks][1], qf[ks][2], qf[ks][3], b2, b3);
            }
        }

        #pragma unroll
        for (int np = 0; np < 4; np++) {
            int row = mr + (g & 1) * 8 + r8;
            int colc = 2 * np + ((g >> 1) & 1); if (colc > 6) colc = 6;
            uint32_t c0, c1, c2, c3;
            ldm4(c0, c1, c2, c3, cbase + row * 112 + colc * 8 * 2);
            float2 f;
            f = __half22float2(*(__half2*)&c0); sacc[2 * np][0] += f.x; sacc[2 * np][1] += f.y;
            f = __half22float2(*(__half2*)&c1); sacc[2 * np][2] += f.x; sacc[2 * np][3] += f.y;
            if (np < 3) {
                f = __half22float2(*(__half2*)&c2); sacc[2 * np + 1][0] += f.x; sacc[2 * np + 1][1] += f.y;
                f = __half22float2(*(__half2*)&c3); sacc[2 * np + 1][2] += f.x; sacc[2 * np + 1][3] += f.y;
            }
        }

        float mx0 = -1e30f, mx8 = -1e30f;
        #pragma unroll
        for (int nt = 0; nt < 7; nt++) {
            mx0 = fmaxf(mx0, fmaxf(sacc[nt][0], sacc[nt][1]));
            mx8 = fmaxf(mx8, fmaxf(sacc[nt][2], sacc[nt][3]));
        }
        #pragma unroll
        for (int o = 1; o <= 2; o <<= 1) {
            mx0 = fmaxf(mx0, __shfl_xor_sync(0xffffffffu, mx0, o));
            mx8 = fmaxf(mx8, __shfl_xor_sync(0xffffffffu, mx8, o));
        }
        float s0 = 0.f, s8 = 0.f;
        #pragma unroll
        for (int nt = 0; nt < 7; nt++) {
            sacc[nt][0] = __expf(sacc[nt][0] - mx0); s0 += sacc[nt][0];
            sacc[nt][1] = __expf(sacc[nt][1] - mx0); s0 += sacc[nt][1];
            sacc[nt][2] = __expf(sacc[nt][2] - mx8); s8 += sacc[nt][2];
            sacc[nt][3] = __expf(sacc[nt][3] - mx8); s8 += sacc[nt][3];
        }
        #pragma unroll
        for (int o = 1; o <= 2; o <<= 1) {
            s0 += __shfl_xor_sync(0xffffffffu, s0, o);
            s8 += __shfl_xor_sync(0xffffffffu, s8, o);
        }
        float inv0 = 1.f / s0, inv8 = 1.f / s8;
        #pragma unroll
        for (int nt = 0; nt < 7; nt++) {
            sacc[nt][0] *= inv0; sacc[nt][1] *= inv0;
            sacc[nt][2] *= inv8; sacc[nt][3] *= inv8;
        }

        float oacc[4][4] = {};
        #pragma unroll
        for (int kt = 0; kt < 4; kt++) {
            uint32_t a0 = f22u(sacc[2 * kt][0], sacc[2 * kt][1]);
            uint32_t a1 = f22u(sacc[2 * kt][2], sacc[2 * kt][3]);
            uint32_t a2 = 0, a3 = 0;
            if (kt < 3) {
                a2 = f22u(sacc[2 * kt + 1][0], sacc[2 * kt + 1][1]);
                a3 = f22u(sacc[2 * kt + 1][2], sacc[2 * kt + 1][3]);
            }
            #pragma unroll
            for (int dp = 0; dp < 2; dp++) {
                int row = kt * 16 + (g & 1) * 8 + r8;
                int col = dp * 16 + ((g >> 1) & 1) * 8;
                uint32_t b0, b1, b2, b3;
                ldm4t(b0, b1, b2, b3, vbase + row * 80 + col * 2);
                mma16816(oacc[2 * dp][0], oacc[2 * dp][1], oacc[2 * dp][2], oacc[2 * dp][3],
                         a0, a1, a2, a3, b0, b1);
                mma16816(oacc[2 * dp + 1][0], oacc[2 * dp + 1][1], oacc[2 * dp + 1][2], oacc[2 * dp + 1][3],
                         a0, a1, a2, a3, b2, b3);
            }
        }

        int r0 = mr + (lane >> 2);
        int cbase2 = h * DHEAD + 2 * (lane & 3);
        if (r0 < NTOK) {
            size_t ob = ((size_t)win * NTOK + r0) * CC + cbase2;
            #pragma unroll
            for (int dn = 0; dn < 4; dn++)
                *(__half2*)&outs[ob + dn * 8] = __floats2half2_rn(oacc[dn][0], oacc[dn][1]);
        }
        int r1 = r0 + 8;
        if (r1 < NTOK) {
            size_t ob = ((size_t)win * NTOK + r1) * CC + cbase2;
            #pragma unroll
            for (int dn = 0; dn < 4; dn++)
                *(__half2*)&outs[ob + dn * 8] = __floats2half2_rn(oacc[dn][2], oacc[dn][3]);
        }
        __syncthreads();
        buf ^= 1;
    }
}

// ---------------- launch ----------------
extern "C" void kernel_launch(void* const* d_in, const int* in_sizes, int n_in,
                              void* d_out, int out_size) {
    const float* x      = (const float*)d_in[0];
    const float* amask  = (const float*)d_in[1];
    const float* n1g    = (const float*)d_in[2];
    const float* n1b    = (const float*)d_in[3];
    const float* qkv_w  = (const float*)d_in[4];
    const float* qkv_b  = (const float*)d_in[5];
    const float* rpb    = (const float*)d_in[6];
    const float* proj_w = (const float*)d_in[7];
    const float* proj_b = (const float*)d_in[8];
    const float* n2g    = (const float*)d_in[9];
    const float* n2b    = (const float*)d_in[10];
    const float* fc1_w  = (const float*)d_in[11];
    const float* fc1_b  = (const float*)d_in[12];
    const float* fc2_w  = (const float*)d_in[13];
    const float* fc2_b  = (const float*)d_in[14];
    float* out = (float*)d_out;

    __half *xs, *aos, *hs, *wqkv, *wproj, *wfc1, *wfc2;
    float *x2;
    cudaGetSymbolAddress((void**)&xs,    g_xs);
    cudaGetSymbolAddress((void**)&aos,   g_aos);
    cudaGetSymbolAddress((void**)&hs,    g_hs);
    cudaGetSymbolAddress((void**)&x2,    g_x2);
    cudaGetSymbolAddress((void**)&wqkv,  g_wqkv);
    cudaGetSymbolAddress((void**)&wproj, g_wproj);
    cudaGetSymbolAddress((void**)&wfc1,  g_wfc1);
    cudaGetSymbolAddress((void**)&wfc2,  g_wfc2);

    cudaFuncSetAttribute(gemm_qkv,    cudaFuncAttributeMaxDynamicSharedMemorySize, SMEM_QKV);
    cudaFuncSetAttribute(gemm_mlp,    cudaFuncAttributeMaxDynamicSharedMemorySize, SMEM_MLP);
    cudaFuncSetAttribute(gemm_pipe64, cudaFuncAttributeMaxDynamicSharedMemorySize, SMEM_P64);
    cudaFuncSetAttribute(attn_mma,    cudaFuncAttributeMaxDynamicSharedMemorySize, SMEM_ATTN);

    const int MB = MROWS / 64;  // 3136

    prep_all<<<1728, 256>>>(qkv_w, proj_w, fc1_w, fc2_w);
    prep_cmb<<<24, 256>>>(amask, rpb);
    // 1) LN1 + shift + window partition -> fp16
    ln1_kernel<<<MROWS / 8, 256>>>(x, n1g, n1b, xs);
    // 2) QKV GEMM (3 independent N-blocks)
    gemm_qkv<<<dim3(3, MB), 256, SMEM_QKV>>>(xs, wqkv, qkv_b);
    // 3) attention
    attn_mma<<<NWIN, 256, SMEM_ATTN>>>(aos);
    // 4) proj + shortcut -> x2 (pixel), LN2 (smem), fc1 + gelu -> hs (pixel rows)
    gemm_mlp<<<MB, 256, SMEM_MLP>>>(aos, wproj, proj_b, x2, x, n2g, n2b, wfc1, fc1_b, hs);
    // 5) fc2 + residual -> out (pixel rows)
    gemm_pipe64<<<dim3(1, MB), 256, SMEM_P64>>>(hs, wfc2, fc2_b, out, x2);
}

// round 16
// speedup vs baseline: 1.1528x; 1.0287x over previous
#include <cuda_runtime.h>
#include <cuda_fp16.h>
#include <math.h>
#include <stdint.h>

// ---------------- problem constants ----------------
#define BATCH   16
#define IMG     112
#define CC      192
#define NHEADS  6
#define DHEAD   32
#define WSZ     7
#define NTOK    49
#define NWIN    4096
#define MROWS   200704
#define HID     768

// ---------------- device scratch ----------------
__device__ __half g_xs [(size_t)MROWS * CC];
__device__ __half g_aos[(size_t)MROWS * CC];
__device__ __half g_hs [(size_t)MROWS * HID];    // PIXEL order
__device__ __half g_q[(size_t)NWIN * NHEADS * NTOK * DHEAD];
__device__ __half g_k[(size_t)NWIN * NHEADS * NTOK * DHEAD];
__device__ __half g_v[(size_t)NWIN * NHEADS * NTOK * DHEAD];
__device__ float g_x2[(size_t)MROWS * CC];       // PIXEL order
__device__ __half g_wqkv [(size_t)576 * 192];
__device__ __half g_wproj[(size_t)192 * 192];
__device__ __half g_wfc1 [(size_t)768 * 192];
__device__ __half g_wfc2 [(size_t)192 * 768];
__device__ __half g_cmb[(size_t)4 * NHEADS * 64 * 56];

// ---------------- helpers ----------------
__device__ __forceinline__ uint32_t smem_to_u32(const void* p) {
    uint32_t a;
    asm("{ .reg .u64 t; cvta.to.shared.u64 t, %1; cvt.u32.u64 %0, t; }" : "=r"(a) : "l"(p));
    return a;
}
__device__ __forceinline__ void cp16(uint32_t sm, const void* gp) {
    asm volatile("cp.async.cg.shared.global [%0], [%1], 16;" :: "r"(sm), "l"(gp));
}
__device__ __forceinline__ void cp_commit() { asm volatile("cp.async.commit_group;"); }
__device__ __forceinline__ void cp_wait1()  { asm volatile("cp.async.wait_group 1;"); }
__device__ __forceinline__ void cp_wait0()  { asm volatile("cp.async.wait_group 0;"); }

__device__ __forceinline__ void ldm4(uint32_t& x0, uint32_t& x1, uint32_t& x2, uint32_t& x3, uint32_t addr) {
    asm volatile("ldmatrix.sync.aligned.m8n8.x4.shared.b16 {%0,%1,%2,%3}, [%4];"
                 : "=r"(x0), "=r"(x1), "=r"(x2), "=r"(x3) : "r"(addr));
}
__device__ __forceinline__ void ldm4t(uint32_t& x0, uint32_t& x1, uint32_t& x2, uint32_t& x3, uint32_t addr) {
    asm volatile("ldmatrix.sync.aligned.m8n8.x4.trans.shared.b16 {%0,%1,%2,%3}, [%4];"
                 : "=r"(x0), "=r"(x1), "=r"(x2), "=r"(x3) : "r"(addr));
}
__device__ __forceinline__ void mma16816(float& d0, float& d1, float& d2, float& d3,
                                         uint32_t a0, uint32_t a1, uint32_t a2, uint32_t a3,
                                         uint32_t b0, uint32_t b1) {
    asm volatile("mma.sync.aligned.m16n8k16.row.col.f32.f16.f16.f32 "
                 "{%0,%1,%2,%3},{%4,%5,%6,%7},{%8,%9},{%0,%1,%2,%3};"
                 : "+f"(d0), "+f"(d1), "+f"(d2), "+f"(d3)
                 : "r"(a0), "r"(a1), "r"(a2), "r"(a3), "r"(b0), "r"(b1));
}
__device__ __forceinline__ uint32_t f22u(float a, float b) {
    __half2 h = __floats2half2_rn(a, b);
    return *(uint32_t*)&h;
}
// full-K tile: rows of 192 halves (384B, 24 x 16B chunks)
__device__ __forceinline__ uint32_t full_off(int row, int c) {
    return (uint32_t)(row * 384 + (((c & 24) | ((c ^ row) & 7)) << 4));
}
// 64-half tile: rows of 128B, 8 x 16B chunks
__device__ __forceinline__ uint32_t t64_addr(uint32_t base, int row, int c) {
    return base + row * 128 + (((c ^ row) & 7) << 4);
}
__device__ __forceinline__ float gelu_exact(float x) {
    return 0.5f * x * (1.f + erff(x * 0.70710678118654752f));
}
__device__ __forceinline__ int pix_of_row(int row) {
    int win = row / NTOK, n = row - win * NTOK;
    int b = win >> 8, wi = win & 255;
    int hh = (wi >> 4) * WSZ + n / WSZ;
    int ww = (wi & 15) * WSZ + n % WSZ;
    int p = hh + 3; if (p >= IMG) p -= IMG;
    int q = ww + 3; if (q >= IMG) q -= IMG;
    return (b * IMG + p) * IMG + q;
}

// ---------------- merged prep: weights (blocks 0..1727) + cmb (blocks 1728..1751) ----------------
__global__ void prep_merged(const float* __restrict__ qkv_w, const float* __restrict__ proj_w,
                            const float* __restrict__ fc1_w, const float* __restrict__ fc2_w,
                            const float* __restrict__ amask, const float* __restrict__ rpb) {
    if (blockIdx.x >= 1728) {
        int ch = blockIdx.x - 1728;
        int cls = ch / NHEADS, head = ch - cls * NHEADS;
        int wi_rep = (cls >> 1 ? 240 : 0) + ((cls & 1) ? 15 : 0);
        __half* dst = g_cmb + (size_t)ch * (64 * 56);
        for (int idx = threadIdx.x; idx < 64 * 56; idx += 256) {
            int r = idx / 56, c = idx - r * 56;
            float v;
            if (r < NTOK && c < NTOK) {
                int i1 = r / WSZ, j1 = r - i1 * WSZ;
                int i2 = c / WSZ, j2 = c - i2 * WSZ;
                int rel = (i1 - i2 + 6) * 13 + (j1 - j2 + 6);
                v = rpb[rel * NHEADS + head] + amask[((size_t)wi_rep * NTOK + r) * NTOK + c];
            } else {
                v = -100.f;
            }
            dst[idx] = __float2half(v);
        }
        return;
    }
    int i = blockIdx.x * 256 + threadIdx.x;
    const float* W; __half* D; int K, N, off;
    if (i < 110592)      { W = qkv_w;  D = g_wqkv;  K = 192; N = 576; off = i; }
    else if (i < 147456) { W = proj_w; D = g_wproj; K = 192; N = 192; off = i - 110592; }
    else if (i < 294912) { W = fc1_w;  D = g_wfc1;  K = 192; N = 768; off = i - 147456; }
    else if (i < 442368) { W = fc2_w;  D = g_wfc2;  K = 768; N = 192; off = i - 294912; }
    else return;
    int k = off / N, n = off - k * N;
    D[(size_t)n * K + k] = __float2half(W[off]);
}

// ---------------- LN1 (fused shift + window partition) ----------------
__global__ __launch_bounds__(256) void ln1_kernel(const float* __restrict__ src_full,
                                                  const float* __restrict__ gam,
                                                  const float* __restrict__ bet,
                                                  __half* __restrict__ out) {
    int t = blockIdx.x * 8 + (threadIdx.x >> 5);
    int lane = threadIdx.x & 31;
    int win = t / NTOK, n = t - win * NTOK;
    int b = win >> 8, wi = win & 255;
    int hh = (wi >> 4) * WSZ + n / WSZ;
    int ww = (wi & 15) * WSZ + n % WSZ;
    int sh = hh + 3; if (sh >= IMG) sh -= IMG;
    int sw = ww + 3; if (sw >= IMG) sw -= IMG;
    const float* src = src_full + (size_t)((b * IMG + sh) * IMG + sw) * CC;

    float v[6]; float s = 0.f, s2 = 0.f;
    #pragma unroll
    for (int i = 0; i < 6; i++) { float a = src[i * 32 + lane]; v[i] = a; s += a; s2 += a * a; }
    #pragma unroll
    for (int o = 16; o; o >>= 1) {
        s  += __shfl_xor_sync(0xffffffffu, s,  o);
        s2 += __shfl_xor_sync(0xffffffffu, s2, o);
    }
    float mean = s * (1.f / 192.f);
    float var  = s2 * (1.f / 192.f) - mean * mean;
    float rstd = rsqrtf(var + 1e-5f);
    __half* dst = out + (size_t)t * CC;
    #pragma unroll
    for (int i = 0; i < 6; i++) {
        int c = i * 32 + lane;
        dst[c] = __float2half((v[i] - mean) * rstd * gam[c] + bet[c]);
    }
}

// ---- mainloop over k-step range [KS0, KS1) on resident full-K tiles ----
template<int KS0, int KS1>
__device__ __forceinline__ void mainloop_rng(uint32_t a_base, uint32_t b_base,
                                             int wm, int wn, int lane,
                                             float acc[2][6][4]) {
    int arow = wm * 32 + (lane & 15);
    int bnrow = wn * 48 + (lane & 7) + ((lane >> 4) << 3);
    int bk8 = (lane >> 3) & 1;
    #pragma unroll
    for (int ks = KS0; ks < KS1; ks++) {
        uint32_t af[2][4];
        #pragma unroll
        for (int mt = 0; mt < 2; mt++)
            ldm4(af[mt][0], af[mt][1], af[mt][2], af[mt][3],
                 a_base + full_off(arow + mt * 16, ks * 2 + (lane >> 4)));
        uint32_t bf[6][2];
        #pragma unroll
        for (int pr = 0; pr < 3; pr++)
            ldm4(bf[2 * pr][0], bf[2 * pr][1], bf[2 * pr + 1][0], bf[2 * pr + 1][1],
                 b_base + full_off(bnrow + pr * 16, ks * 2 + bk8));
        #pragma unroll
        for (int mt = 0; mt < 2; mt++)
            #pragma unroll
            for (int nt = 0; nt < 6; nt++)
                mma16816(acc[mt][nt][0], acc[mt][nt][1], acc[mt][nt][2], acc[mt][nt][3],
                         af[mt][0], af[mt][1], af[mt][2], af[mt][3],
                         bf[nt][0], bf[nt][1]);
    }
}

// half-tile loaders: chunks [c0, c0+12) of A(64 rows) / B(192 rows)
__device__ __forceinline__ void load_A_half(uint32_t a_base, const __half* Ag, int tid, int c0) {
    #pragma unroll
    for (int i = 0; i < 3; i++) {
        int t = tid + i * 256, row = t / 12, c = c0 + (t % 12);
        cp16(a_base + full_off(row, c), Ag + (size_t)row * 192 + c * 8);
    }
}
__device__ __forceinline__ void load_B_half(uint32_t b_base, const __half* Bg, int tid, int c0) {
    #pragma unroll
    for (int i = 0; i < 9; i++) {
        int t = tid + i * 256, row = t / 12, c = c0 + (t % 12);
        cp16(b_base + full_off(row, c), Bg + (size_t)row * 192 + c * 8);
    }
}

// ================= gemm_qkv: split-K two-stage load =================
#define SMEM_QKV 98304
__global__ __launch_bounds__(256, 2)
void gemm_qkv(const __half* __restrict__ A2, const __half* __restrict__ B2,
              const float* __restrict__ bias) {
    extern __shared__ __align__(16) char sm_dyn[];
    uint32_t a_base = smem_to_u32(sm_dyn);
    uint32_t b_base = a_base + 24576;

    int tid = threadIdx.x, lane = tid & 31, wid = tid >> 5;
    int wm = wid >> 2, wn = wid & 3;
    int bm = blockIdx.y * 64;
    int nc = blockIdx.x;
    const __half* Ag = A2 + (size_t)bm * 192;
    const __half* Bg = B2 + (size_t)nc * 192 * 192;

    load_A_half(a_base, Ag, tid, 0);
    load_B_half(b_base, Bg, tid, 0);
    cp_commit();
    load_A_half(a_base, Ag, tid, 12);
    load_B_half(b_base, Bg, tid, 12);
    cp_commit();

    cp_wait1();
    __syncthreads();
    float acc[2][6][4] = {};
    mainloop_rng<0, 6>(a_base, b_base, wm, wn, lane, acc);
    cp_wait0();
    __syncthreads();
    mainloop_rng<6, 12>(a_base, b_base, wm, wn, lane, acc);

    float scale = (nc == 0) ? 0.17677669529663687f : 1.f;
    __half* dst = (nc == 0) ? g_q : ((nc == 1) ? g_k : g_v);
    float2 bcol[6];
    #pragma unroll
    for (int nt = 0; nt < 6; nt++)
        bcol[nt] = *(const float2*)&bias[nc * 192 + wn * 48 + nt * 8 + 2 * (lane & 3)];

    #pragma unroll
    for (int mt = 0; mt < 2; mt++) {
        #pragma unroll
        for (int half = 0; half < 2; half++) {
            int row = bm + wm * 32 + mt * 16 + (lane >> 2) + half * 8;
            int win = row / NTOK, n = row - win * NTOK;
            #pragma unroll
            for (int nt = 0; nt < 6; nt++) {
                int col = wn * 48 + nt * 8 + 2 * (lane & 3);
                int head = col >> 5, dd = col & 31;
                float vx = (acc[mt][nt][half * 2] + bcol[nt].x) * scale;
                float vy = (acc[mt][nt][half * 2 + 1] + bcol[nt].y) * scale;
                *(__half2*)&dst[(((size_t)win * NHEADS + head) * NTOK + n) * DHEAD + dd] =
                    __floats2half2_rn(vx, vy);
            }
        }
    }
}

// ================= gemm_mlp: proj(split-K start) -> x2/LN2(smem) -> fc1 x4 -> hs (PIXEL) =======
#define SMEM_MLP 107008
__global__ __launch_bounds__(256, 2)
void gemm_mlp(const __half* __restrict__ Aaos, const __half* __restrict__ Wproj,
              const float* __restrict__ pbias, float* __restrict__ x2out,
              const float* __restrict__ xsrc,
              const float* __restrict__ g2, const float* __restrict__ b2,
              const __half* __restrict__ Wfc1, const float* __restrict__ f1bias,
              __half* __restrict__ hsout) {
    extern __shared__ __align__(16) char sm_dyn[];
    uint32_t a_base = smem_to_u32(sm_dyn);
    uint32_t b_base = a_base + 24576;
    float* red  = (float*)(sm_dyn + 98304);
    float* redq = (float*)(sm_dyn + 102656);

    int tid = threadIdx.x, lane = tid & 31, wid = tid >> 5;
    int wm = wid >> 2, wn = wid & 3;
    int bm = blockIdx.x * 64;
    const __half* Ag = Aaos + (size_t)bm * 192;

    load_A_half(a_base, Ag, tid, 0);
    load_B_half(b_base, Wproj, tid, 0);
    cp_commit();
    load_A_half(a_base, Ag, tid, 12);
    load_B_half(b_base, Wproj, tid, 12);
    cp_commit();

    cp_wait1();
    __syncthreads();
    float acc[2][6][4] = {};
    mainloop_rng<0, 6>(a_base, b_base, wm, wn, lane, acc);
    cp_wait0();
    __syncthreads();
    mainloop_rng<6, 12>(a_base, b_base, wm, wn, lane, acc);
    __syncthreads();   // b_base free

    // prefetch fc1 chunk 0 (overlaps epilogue)
    load_B_half(b_base, Wfc1, tid, 0);
    load_B_half(b_base, Wfc1, tid, 12);
    cp_commit();

    // ---- proj epilogue: residual -> x2 (pixel), LN2 stats; cache pixel rows ----
    float2 bcol[6];
    #pragma unroll
    for (int nt = 0; nt < 6; nt++)
        bcol[nt] = *(const float2*)&pbias[wn * 48 + nt * 8 + 2 * (lane & 3)];
    int slot = wn * 4 + (lane & 3);
    int pixrow[2][2];

    #pragma unroll
    for (int mt = 0; mt < 2; mt++) {
        #pragma unroll
        for (int half = 0; half < 2; half++) {
            int rl = wm * 32 + mt * 16 + (lane >> 2) + half * 8;
            int row = bm + rl;
            int pr = pix_of_row(row);
            pixrow[mt][half] = pr;
            size_t pixbase = (size_t)pr * CC;
            float s = 0.f, sq2 = 0.f;
            #pragma unroll
            for (int nt = 0; nt < 6; nt++) {
                int col = wn * 48 + nt * 8 + 2 * (lane & 3);
                float2 sc = *(const float2*)&xsrc[pixbase + col];
                float vx = acc[mt][nt][half * 2] + bcol[nt].x + sc.x;
                float vy = acc[mt][nt][half * 2 + 1] + bcol[nt].y + sc.y;
                acc[mt][nt][half * 2] = vx;
                acc[mt][nt][half * 2 + 1] = vy;
                *(float2*)&x2out[pixbase + col] = make_float2(vx, vy);
                s += vx + vy;
                sq2 += vx * vx + vy * vy;
            }
            red [rl * 17 + slot] = s;
            redq[rl * 17 + slot] = sq2;
        }
    }
    __syncthreads();
    if (tid < 64) {
        float s = 0.f, qq = 0.f;
        #pragma unroll
        for (int i = 0; i < 16; i++) { s += red[tid * 17 + i]; qq += redq[tid * 17 + i]; }
        float mean = s * (1.f / 192.f);
        float var = qq * (1.f / 192.f) - mean * mean;
        red [tid * 17 + 16] = mean;
        redq[tid * 17 + 16] = rsqrtf(var + 1e-5f);
    }
    __syncthreads();

    // ---- LN2'd xs into a_base (smem only) ----
    #pragma unroll
    for (int mt = 0; mt < 2; mt++) {
        #pragma unroll
        for (int half = 0; half < 2; half++) {
            int rl = wm * 32 + mt * 16 + (lane >> 2) + half * 8;
            float mean = red [rl * 17 + 16];
            float rstd = redq[rl * 17 + 16];
            #pragma unroll
            for (int nt = 0; nt < 6; nt++) {
                int col = wn * 48 + nt * 8 + 2 * (lane & 3);
                float2 gv = *(const float2*)&g2[col];
                float2 bv = *(const float2*)&b2[col];
                float yx = (acc[mt][nt][half * 2] - mean) * rstd * gv.x + bv.x;
                float yy = (acc[mt][nt][half * 2 + 1] - mean) * rstd * gv.y + bv.y;
                uint32_t addr = a_base + full_off(rl, col >> 3) + (col & 7) * 2;
                asm volatile("st.shared.b32 [%0], %1;" :: "r"(addr), "r"(f22u(yx, yy)));
            }
        }
    }

    // ---- fc1: 4 N-chunks of 192; outputs at PIXEL rows ----
    for (int nc = 0; nc < 4; nc++) {
        cp_wait0();
        __syncthreads();

        float acc2[2][6][4] = {};
        mainloop_rng<0, 12>(a_base, b_base, wm, wn, lane, acc2);
        __syncthreads();

        if (nc < 3) {
            const __half* Bg = Wfc1 + (size_t)(nc + 1) * 192 * 192;
            load_B_half(b_base, Bg, tid, 0);
            load_B_half(b_base, Bg, tid, 12);
            cp_commit();
        }

        float2 fb[6];
        #pragma unroll
        for (int nt = 0; nt < 6; nt++)
            fb[nt] = *(const float2*)&f1bias[nc * 192 + wn * 48 + nt * 8 + 2 * (lane & 3)];

        #pragma unroll
        for (int mt = 0; mt < 2; mt++) {
            #pragma unroll
            for (int half = 0; half < 2; half++) {
                size_t rb = (size_t)pixrow[mt][half] * HID + nc * 192;
                #pragma unroll
                for (int nt = 0; nt < 6; nt++) {
                    int col = wn * 48 + nt * 8 + 2 * (lane & 3);
                    float gx = gelu_exact(acc2[mt][nt][half * 2] + fb[nt].x);
                    float gy = gelu_exact(acc2[mt][nt][half * 2 + 1] + fb[nt].y);
                    *(__half2*)&hsout[rb + col] = __floats2half2_rn(gx, gy);
                }
            }
        }
    }
}

// ================= gemm_pipe64 (fc2: K=768, PIXEL rows): 3-stage BK=64 pipeline =================
#define SMEM_P64 98304
__global__ __launch_bounds__(256, 2)
void gemm_pipe64(const __half* __restrict__ A2, const __half* __restrict__ B2,
                 const float* __restrict__ bias, float* __restrict__ outF,
                 const float* __restrict__ addsrc) {
    extern __shared__ __align__(16) char sm_dyn[];
    uint32_t a_base = smem_to_u32(sm_dyn);
    uint32_t b_base = a_base + 24576;
    const int K = 768;

    int tid = threadIdx.x, lane = tid & 31, wid = tid >> 5;
    int wm = wid >> 2, wn = wid & 3;
    int bm = blockIdx.y * 64, bn = blockIdx.x * 192;
    const int NC = 12;

    float acc[2][6][4] = {};

    auto issue = [&](int buf, int cc) {
        const __half* Ag = A2 + (size_t)bm * K + cc * 64;
        const __half* Bg = B2 + (size_t)bn * K + cc * 64;
        uint32_t ab = a_base + buf * 8192;
        uint32_t bb = b_base + buf * 24576;
        #pragma unroll
        for (int i = 0; i < 2; i++) {
            int t = tid + i * 256, row = t >> 3, c = t & 7;
            cp16(t64_addr(ab, row, c), Ag + (size_t)row * K + c * 8);
        }
        #pragma unroll
        for (int i = 0; i < 6; i++) {
            int t = tid + i * 256, row = t >> 3, c = t & 7;
            cp16(t64_addr(bb, row, c), Bg + (size_t)row * K + c * 8);
        }
        cp_commit();
    };

    issue(0, 0);
    issue(1, 1);

    for (int cc = 0; cc < NC; cc++) {
        int buf = cc % 3;
        if (cc + 1 < NC) cp_wait1(); else cp_wait0();
        __syncthreads();
        if (cc + 2 < NC) issue((cc + 2) % 3, cc + 2);

        uint32_t ab = a_base + buf * 8192;
        uint32_t bb = b_base + buf * 24576;
        int arow = wm * 32 + (lane & 15);
        int bnrow = wn * 48 + (lane & 7) + ((lane >> 4) << 3);
        int bk8 = (lane >> 3) & 1;
        #pragma unroll
        for (int ks = 0; ks < 4; ks++) {
            uint32_t af[2][4];
            #pragma unroll
            for (int mt = 0; mt < 2; mt++)
                ldm4(af[mt][0], af[mt][1], af[mt][2], af[mt][3],
                     t64_addr(ab, arow + mt * 16, ks * 2 + (lane >> 4)));
            uint32_t bf[6][2];
            #pragma unroll
            for (int pr = 0; pr < 3; pr++)
                ldm4(bf[2 * pr][0], bf[2 * pr][1], bf[2 * pr + 1][0], bf[2 * pr + 1][1],
                     t64_addr(bb, bnrow + pr * 16, ks * 2 + bk8));
            #pragma unroll
            for (int mt = 0; mt < 2; mt++)
                #pragma unroll
                for (int nt = 0; nt < 6; nt++)
                    mma16816(acc[mt][nt][0], acc[mt][nt][1], acc[mt][nt][2], acc[mt][nt][3],
                             af[mt][0], af[mt][1], af[mt][2], af[mt][3],
                             bf[nt][0], bf[nt][1]);
        }
    }

    float2 bcol[6];
    #pragma unroll
    for (int nt = 0; nt < 6; nt++) {
        int col = bn + wn * 48 + nt * 8 + 2 * (lane & 3);
        bcol[nt] = *(const float2*)&bias[col];
    }
    #pragma unroll
    for (int mt = 0; mt < 2; mt++) {
        #pragma unroll
        for (int half = 0; half < 2; half++) {
            int row = bm + wm * 32 + mt * 16 + (lane >> 2) + half * 8;
            size_t rb = (size_t)row * 192;
            #pragma unroll
            for (int nt = 0; nt < 6; nt++) {
                int col = bn + wn * 48 + nt * 8 + 2 * (lane & 3);
                float2 s = *(const float2*)&addsrc[rb + col];
                float vx = acc[mt][nt][half * 2] + bcol[nt].x + s.x;
                float vy = acc[mt][nt][half * 2 + 1] + bcol[nt].y + s.y;
                *(float2*)&outF[rb + col] = make_float2(vx, vy);
            }
        }
    }
}

// ---------------- attention: 256 thr, 2 heads parallel, cp.async double-buffered ----------------
#define SMEM_ATTN 90112
__global__ __launch_bounds__(256) void attn_mma(__half* __restrict__ outs) {
    extern __shared__ __align__(16) char sm_dyn[];
    uint32_t smb = smem_to_u32(sm_dyn);
    int win = blockIdx.x;
    int wi = win & 255;
    int cls = (((wi >> 4) == 15) ? 2 : 0) + (((wi & 15) == 15) ? 1 : 0);
    int tid = threadIdx.x;
    int wg = tid >> 7;
    int t = tid & 127;
    int lane = t & 31, wmg = t >> 5;
    int g = lane >> 3, r8 = lane & 7;
    int mr = wmg * 16;

    uint4 z = make_uint4(0, 0, 0, 0);
    for (int i = tid; i < 3840; i += 256) ((uint4*)sm_dyn)[i] = z;
    __syncthreads();

    auto load_pair = [&](int buf, int h2) {
        int h = h2 * 2 + wg;
        uint32_t qb = smb + (buf * 2 + wg) * 15360;
        const uint4* qg = (const uint4*)(g_q + (size_t)(win * NHEADS + h) * (NTOK * DHEAD));
        const uint4* kg = (const uint4*)(g_k + (size_t)(win * NHEADS + h) * (NTOK * DHEAD));
        const uint4* vg = (const uint4*)(g_v + (size_t)(win * NHEADS + h) * (NTOK * DHEAD));
        for (int i = t; i < 196; i += 128) {
            int r = i >> 2, c = i & 3;
            uint32_t off = r * 80 + c * 16;
            cp16(qb + off, qg + i);
            cp16(qb + 5120 + off, kg + i);
            cp16(qb + 10240 + off, vg + i);
        }
        uint32_t cb = smb + 61440 + (buf * 2 + wg) * 7168;
        const uint4* cg = (const uint4*)(g_cmb + (size_t)(cls * NHEADS + h) * (64 * 56));
        for (int i = t; i < 448; i += 128) cp16(cb + i * 16, cg + i);
        cp_commit();
    };

    load_pair(0, 0);

    int buf = 0;
    for (int h2 = 0; h2 < 3; h2++) {
        int h = h2 * 2 + wg;
        if (h2 < 2) load_pair(buf ^ 1, h2 + 1);
        if (h2 < 2) cp_wait1(); else cp_wait0();
        __syncthreads();

        uint32_t qbase = smb + (buf * 2 + wg) * 15360;
        uint32_t kbase = qbase + 5120, vbase = qbase + 10240;
        uint32_t cbase = smb + 61440 + (buf * 2 + wg) * 7168;

        uint32_t qf[2][4];
        #pragma unroll
        for (int ks = 0; ks < 2; ks++) {
            int row = mr + (g & 1) * 8 + r8;
            int col = ks * 16 + (g >> 1) * 8;
            ldm4(qf[ks][0], qf[ks][1], qf[ks][2], qf[ks][3], qbase + row * 80 + col * 2);
        }

        float sacc[7][4] = {};
        #pragma unroll
        for (int ks = 0; ks < 2; ks++) {
            #pragma unroll
            for (int np = 0; np < 4; np++) {
                int row = np * 16 + ((g >> 1) & 1) * 8 + r8;
                int col = ks * 16 + (g & 1) * 8;
                uint32_t b0, b1, b2, b3;
                ldm4(b0, b1, b2, b3, kbase + row * 80 + col * 2);
                mma16816(sacc[2 * np][0], sacc[2 * np][1], sacc[2 * np][2], sacc[2 * np][3],
                         qf[ks][0], qf[ks][1], qf[ks][2], qf[ks][3], b0, b1);
                if (np < 3)
                    mma16816(sacc[2 * np + 1][0], sacc[2 * np + 1][1], sacc[2 * np + 1][2], sacc[2 * np + 1][3],
                             qf[ks][0], qf[ks][1], qf[ks][2], qf[ks][3], b2, b3);
            }
        }

        #pragma unroll
        for (int np = 0; np < 4; np++) {
            int row = mr + (g & 1) * 8 + r8;
            int colc = 2 * np + ((g >> 1) & 1); if (colc > 6) colc = 6;
            uint32_t c0, c1, c2, c3;
            ldm4(c0, c1, c2, c3, cbase + row * 112 + colc * 8 * 2);
            float2 f;
            f = __half22float2(*(__half2*)&c0); sacc[2 * np][0] += f.x; sacc[2 * np][1] += f.y;
            f = __half22float2(*(__half2*)&c1); sacc[2 * np][2] += f.x; sacc[2 * np][3] += f.y;
            if (np < 3) {
                f = __half22float2(*(__half2*)&c2); sacc[2 * np + 1][0] += f.x; sacc[2 * np + 1][1] += f.y;
                f = __half22float2(*(__half2*)&c3); sacc[2 * np + 1][2] += f.x; sacc[2 * np + 1][3] += f.y;
            }
        }

        float mx0 = -1e30f, mx8 = -1e30f;
        #pragma unroll
        for (int nt = 0; nt < 7; nt++) {
            mx0 = fmaxf(mx0, fmaxf(sacc[nt][0], sacc[nt][1]));
            mx8 = fmaxf(mx8, fmaxf(sacc[nt][2], sacc[nt][3]));
        }
        #pragma unroll
        for (int o = 1; o <= 2; o <<= 1) {
            mx0 = fmaxf(mx0, __shfl_xor_sync(0xffffffffu, mx0, o));
            mx8 = fmaxf(mx8, __shfl_xor_sync(0xffffffffu, mx8, o));
        }
        float s0 = 0.f, s8 = 0.f;
        #pragma unroll
        for (int nt = 0; nt < 7; nt++) {
            sacc[nt][0] = __expf(sacc[nt][0] - mx0); s0 += sacc[nt][0];
            sacc[nt][1] = __expf(sacc[nt][1] - mx0); s0 += sacc[nt][1];
            sacc[nt][2] = __expf(sacc[nt][2] - mx8); s8 += sacc[nt][2];
            sacc[nt][3] = __expf(sacc[nt][3] - mx8); s8 += sacc[nt][3];
        }
        #pragma unroll
        for (int o = 1; o <= 2; o <<= 1) {
            s0 += __shfl_xor_sync(0xffffffffu, s0, o);
            s8 += __shfl_xor_sync(0xffffffffu, s8, o);
        }
        float inv0 = 1.f / s0, inv8 = 1.f / s8;
        #pragma unroll
        for (int nt = 0; nt < 7; nt++) {
            sacc[nt][0] *= inv0; sacc[nt][1] *= inv0;
            sacc[nt][2] *= inv8; sacc[nt][3] *= inv8;
        }

        float oacc[4][4] = {};
        #pragma unroll
        for (int kt = 0; kt < 4; kt++) {
            uint32_t a0 = f22u(sacc[2 * kt][0], sacc[2 * kt][1]);
            uint32_t a1 = f22u(sacc[2 * kt][2], sacc[2 * kt][3]);
            uint32_t a2 = 0, a3 = 0;
            if (kt < 3) {
                a2 = f22u(sacc[2 * kt + 1][0], sacc[2 * kt + 1][1]);
                a3 = f22u(sacc[2 * kt + 1][2], sacc[2 * kt + 1][3]);
            }
            #pragma unroll
            for (int dp = 0; dp < 2; dp++) {
                int row = kt * 16 + (g & 1) * 8 + r8;
                int col = dp * 16 + ((g >> 1) & 1) * 8;
                uint32_t b0, b1, b2, b3;
                ldm4t(b0, b1, b2, b3, vbase + row * 80 + col * 2);
                mma16816(oacc[2 * dp][0], oacc[2 * dp][1], oacc[2 * dp][2], oacc[2 * dp][3],
                         a0, a1, a2, a3, b0, b1);
                mma16816(oacc[2 * dp + 1][0], oacc[2 * dp + 1][1], oacc[2 * dp + 1][2], oacc[2 * dp + 1][3],
                         a0, a1, a2, a3, b2, b3);
            }
        }

        int r0 = mr + (lane >> 2);
        int cbase2 = h * DHEAD + 2 * (lane & 3);
        if (r0 < NTOK) {
            size_t ob = ((size_t)win * NTOK + r0) * CC + cbase2;
            #pragma unroll
            for (int dn = 0; dn < 4; dn++)
                *(__half2*)&outs[ob + dn * 8] = __floats2half2_rn(oacc[dn][0], oacc[dn][1]);
        }
        int r1 = r0 + 8;
        if (r1 < NTOK) {
            size_t ob = ((size_t)win * NTOK + r1) * CC + cbase2;
            #pragma unroll
            for (int dn = 0; dn < 4; dn++)
                *(__half2*)&outs[ob + dn * 8] = __floats2half2_rn(oacc[dn][2], oacc[dn][3]);
        }
        __syncthreads();
        buf ^= 1;
    }
}

// ---------------- launch ----------------
extern "C" void kernel_launch(void* const* d_in, const int* in_sizes, int n_in,
                              void* d_out, int out_size) {
    const float* x      = (const float*)d_in[0];
    const float* amask  = (const float*)d_in[1];
    const float* n1g    = (const float*)d_in[2];
    const float* n1b    = (const float*)d_in[3];
    const float* qkv_w  = (const float*)d_in[4];
    const float* qkv_b  = (const float*)d_in[5];
    const float* rpb    = (const float*)d_in[6];
    const float* proj_w = (const float*)d_in[7];
    const float* proj_b = (const float*)d_in[8];
    const float* n2g    = (const float*)d_in[9];
    const float* n2b    = (const float*)d_in[10];
    const float* fc1_w  = (const float*)d_in[11];
    const float* fc1_b  = (const float*)d_in[12];
    const float* fc2_w  = (const float*)d_in[13];
    const float* fc2_b  = (const float*)d_in[14];
    float* out = (float*)d_out;

    __half *xs, *aos, *hs, *wqkv, *wproj, *wfc1, *wfc2;
    float *x2;
    cudaGetSymbolAddress((void**)&xs,    g_xs);
    cudaGetSymbolAddress((void**)&aos,   g_aos);
    cudaGetSymbolAddress((void**)&hs,    g_hs);
    cudaGetSymbolAddress((void**)&x2,    g_x2);
    cudaGetSymbolAddress((void**)&wqkv,  g_wqkv);
    cudaGetSymbolAddress((void**)&wproj, g_wproj);
    cudaGetSymbolAddress((void**)&wfc1,  g_wfc1);
    cudaGetSymbolAddress((void**)&wfc2,  g_wfc2);

    cudaFuncSetAttribute(gemm_qkv,    cudaFuncAttributeMaxDynamicSharedMemorySize, SMEM_QKV);
    cudaFuncSetAttribute(gemm_mlp,    cudaFuncAttributeMaxDynamicSharedMemorySize, SMEM_MLP);
    cudaFuncSetAttribute(gemm_pipe64, cudaFuncAttributeMaxDynamicSharedMemorySize, SMEM_P64);
    cudaFuncSetAttribute(attn_mma,    cudaFuncAttributeMaxDynamicSharedMemorySize, SMEM_ATTN);

    const int MB = MROWS / 64;  // 3136

    prep_merged<<<1752, 256>>>(qkv_w, proj_w, fc1_w, fc2_w, amask, rpb);
    ln1_kernel<<<MROWS / 8, 256>>>(x, n1g, n1b, xs);
    gemm_qkv<<<dim3(3, MB), 256, SMEM_QKV>>>(xs, wqkv, qkv_b);
    attn_mma<<<NWIN, 256, SMEM_ATTN>>>(aos);
    gemm_mlp<<<MB, 256, SMEM_MLP>>>(aos, wproj, proj_b, x2, x, n2g, n2b, wfc1, fc1_b, hs);
    gemm_pipe64<<<dim3(1, MB), 256, SMEM_P64>>>(hs, wfc2, fc2_b, out, x2);
}

// round 17
// speedup vs baseline: 1.1656x; 1.0111x over previous
#include <cuda_runtime.h>
#include <cuda_fp16.h>
#include <math.h>
#include <stdint.h>

// ---------------- problem constants ----------------
#define BATCH   16
#define IMG     112
#define CC      192
#define NHEADS  6
#define DHEAD   32
#define WSZ     7
#define NTOK    49
#define NWIN    4096
#define MROWS   200704
#define HID     768

// ---------------- device scratch ----------------
__device__ __half g_xs [(size_t)MROWS * CC];
__device__ __half g_aos[(size_t)MROWS * CC];
__device__ __half g_hs [(size_t)MROWS * HID];    // PIXEL order
__device__ __half g_q[(size_t)NWIN * NHEADS * NTOK * DHEAD];
__device__ __half g_k[(size_t)NWIN * NHEADS * NTOK * DHEAD];
__device__ __half g_v[(size_t)NWIN * NHEADS * NTOK * DHEAD];
__device__ float g_x2[(size_t)MROWS * CC];       // PIXEL order
__device__ __half g_wqkv [(size_t)576 * 192];
__device__ __half g_wproj[(size_t)192 * 192];
__device__ __half g_wfc1 [(size_t)768 * 192];
__device__ __half g_wfc2 [(size_t)192 * 768];
__device__ __half g_cmb[(size_t)4 * NHEADS * 64 * 56];

// ---------------- helpers ----------------
__device__ __forceinline__ uint32_t smem_to_u32(const void* p) {
    uint32_t a;
    asm("{ .reg .u64 t; cvta.to.shared.u64 t, %1; cvt.u32.u64 %0, t; }" : "=r"(a) : "l"(p));
    return a;
}
__device__ __forceinline__ void cp16(uint32_t sm, const void* gp) {
    asm volatile("cp.async.cg.shared.global [%0], [%1], 16;" :: "r"(sm), "l"(gp));
}
__device__ __forceinline__ void cp_commit() { asm volatile("cp.async.commit_group;"); }
__device__ __forceinline__ void cp_wait1()  { asm volatile("cp.async.wait_group 1;"); }
__device__ __forceinline__ void cp_wait0()  { asm volatile("cp.async.wait_group 0;"); }

__device__ __forceinline__ void ldm4(uint32_t& x0, uint32_t& x1, uint32_t& x2, uint32_t& x3, uint32_t addr) {
    asm volatile("ldmatrix.sync.aligned.m8n8.x4.shared.b16 {%0,%1,%2,%3}, [%4];"
                 : "=r"(x0), "=r"(x1), "=r"(x2), "=r"(x3) : "r"(addr));
}
__device__ __forceinline__ void ldm4t(uint32_t& x0, uint32_t& x1, uint32_t& x2, uint32_t& x3, uint32_t addr) {
    asm volatile("ldmatrix.sync.aligned.m8n8.x4.trans.shared.b16 {%0,%1,%2,%3}, [%4];"
                 : "=r"(x0), "=r"(x1), "=r"(x2), "=r"(x3) : "r"(addr));
}
__device__ __forceinline__ void mma16816(float& d0, float& d1, float& d2, float& d3,
                                         uint32_t a0, uint32_t a1, uint32_t a2, uint32_t a3,
                                         uint32_t b0, uint32_t b1) {
    asm volatile("mma.sync.aligned.m16n8k16.row.col.f32.f16.f16.f32 "
                 "{%0,%1,%2,%3},{%4,%5,%6,%7},{%8,%9},{%0,%1,%2,%3};"
                 : "+f"(d0), "+f"(d1), "+f"(d2), "+f"(d3)
                 : "r"(a0), "r"(a1), "r"(a2), "r"(a3), "r"(b0), "r"(b1));
}
__device__ __forceinline__ uint32_t f22u(float a, float b) {
    __half2 h = __floats2half2_rn(a, b);
    return *(uint32_t*)&h;
}
// full-K tile: rows of 192 halves (384B, 24 x 16B chunks)
__device__ __forceinline__ uint32_t full_off(int row, int c) {
    return (uint32_t)(row * 384 + (((c & 24) | ((c ^ row) & 7)) << 4));
}
// 64-half tile: rows of 128B, 8 x 16B chunks
__device__ __forceinline__ uint32_t t64_addr(uint32_t base, int row, int c) {
    return base + row * 128 + (((c ^ row) & 7) << 4);
}
__device__ __forceinline__ float gelu_exact(float x) {
    return 0.5f * x * (1.f + erff(x * 0.70710678118654752f));
}
__device__ __forceinline__ int pix_of_row(int row) {
    int win = row / NTOK, n = row - win * NTOK;
    int b = win >> 8, wi = win & 255;
    int hh = (wi >> 4) * WSZ + n / WSZ;
    int ww = (wi & 15) * WSZ + n % WSZ;
    int p = hh + 3; if (p >= IMG) p -= IMG;
    int q = ww + 3; if (q >= IMG) q -= IMG;
    return (b * IMG + p) * IMG + q;
}

// ---------------- merged prep: weights + cmb ----------------
__global__ void prep_merged(const float* __restrict__ qkv_w, const float* __restrict__ proj_w,
                            const float* __restrict__ fc1_w, const float* __restrict__ fc2_w,
                            const float* __restrict__ amask, const float* __restrict__ rpb) {
    if (blockIdx.x >= 1728) {
        int ch = blockIdx.x - 1728;
        int cls = ch / NHEADS, head = ch - cls * NHEADS;
        int wi_rep = (cls >> 1 ? 240 : 0) + ((cls & 1) ? 15 : 0);
        __half* dst = g_cmb + (size_t)ch * (64 * 56);
        for (int idx = threadIdx.x; idx < 64 * 56; idx += 256) {
            int r = idx / 56, c = idx - r * 56;
            float v;
            if (r < NTOK && c < NTOK) {
                int i1 = r / WSZ, j1 = r - i1 * WSZ;
                int i2 = c / WSZ, j2 = c - i2 * WSZ;
                int rel = (i1 - i2 + 6) * 13 + (j1 - j2 + 6);
                v = rpb[rel * NHEADS + head] + amask[((size_t)wi_rep * NTOK + r) * NTOK + c];
            } else {
                v = -100.f;
            }
            dst[idx] = __float2half(v);
        }
        return;
    }
    int i = blockIdx.x * 256 + threadIdx.x;
    const float* W; __half* D; int K, N, off;
    if (i < 110592)      { W = qkv_w;  D = g_wqkv;  K = 192; N = 576; off = i; }
    else if (i < 147456) { W = proj_w; D = g_wproj; K = 192; N = 192; off = i - 110592; }
    else if (i < 294912) { W = fc1_w;  D = g_wfc1;  K = 192; N = 768; off = i - 147456; }
    else if (i < 442368) { W = fc2_w;  D = g_wfc2;  K = 768; N = 192; off = i - 294912; }
    else return;
    int k = off / N, n = off - k * N;
    D[(size_t)n * K + k] = __float2half(W[off]);
}

// ---------------- LN1 (fused shift + window partition) ----------------
__global__ __launch_bounds__(256) void ln1_kernel(const float* __restrict__ src_full,
                                                  const float* __restrict__ gam,
                                                  const float* __restrict__ bet,
                                                  __half* __restrict__ out) {
    int t = blockIdx.x * 8 + (threadIdx.x >> 5);
    int lane = threadIdx.x & 31;
    int win = t / NTOK, n = t - win * NTOK;
    int b = win >> 8, wi = win & 255;
    int hh = (wi >> 4) * WSZ + n / WSZ;
    int ww = (wi & 15) * WSZ + n % WSZ;
    int sh = hh + 3; if (sh >= IMG) sh -= IMG;
    int sw = ww + 3; if (sw >= IMG) sw -= IMG;
    const float* src = src_full + (size_t)((b * IMG + sh) * IMG + sw) * CC;

    float v[6]; float s = 0.f, s2 = 0.f;
    #pragma unroll
    for (int i = 0; i < 6; i++) { float a = src[i * 32 + lane]; v[i] = a; s += a; s2 += a * a; }
    #pragma unroll
    for (int o = 16; o; o >>= 1) {
        s  += __shfl_xor_sync(0xffffffffu, s,  o);
        s2 += __shfl_xor_sync(0xffffffffu, s2, o);
    }
    float mean = s * (1.f / 192.f);
    float var  = s2 * (1.f / 192.f) - mean * mean;
    float rstd = rsqrtf(var + 1e-5f);
    __half* dst = out + (size_t)t * CC;
    #pragma unroll
    for (int i = 0; i < 6; i++) {
        int c = i * 32 + lane;
        dst[c] = __float2half((v[i] - mean) * rstd * gam[c] + bet[c]);
    }
}

// ---- mainloop over k-step range [KS0, KS1) ----
template<int KS0, int KS1>
__device__ __forceinline__ void mainloop_rng(uint32_t a_base, uint32_t b_base,
                                             int wm, int wn, int lane,
                                             float acc[2][6][4]) {
    int arow = wm * 32 + (lane & 15);
    int bnrow = wn * 48 + (lane & 7) + ((lane >> 4) << 3);
    int bk8 = (lane >> 3) & 1;
    #pragma unroll
    for (int ks = KS0; ks < KS1; ks++) {
        uint32_t af[2][4];
        #pragma unroll
        for (int mt = 0; mt < 2; mt++)
            ldm4(af[mt][0], af[mt][1], af[mt][2], af[mt][3],
                 a_base + full_off(arow + mt * 16, ks * 2 + (lane >> 4)));
        uint32_t bf[6][2];
        #pragma unroll
        for (int pr = 0; pr < 3; pr++)
            ldm4(bf[2 * pr][0], bf[2 * pr][1], bf[2 * pr + 1][0], bf[2 * pr + 1][1],
                 b_base + full_off(bnrow + pr * 16, ks * 2 + bk8));
        #pragma unroll
        for (int mt = 0; mt < 2; mt++)
            #pragma unroll
            for (int nt = 0; nt < 6; nt++)
                mma16816(acc[mt][nt][0], acc[mt][nt][1], acc[mt][nt][2], acc[mt][nt][3],
                         af[mt][0], af[mt][1], af[mt][2], af[mt][3],
                         bf[nt][0], bf[nt][1]);
    }
}

__device__ __forceinline__ void load_A_half(uint32_t a_base, const __half* Ag, int tid, int c0) {
    #pragma unroll
    for (int i = 0; i < 3; i++) {
        int t = tid + i * 256, row = t / 12, c = c0 + (t % 12);
        cp16(a_base + full_off(row, c), Ag + (size_t)row * 192 + c * 8);
    }
}
__device__ __forceinline__ void load_B_half(uint32_t b_base, const __half* Bg, int tid, int c0) {
    #pragma unroll
    for (int i = 0; i < 9; i++) {
        int t = tid + i * 256, row = t / 12, c = c0 + (t % 12);
        cp16(b_base + full_off(row, c), Bg + (size_t)row * 192 + c * 8);
    }
}

// ================= gemm_qkv: split-K two-stage load =================
#define SMEM_QKV 98304
__global__ __launch_bounds__(256, 2)
void gemm_qkv(const __half* __restrict__ A2, const __half* __restrict__ B2,
              const float* __restrict__ bias) {
    extern __shared__ __align__(16) char sm_dyn[];
    uint32_t a_base = smem_to_u32(sm_dyn);
    uint32_t b_base = a_base + 24576;

    int tid = threadIdx.x, lane = tid & 31, wid = tid >> 5;
    int wm = wid >> 2, wn = wid & 3;
    int bm = blockIdx.y * 64;
    int nc = blockIdx.x;
    const __half* Ag = A2 + (size_t)bm * 192;
    const __half* Bg = B2 + (size_t)nc * 192 * 192;

    load_A_half(a_base, Ag, tid, 0);
    load_B_half(b_base, Bg, tid, 0);
    cp_commit();
    load_A_half(a_base, Ag, tid, 12);
    load_B_half(b_base, Bg, tid, 12);
    cp_commit();

    cp_wait1();
    __syncthreads();
    float acc[2][6][4] = {};
    mainloop_rng<0, 6>(a_base, b_base, wm, wn, lane, acc);
    cp_wait0();
    __syncthreads();
    mainloop_rng<6, 12>(a_base, b_base, wm, wn, lane, acc);

    float scale = (nc == 0) ? 0.17677669529663687f : 1.f;
    __half* dst = (nc == 0) ? g_q : ((nc == 1) ? g_k : g_v);
    float2 bcol[6];
    #pragma unroll
    for (int nt = 0; nt < 6; nt++)
        bcol[nt] = *(const float2*)&bias[nc * 192 + wn * 48 + nt * 8 + 2 * (lane & 3)];

    #pragma unroll
    for (int mt = 0; mt < 2; mt++) {
        #pragma unroll
        for (int half = 0; half < 2; half++) {
            int row = bm + wm * 32 + mt * 16 + (lane >> 2) + half * 8;
            int win = row / NTOK, n = row - win * NTOK;
            #pragma unroll
            for (int nt = 0; nt < 6; nt++) {
                int col = wn * 48 + nt * 8 + 2 * (lane & 3);
                int head = col >> 5, dd = col & 31;
                float vx = (acc[mt][nt][half * 2] + bcol[nt].x) * scale;
                float vy = (acc[mt][nt][half * 2 + 1] + bcol[nt].y) * scale;
                *(__half2*)&dst[(((size_t)win * NHEADS + head) * NTOK + n) * DHEAD + dd] =
                    __floats2half2_rn(vx, vy);
            }
        }
    }
}

// ================= gemm_mlp: proj -> x2/LN2(smem) -> fc1 x4 -> hs (PIXEL) =================
#define SMEM_MLP 107008
__global__ __launch_bounds__(256, 2)
void gemm_mlp(const __half* __restrict__ Aaos, const __half* __restrict__ Wproj,
              const float* __restrict__ pbias, float* __restrict__ x2out,
              const float* __restrict__ xsrc,
              const float* __restrict__ g2, const float* __restrict__ b2,
              const __half* __restrict__ Wfc1, const float* __restrict__ f1bias,
              __half* __restrict__ hsout) {
    extern __shared__ __align__(16) char sm_dyn[];
    uint32_t a_base = smem_to_u32(sm_dyn);
    uint32_t b_base = a_base + 24576;
    float* red  = (float*)(sm_dyn + 98304);
    float* redq = (float*)(sm_dyn + 102656);

    int tid = threadIdx.x, lane = tid & 31, wid = tid >> 5;
    int wm = wid >> 2, wn = wid & 3;
    int bm = blockIdx.x * 64;
    const __half* Ag = Aaos + (size_t)bm * 192;

    load_A_half(a_base, Ag, tid, 0);
    load_B_half(b_base, Wproj, tid, 0);
    cp_commit();
    load_A_half(a_base, Ag, tid, 12);
    load_B_half(b_base, Wproj, tid, 12);
    cp_commit();

    cp_wait1();
    __syncthreads();
    float acc[2][6][4] = {};
    mainloop_rng<0, 6>(a_base, b_base, wm, wn, lane, acc);
    cp_wait0();
    __syncthreads();
    mainloop_rng<6, 12>(a_base, b_base, wm, wn, lane, acc);
    __syncthreads();

    load_B_half(b_base, Wfc1, tid, 0);
    load_B_half(b_base, Wfc1, tid, 12);
    cp_commit();

    float2 bcol[6];
    #pragma unroll
    for (int nt = 0; nt < 6; nt++)
        bcol[nt] = *(const float2*)&pbias[wn * 48 + nt * 8 + 2 * (lane & 3)];
    int slot = wn * 4 + (lane & 3);
    int pixrow[2][2];

    #pragma unroll
    for (int mt = 0; mt < 2; mt++) {
        #pragma unroll
        for (int half = 0; half < 2; half++) {
            int rl = wm * 32 + mt * 16 + (lane >> 2) + half * 8;
            int row = bm + rl;
            int pr = pix_of_row(row);
            pixrow[mt][half] = pr;
            size_t pixbase = (size_t)pr * CC;
            float s = 0.f, sq2 = 0.f;
            #pragma unroll
            for (int nt = 0; nt < 6; nt++) {
                int col = wn * 48 + nt * 8 + 2 * (lane & 3);
                float2 sc = *(const float2*)&xsrc[pixbase + col];
                float vx = acc[mt][nt][half * 2] + bcol[nt].x + sc.x;
                float vy = acc[mt][nt][half * 2 + 1] + bcol[nt].y + sc.y;
                acc[mt][nt][half * 2] = vx;
                acc[mt][nt][half * 2 + 1] = vy;
                *(float2*)&x2out[pixbase + col] = make_float2(vx, vy);
                s += vx + vy;
                sq2 += vx * vx + vy * vy;
            }
            red [rl * 17 + slot] = s;
            redq[rl * 17 + slot] = sq2;
        }
    }
    __syncthreads();
    if (tid < 64) {
        float s = 0.f, qq = 0.f;
        #pragma unroll
        for (int i = 0; i < 16; i++) { s += red[tid * 17 + i]; qq += redq[tid * 17 + i]; }
        float mean = s * (1.f / 192.f);
        float var = qq * (1.f / 192.f) - mean * mean;
        red [tid * 17 + 16] = mean;
        redq[tid * 17 + 16] = rsqrtf(var + 1e-5f);
    }
    __syncthreads();

    #pragma unroll
    for (int mt = 0; mt < 2; mt++) {
        #pragma unroll
        for (int half = 0; half < 2; half++) {
            int rl = wm * 32 + mt * 16 + (lane >> 2) + half * 8;
            float mean = red [rl * 17 + 16];
            float rstd = redq[rl * 17 + 16];
            #pragma unroll
            for (int nt = 0; nt < 6; nt++) {
                int col = wn * 48 + nt * 8 + 2 * (lane & 3);
                float2 gv = *(const float2*)&g2[col];
                float2 bv = *(const float2*)&b2[col];
                float yx = (acc[mt][nt][half * 2] - mean) * rstd * gv.x + bv.x;
                float yy = (acc[mt][nt][half * 2 + 1] - mean) * rstd * gv.y + bv.y;
                uint32_t addr = a_base + full_off(rl, col >> 3) + (col & 7) * 2;
                asm volatile("st.shared.b32 [%0], %1;" :: "r"(addr), "r"(f22u(yx, yy)));
            }
        }
    }

    for (int nc = 0; nc < 4; nc++) {
        cp_wait0();
        __syncthreads();

        float acc2[2][6][4] = {};
        mainloop_rng<0, 12>(a_base, b_base, wm, wn, lane, acc2);
        __syncthreads();

        if (nc < 3) {
            const __half* Bg = Wfc1 + (size_t)(nc + 1) * 192 * 192;
            load_B_half(b_base, Bg, tid, 0);
            load_B_half(b_base, Bg, tid, 12);
            cp_commit();
        }

        float2 fb[6];
        #pragma unroll
        for (int nt = 0; nt < 6; nt++)
            fb[nt] = *(const float2*)&f1bias[nc * 192 + wn * 48 + nt * 8 + 2 * (lane & 3)];

        #pragma unroll
        for (int mt = 0; mt < 2; mt++) {
            #pragma unroll
            for (int half = 0; half < 2; half++) {
                size_t rb = (size_t)pixrow[mt][half] * HID + nc * 192;
                #pragma unroll
                for (int nt = 0; nt < 6; nt++) {
                    int col = wn * 48 + nt * 8 + 2 * (lane & 3);
                    float gx = gelu_exact(acc2[mt][nt][half * 2] + fb[nt].x);
                    float gy = gelu_exact(acc2[mt][nt][half * 2 + 1] + fb[nt].y);
                    *(__half2*)&hsout[rb + col] = __floats2half2_rn(gx, gy);
                }
            }
        }
    }
}

// ================= gemm_pipe64 (fc2) =================
#define SMEM_P64 98304
__global__ __launch_bounds__(256, 2)
void gemm_pipe64(const __half* __restrict__ A2, const __half* __restrict__ B2,
                 const float* __restrict__ bias, float* __restrict__ outF,
                 const float* __restrict__ addsrc) {
    extern __shared__ __align__(16) char sm_dyn[];
    uint32_t a_base = smem_to_u32(sm_dyn);
    uint32_t b_base = a_base + 24576;
    const int K = 768;

    int tid = threadIdx.x, lane = tid & 31, wid = tid >> 5;
    int wm = wid >> 2, wn = wid & 3;
    int bm = blockIdx.y * 64, bn = blockIdx.x * 192;
    const int NC = 12;

    float acc[2][6][4] = {};

    auto issue = [&](int buf, int cc) {
        const __half* Ag = A2 + (size_t)bm * K + cc * 64;
        const __half* Bg = B2 + (size_t)bn * K + cc * 64;
        uint32_t ab = a_base + buf * 8192;
        uint32_t bb = b_base + buf * 24576;
        #pragma unroll
        for (int i = 0; i < 2; i++) {
            int t = tid + i * 256, row = t >> 3, c = t & 7;
            cp16(t64_addr(ab, row, c), Ag + (size_t)row * K + c * 8);
        }
        #pragma unroll
        for (int i = 0; i < 6; i++) {
            int t = tid + i * 256, row = t >> 3, c = t & 7;
            cp16(t64_addr(bb, row, c), Bg + (size_t)row * K + c * 8);
        }
        cp_commit();
    };

    issue(0, 0);
    issue(1, 1);

    for (int cc = 0; cc < NC; cc++) {
        int buf = cc % 3;
        if (cc + 1 < NC) cp_wait1(); else cp_wait0();
        __syncthreads();
        if (cc + 2 < NC) issue((cc + 2) % 3, cc + 2);

        uint32_t ab = a_base + buf * 8192;
        uint32_t bb = b_base + buf * 24576;
        int arow = wm * 32 + (lane & 15);
        int bnrow = wn * 48 + (lane & 7) + ((lane >> 4) << 3);
        int bk8 = (lane >> 3) & 1;
        #pragma unroll
        for (int ks = 0; ks < 4; ks++) {
            uint32_t af[2][4];
            #pragma unroll
            for (int mt = 0; mt < 2; mt++)
                ldm4(af[mt][0], af[mt][1], af[mt][2], af[mt][3],
                     t64_addr(ab, arow + mt * 16, ks * 2 + (lane >> 4)));
            uint32_t bf[6][2];
            #pragma unroll
            for (int pr = 0; pr < 3; pr++)
                ldm4(bf[2 * pr][0], bf[2 * pr][1], bf[2 * pr + 1][0], bf[2 * pr + 1][1],
                     t64_addr(bb, bnrow + pr * 16, ks * 2 + bk8));
            #pragma unroll
            for (int mt = 0; mt < 2; mt++)
                #pragma unroll
                for (int nt = 0; nt < 6; nt++)
                    mma16816(acc[mt][nt][0], acc[mt][nt][1], acc[mt][nt][2], acc[mt][nt][3],
                             af[mt][0], af[mt][1], af[mt][2], af[mt][3],
                             bf[nt][0], bf[nt][1]);
        }
    }

    float2 bcol[6];
    #pragma unroll
    for (int nt = 0; nt < 6; nt++) {
        int col = bn + wn * 48 + nt * 8 + 2 * (lane & 3);
        bcol[nt] = *(const float2*)&bias[col];
    }
    #pragma unroll
    for (int mt = 0; mt < 2; mt++) {
        #pragma unroll
        for (int half = 0; half < 2; half++) {
            int row = bm + wm * 32 + mt * 16 + (lane >> 2) + half * 8;
            size_t rb = (size_t)row * 192;
            #pragma unroll
            for (int nt = 0; nt < 6; nt++) {
                int col = bn + wn * 48 + nt * 8 + 2 * (lane & 3);
                float2 s = *(const float2*)&addsrc[rb + col];
                float vx = acc[mt][nt][half * 2] + bcol[nt].x + s.x;
                float vy = acc[mt][nt][half * 2 + 1] + bcol[nt].y + s.y;
                *(float2*)&outF[rb + col] = make_float2(vx, vy);
            }
        }
    }
}

// ---------------- attention: 3 CTA/SM (smem 75776), per-wg named barriers ----------------
// smem: QKV [buf][wg] 4 x 15360 = 61440; C [wg] 2 x 7168 = 14336.
#define SMEM_ATTN 75776
__global__ __launch_bounds__(256, 3) void attn_mma(__half* __restrict__ outs) {
    extern __shared__ __align__(16) char sm_dyn[];
    uint32_t smb = smem_to_u32(sm_dyn);
    int win = blockIdx.x;
    int wi = win & 255;
    int cls = (((wi >> 4) == 15) ? 2 : 0) + (((wi & 15) == 15) ? 1 : 0);
    int tid = threadIdx.x;
    int wg = tid >> 7;
    int t = tid & 127;
    int lane = t & 31, wmg = t >> 5;
    int g = lane >> 3, r8 = lane & 7;
    int mr = wmg * 16;

    // per-wg barrier (ids 1,2; 128 threads each)
    #define BAR_WG() asm volatile("bar.sync %0, %1;" :: "r"(1 + wg), "r"(128) : "memory")

    uint4 z = make_uint4(0, 0, 0, 0);
    for (int i = tid; i < 3840; i += 256) ((uint4*)sm_dyn)[i] = z;
    __syncthreads();

    auto load_qkv = [&](int buf, int h2) {
        int h = h2 * 2 + wg;
        uint32_t qb = smb + (buf * 2 + wg) * 15360;
        const uint4* qg = (const uint4*)(g_q + (size_t)(win * NHEADS + h) * (NTOK * DHEAD));
        const uint4* kg = (const uint4*)(g_k + (size_t)(win * NHEADS + h) * (NTOK * DHEAD));
        const uint4* vg = (const uint4*)(g_v + (size_t)(win * NHEADS + h) * (NTOK * DHEAD));
        for (int i = t; i < 196; i += 128) {
            int r = i >> 2, c = i & 3;
            uint32_t off = r * 80 + c * 16;
            cp16(qb + off, qg + i);
            cp16(qb + 5120 + off, kg + i);
            cp16(qb + 10240 + off, vg + i);
        }
        cp_commit();
    };
    auto load_c = [&](int h2) {
        int h = h2 * 2 + wg;
        uint32_t cb = smb + 61440 + wg * 7168;
        const uint4* cg = (const uint4*)(g_cmb + (size_t)(cls * NHEADS + h) * (64 * 56));
        for (int i = t; i < 448; i += 128) cp16(cb + i * 16, cg + i);
        cp_commit();
    };

    load_qkv(0, 0);
    load_c(0);

    int buf = 0;
    for (int h2 = 0; h2 < 3; h2++) {
        int h = h2 * 2 + wg;
        if (h2 < 2) load_qkv(buf ^ 1, h2 + 1);
        if (h2 < 2) cp_wait1(); else cp_wait0();
        BAR_WG();

        uint32_t qbase = smb + (buf * 2 + wg) * 15360;
        uint32_t kbase = qbase + 5120, vbase = qbase + 10240;
        uint32_t cbase = smb + 61440 + wg * 7168;

        uint32_t qf[2][4];
        #pragma unroll
        for (int ks = 0; ks < 2; ks++) {
            int row = mr + (g & 1) * 8 + r8;
            int col = ks * 16 + (g >> 1) * 8;
            ldm4(qf[ks][0], qf[ks][1], qf[ks][2], qf[ks][3], qbase + row * 80 + col * 2);
        }

        float sacc[7][4] = {};
        #pragma unroll
        for (int ks = 0; ks < 2; ks++) {
            #pragma unroll
            for (int np = 0; np < 4; np++) {
                int row = np * 16 + ((g >> 1) & 1) * 8 + r8;
                int col = ks * 16 + (g & 1) * 8;
                uint32_t b0, b1, b2, b3;
                ldm4(b0, b1, b2, b3, kbase + row * 80 + col * 2);
                mma16816(sacc[2 * np][0], sacc[2 * np][1], sacc[2 * np][2], sacc[2 * np][3],
                         qf[ks][0], qf[ks][1], qf[ks][2], qf[ks][3], b0, b1);
                if (np < 3)
                    mma16816(sacc[2 * np + 1][0], sacc[2 * np + 1][1], sacc[2 * np + 1][2], sacc[2 * np + 1][3],
                             qf[ks][0], qf[ks][1], qf[ks][2], qf[ks][3], b2, b3);
            }
        }

        // bias add (consumes C buffer)
        #pragma unroll
        for (int np = 0; np < 4; np++) {
            int row = mr + (g & 1) * 8 + r8;
            int colc = 2 * np + ((g >> 1) & 1); if (colc > 6) colc = 6;
            uint32_t c0, c1, c2, c3;
            ldm4(c0, c1, c2, c3, cbase + row * 112 + colc * 8 * 2);
            float2 f;
            f = __half22float2(*(__half2*)&c0); sacc[2 * np][0] += f.x; sacc[2 * np][1] += f.y;
            f = __half22float2(*(__half2*)&c1); sacc[2 * np][2] += f.x; sacc[2 * np][3] += f.y;
            if (np < 3) {
                f = __half22float2(*(__half2*)&c2); sacc[2 * np + 1][0] += f.x; sacc[2 * np + 1][1] += f.y;
                f = __half22float2(*(__half2*)&c3); sacc[2 * np + 1][2] += f.x; sacc[2 * np + 1][3] += f.y;
            }
        }
        BAR_WG();   // all wg warps done reading C
        if (h2 < 2) load_c(h2 + 1);

        float mx0 = -1e30f, mx8 = -1e30f;
        #pragma unroll
        for (int nt = 0; nt < 7; nt++) {
            mx0 = fmaxf(mx0, fmaxf(sacc[nt][0], sacc[nt][1]));
            mx8 = fmaxf(mx8, fmaxf(sacc[nt][2], sacc[nt][3]));
        }
        #pragma unroll
        for (int o = 1; o <= 2; o <<= 1) {
            mx0 = fmaxf(mx0, __shfl_xor_sync(0xffffffffu, mx0, o));
            mx8 = fmaxf(mx8, __shfl_xor_sync(0xffffffffu, mx8, o));
        }
        float s0 = 0.f, s8 = 0.f;
        #pragma unroll
        for (int nt = 0; nt < 7; nt++) {
            sacc[nt][0] = __expf(sacc[nt][0] - mx0); s0 += sacc[nt][0];
            sacc[nt][1] = __expf(sacc[nt][1] - mx0); s0 += sacc[nt][1];
            sacc[nt][2] = __expf(sacc[nt][2] - mx8); s8 += sacc[nt][2];
            sacc[nt][3] = __expf(sacc[nt][3] - mx8); s8 += sacc[nt][3];
        }
        #pragma unroll
        for (int o = 1; o <= 2; o <<= 1) {
            s0 += __shfl_xor_sync(0xffffffffu, s0, o);
            s8 += __shfl_xor_sync(0xffffffffu, s8, o);
        }
        float inv0 = 1.f / s0, inv8 = 1.f / s8;
        #pragma unroll
        for (int nt = 0; nt < 7; nt++) {
            sacc[nt][0] *= inv0; sacc[nt][1] *= inv0;
            sacc[nt][2] *= inv8; sacc[nt][3] *= inv8;
        }

        float oacc[4][4] = {};
        #pragma unroll
        for (int kt = 0; kt < 4; kt++) {
            uint32_t a0 = f22u(sacc[2 * kt][0], sacc[2 * kt][1]);
            uint32_t a1 = f22u(sacc[2 * kt][2], sacc[2 * kt][3]);
            uint32_t a2 = 0, a3 = 0;
            if (kt < 3) {
                a2 = f22u(sacc[2 * kt + 1][0], sacc[2 * kt + 1][1]);
                a3 = f22u(sacc[2 * kt + 1][2], sacc[2 * kt + 1][3]);
            }
            #pragma unroll
            for (int dp = 0; dp < 2; dp++) {
                int row = kt * 16 + (g & 1) * 8 + r8;
                int col = dp * 16 + ((g >> 1) & 1) * 8;
                uint32_t b0, b1, b2, b3;
                ldm4t(b0, b1, b2, b3, vbase + row * 80 + col * 2);
                mma16816(oacc[2 * dp][0], oacc[2 * dp][1], oacc[2 * dp][2], oacc[2 * dp][3],
                         a0, a1, a2, a3, b0, b1);
                mma16816(oacc[2 * dp + 1][0], oacc[2 * dp + 1][1], oacc[2 * dp + 1][2], oacc[2 * dp + 1][3],
                         a0, a1, a2, a3, b2, b3);
            }
        }

        int r0 = mr + (lane >> 2);
        int cbase2 = h * DHEAD + 2 * (lane & 3);
        if (r0 < NTOK) {
            size_t ob = ((size_t)win * NTOK + r0) * CC + cbase2;
            #pragma unroll
            for (int dn = 0; dn < 4; dn++)
                *(__half2*)&outs[ob + dn * 8] = __floats2half2_rn(oacc[dn][0], oacc[dn][1]);
        }
        int r1 = r0 + 8;
        if (r1 < NTOK) {
            size_t ob = ((size_t)win * NTOK + r1) * CC + cbase2;
            #pragma unroll
            for (int dn = 0; dn < 4; dn++)
                *(__half2*)&outs[ob + dn * 8] = __floats2half2_rn(oacc[dn][2], oacc[dn][3]);
        }
        BAR_WG();   // QKV[buf] fully consumed before next iter reissues into it
        buf ^= 1;
    }
    #undef BAR_WG
}

// ---------------- launch ----------------
extern "C" void kernel_launch(void* const* d_in, const int* in_sizes, int n_in,
                              void* d_out, int out_size) {
    const float* x      = (const float*)d_in[0];
    const float* amask  = (const float*)d_in[1];
    const float* n1g    = (const float*)d_in[2];
    const float* n1b    = (const float*)d_in[3];
    const float* qkv_w  = (const float*)d_in[4];
    const float* qkv_b  = (const float*)d_in[5];
    const float* rpb    = (const float*)d_in[6];
    const float* proj_w = (const float*)d_in[7];
    const float* proj_b = (const float*)d_in[8];
    const float* n2g    = (const float*)d_in[9];
    const float* n2b    = (const float*)d_in[10];
    const float* fc1_w  = (const float*)d_in[11];
    const float* fc1_b  = (const float*)d_in[12];
    const float* fc2_w  = (const float*)d_in[13];
    const float* fc2_b  = (const float*)d_in[14];
    float* out = (float*)d_out;

    __half *xs, *aos, *hs, *wqkv, *wproj, *wfc1, *wfc2;
    float *x2;
    cudaGetSymbolAddress((void**)&xs,    g_xs);
    cudaGetSymbolAddress((void**)&aos,   g_aos);
    cudaGetSymbolAddress((void**)&hs,    g_hs);
    cudaGetSymbolAddress((void**)&x2,    g_x2);
    cudaGetSymbolAddress((void**)&wqkv,  g_wqkv);
    cudaGetSymbolAddress((void**)&wproj, g_wproj);
    cudaGetSymbolAddress((void**)&wfc1,  g_wfc1);
    cudaGetSymbolAddress((void**)&wfc2,  g_wfc2);

    cudaFuncSetAttribute(gemm_qkv,    cudaFuncAttributeMaxDynamicSharedMemorySize, SMEM_QKV);
    cudaFuncSetAttribute(gemm_mlp,    cudaFuncAttributeMaxDynamicSharedMemorySize, SMEM_MLP);
    cudaFuncSetAttribute(gemm_pipe64, cudaFuncAttributeMaxDynamicSharedMemorySize, SMEM_P64);
    cudaFuncSetAttribute(attn_mma,    cudaFuncAttributeMaxDynamicSharedMemorySize, SMEM_ATTN);

    const int MB = MROWS / 64;  // 3136

    prep_merged<<<1752, 256>>>(qkv_w, proj_w, fc1_w, fc2_w, amask, rpb);
    ln1_kernel<<<MROWS / 8, 256>>>(x, n1g, n1b, xs);
    gemm_qkv<<<dim3(3, MB), 256, SMEM_QKV>>>(xs, wqkv, qkv_b);
    attn_mma<<<NWIN, 256, SMEM_ATTN>>>(aos);
    gemm_mlp<<<MB, 256, SMEM_MLP>>>(aos, wproj, proj_b, x2, x, n2g, n2b, wfc1, fc1_b, hs);
    gemm_pipe64<<<dim3(1, MB), 256, SMEM_P64>>>(hs, wfc2, fc2_b, out, x2);
}